// round 7
// baseline (speedup 1.0000x reference)
#include <cuda_runtime.h>
#include <cstdint>

// ---------------- problem constants ----------------
constexpr int S = 1024, B = 8, D = 1024, H = 16, F = 4096, E = 8;
constexpr int HD = D / H;           // 64
constexpr int N = S * B;            // 8192
constexpr int CAP = 4 * N / E;      // 4096
constexpr int D3 = 3 * D;           // 3072 (merged qkv width)

// ---------------- scratch (device globals; no allocations) ----------------
__device__ uint32_t g_xnh[N * D], g_xnl[N * D];      // LN1 out, tf32 hi/lo
__device__ float    g_qkv[N * D3];                   // merged q|k|v
__device__ uint32_t g_aoh[N * D], g_aol[N * D];      // attn out, tf32 hi/lo
__device__ float g_x1 [N * D];
__device__ float g_tok[N * D];
__device__ uint32_t g_wqkvh[D * D3], g_wqkvl[D * D3];
__device__ float    g_b3[D3];
__device__ uint32_t g_woh[D * D], g_wol[D * D];
__device__ uint16_t g_dispb[E * CAP * D];            // bf16 dispatched tokens
__device__ uint16_t g_hb  [134217728];               // E*CAP*F bf16 hidden
__device__ float    g_eo  [E * CAP * D];
__device__ uint32_t g_w1p [(D / 2) * F * E];         // bf16 k-pair packed w1
__device__ uint32_t g_w2p [(F / 2) * D * E];         // bf16 k-pair packed w2
__device__ float g_gates[N * E];
__device__ int   g_eidx[N];
__device__ float g_gp  [N];
__device__ int   g_slot[N];
__device__ float g_gv  [N];
__device__ int   g_cnt [E];

// ---------------- helpers ----------------
__device__ __forceinline__ uint32_t f2tf32(float f) {
    uint32_t u;
    asm("cvt.rna.tf32.f32 %0, %1;" : "=r"(u) : "f"(f));
    return u;
}
__device__ __forceinline__ uint32_t packbf2(float lo, float hi) {
    uint32_t d;
    asm("cvt.rn.bf16x2.f32 %0, %1, %2;" : "=r"(d) : "f"(hi), "f"(lo));
    return d;
}

// ---------------- weight split (with column offset + exact pow2 scale) ------
__global__ void __launch_bounds__(256) splitw3_kernel(
    const float* __restrict__ W, uint32_t* __restrict__ Wh3,
    uint32_t* __restrict__ Wl3, int colOff, float scale)
{
    int i = blockIdx.x * 256 + threadIdx.x;   // over D*D
    int d = i >> 10, e = i & 1023;
    float v = W[i] * scale;                   // scale is power of 2: exact
    uint32_t h = f2tf32(v);
    Wh3[(long long)d * D3 + colOff + e] = h;
    Wl3[(long long)d * D3 + colOff + e] = f2tf32(v - __uint_as_float(h));
}
__global__ void __launch_bounds__(256) splitw_kernel(
    const float* __restrict__ W, uint32_t* __restrict__ Wh,
    uint32_t* __restrict__ Wl)
{
    int i = blockIdx.x * 256 + threadIdx.x;
    float v = W[i];
    uint32_t h = f2tf32(v);
    Wh[i] = h;
    Wl[i] = f2tf32(v - __uint_as_float(h));
}
__global__ void __launch_bounds__(256) biascat_kernel(
    const float* __restrict__ src, float* __restrict__ dst, float scale)
{
    int i = blockIdx.x * 256 + threadIdx.x;
    dst[i] = src[i] * scale;
}

// ---------------- LayerNorm (fp32 out) ----------------
__global__ void __launch_bounds__(256) ln_kernel(const float* __restrict__ x,
                                                 const float* __restrict__ gam,
                                                 const float* __restrict__ bet,
                                                 float* __restrict__ y) {
    int n = blockIdx.x;
    const float* row = x + (long)n * D;
    int t = threadIdx.x;
    float s = 0.f, s2 = 0.f;
    for (int d = t; d < D; d += 256) { float v = row[d]; s += v; s2 += v * v; }
    __shared__ float r1[256], r2[256];
    r1[t] = s; r2[t] = s2; __syncthreads();
    for (int st = 128; st > 0; st >>= 1) {
        if (t < st) { r1[t] += r1[t + st]; r2[t] += r2[t + st]; }
        __syncthreads();
    }
    float mean = r1[0] / D;
    float var  = r2[0] / D - mean * mean;
    float inv  = rsqrtf(var + 1e-5f);
    float* yo = y + (long)n * D;
    for (int d = t; d < D; d += 256)
        yo[d] = (row[d] - mean) * inv * gam[d] + bet[d];
}

// ---------------- LayerNorm (tf32 hi/lo out) ----------------
__global__ void __launch_bounds__(256) ln_split_kernel(
    const float* __restrict__ x, const float* __restrict__ gam,
    const float* __restrict__ bet,
    uint32_t* __restrict__ yh, uint32_t* __restrict__ yl)
{
    int n = blockIdx.x;
    const float* row = x + (long)n * D;
    int t = threadIdx.x;
    float s = 0.f, s2 = 0.f;
    for (int d = t; d < D; d += 256) { float v = row[d]; s += v; s2 += v * v; }
    __shared__ float r1[256], r2[256];
    r1[t] = s; r2[t] = s2; __syncthreads();
    for (int st = 128; st > 0; st >>= 1) {
        if (t < st) { r1[t] += r1[t + st]; r2[t] += r2[t + st]; }
        __syncthreads();
    }
    float mean = r1[0] / D;
    float var  = r2[0] / D - mean * mean;
    float inv  = rsqrtf(var + 1e-5f);
    for (int d = t; d < D; d += 256) {
        float v = (row[d] - mean) * inv * gam[d] + bet[d];
        uint32_t h = f2tf32(v);
        yh[(long)n * D + d] = h;
        yl[(long)n * D + d] = f2tf32(v - __uint_as_float(h));
    }
}

// ---------------- 3xTF32 GEMM, pre-split, single-buffer, occ=2 --------------
// C[M,Nc] = (Ah+Al)@(Bh+Bl) + bias (+ resid). Block 128x128, warp 64x32.
template<int HAS_RESID>
__global__ void __launch_bounds__(256, 2) gemm_t3s_kernel(
    const uint32_t* __restrict__ Ah, const uint32_t* __restrict__ Al,
    const uint32_t* __restrict__ Bh, const uint32_t* __restrict__ Bl,
    const float* __restrict__ bias, const float* __restrict__ resid,
    float* __restrict__ C, int M, int Nc, int K)
{
    __shared__ uint32_t As_h[16][136], As_l[16][136];
    __shared__ uint32_t Bs_h[16][136], Bs_l[16][136];

    int t    = threadIdx.x;
    int wid  = t >> 5, lane = t & 31;
    int gid  = lane >> 2, tig = lane & 3;
    int wm0  = (wid & 1) * 64;
    int wn0  = (wid >> 1) * 32;
    int m0   = blockIdx.y * 128, n0 = blockIdx.x * 128;

    float acc[4][4][4];
#pragma unroll
    for (int mt = 0; mt < 4; mt++)
#pragma unroll
        for (int nt = 0; nt < 4; nt++)
#pragma unroll
            for (int r = 0; r < 4; r++) acc[mt][nt][r] = 0.f;

    for (int k0 = 0; k0 < K; k0 += 16) {
#pragma unroll
        for (int l = 0; l < 2; l++) {
            int f  = t + l * 256;
            int r  = f >> 2;
            int c4 = (f & 3) * 4;
            uint4 vh = *(const uint4*)(Ah + (long long)(m0 + r) * K + k0 + c4);
            uint4 vl = *(const uint4*)(Al + (long long)(m0 + r) * K + k0 + c4);
            As_h[c4 + 0][r] = vh.x; As_h[c4 + 1][r] = vh.y;
            As_h[c4 + 2][r] = vh.z; As_h[c4 + 3][r] = vh.w;
            As_l[c4 + 0][r] = vl.x; As_l[c4 + 1][r] = vl.y;
            As_l[c4 + 2][r] = vl.z; As_l[c4 + 3][r] = vl.w;
        }
#pragma unroll
        for (int l = 0; l < 2; l++) {
            int f  = t + l * 256;
            int r  = f >> 5;
            int c4 = (f & 31) * 4;
            *(uint4*)(&Bs_h[r][c4]) =
                *(const uint4*)(Bh + (long long)(k0 + r) * Nc + n0 + c4);
            *(uint4*)(&Bs_l[r][c4]) =
                *(const uint4*)(Bl + (long long)(k0 + r) * Nc + n0 + c4);
        }
        __syncthreads();

#pragma unroll
        for (int kb = 0; kb < 16; kb += 8) {
            uint32_t fah[4][4], fal[4][4], fbh[4][2], fbl[4][2];
#pragma unroll
            for (int mt = 0; mt < 4; mt++) {
                int mm = wm0 + mt * 16 + gid;
                fah[mt][0] = As_h[kb + tig    ][mm];
                fah[mt][1] = As_h[kb + tig    ][mm + 8];
                fah[mt][2] = As_h[kb + tig + 4][mm];
                fah[mt][3] = As_h[kb + tig + 4][mm + 8];
                fal[mt][0] = As_l[kb + tig    ][mm];
                fal[mt][1] = As_l[kb + tig    ][mm + 8];
                fal[mt][2] = As_l[kb + tig + 4][mm];
                fal[mt][3] = As_l[kb + tig + 4][mm + 8];
            }
#pragma unroll
            for (int nt = 0; nt < 4; nt++) {
                int nn = wn0 + nt * 8 + gid;
                fbh[nt][0] = Bs_h[kb + tig    ][nn];
                fbh[nt][1] = Bs_h[kb + tig + 4][nn];
                fbl[nt][0] = Bs_l[kb + tig    ][nn];
                fbl[nt][1] = Bs_l[kb + tig + 4][nn];
            }
#pragma unroll
            for (int mt = 0; mt < 4; mt++)
#pragma unroll
                for (int nt = 0; nt < 4; nt++) {
                    asm volatile(
                        "mma.sync.aligned.m16n8k8.row.col.f32.tf32.tf32.f32 "
                        "{%0,%1,%2,%3}, {%4,%5,%6,%7}, {%8,%9}, {%0,%1,%2,%3};"
                        : "+f"(acc[mt][nt][0]), "+f"(acc[mt][nt][1]),
                          "+f"(acc[mt][nt][2]), "+f"(acc[mt][nt][3])
                        : "r"(fah[mt][0]), "r"(fah[mt][1]), "r"(fah[mt][2]), "r"(fah[mt][3]),
                          "r"(fbl[nt][0]), "r"(fbl[nt][1]));
                    asm volatile(
                        "mma.sync.aligned.m16n8k8.row.col.f32.tf32.tf32.f32 "
                        "{%0,%1,%2,%3}, {%4,%5,%6,%7}, {%8,%9}, {%0,%1,%2,%3};"
                        : "+f"(acc[mt][nt][0]), "+f"(acc[mt][nt][1]),
                          "+f"(acc[mt][nt][2]), "+f"(acc[mt][nt][3])
                        : "r"(fal[mt][0]), "r"(fal[mt][1]), "r"(fal[mt][2]), "r"(fal[mt][3]),
                          "r"(fbh[nt][0]), "r"(fbh[nt][1]));
                    asm volatile(
                        "mma.sync.aligned.m16n8k8.row.col.f32.tf32.tf32.f32 "
                        "{%0,%1,%2,%3}, {%4,%5,%6,%7}, {%8,%9}, {%0,%1,%2,%3};"
                        : "+f"(acc[mt][nt][0]), "+f"(acc[mt][nt][1]),
                          "+f"(acc[mt][nt][2]), "+f"(acc[mt][nt][3])
                        : "r"(fah[mt][0]), "r"(fah[mt][1]), "r"(fah[mt][2]), "r"(fah[mt][3]),
                          "r"(fbh[nt][0]), "r"(fbh[nt][1]));
                }
        }
        __syncthreads();
    }

#pragma unroll
    for (int mt = 0; mt < 4; mt++) {
#pragma unroll
        for (int nt = 0; nt < 4; nt++) {
            int row = m0 + wm0 + mt * 16 + gid;
            int col = n0 + wn0 + nt * 8 + 2 * tig;
            float b0 = bias[col], b1 = bias[col + 1];
            float c0 = acc[mt][nt][0] + b0;
            float c1 = acc[mt][nt][1] + b1;
            float c2 = acc[mt][nt][2] + b0;
            float c3 = acc[mt][nt][3] + b1;
            if (HAS_RESID) {
                float2 r0 = *(const float2*)(resid + (long long)row * Nc + col);
                float2 r1 = *(const float2*)(resid + (long long)(row + 8) * Nc + col);
                c0 += r0.x; c1 += r0.y; c2 += r1.x; c3 += r1.y;
            }
            *(float2*)(C + (long long)row * Nc + col)       = make_float2(c0, c1);
            *(float2*)(C + (long long)(row + 8) * Nc + col) = make_float2(c2, c3);
        }
    }
}

// ---------------- weight packing: fp32 [K][Nc] -> bf16 k-pair u32 [K/2][Nc] --
__global__ void __launch_bounds__(256) packw_kernel(
    const float* __restrict__ W, uint32_t* __restrict__ P, int Nc,
    long long sW, long long sP)
{
    int n  = blockIdx.x * 256 + threadIdx.x;
    int k2 = blockIdx.y;
    int z  = blockIdx.z;
    const float* w = W + (long long)z * sW + (long long)(2 * k2) * Nc + n;
    P[(long long)z * sP + (long long)k2 * Nc + n] = packbf2(w[0], w[Nc]);
}

// ---------------- bf16 expert GEMM: block 128x256, warp 64x64, k32 ----------
// C = op(A[M,K](bf16) @ Bp(packed bf16 pairs [K/2][Nc]) + bias)
constexpr int EXP_SMEM = 2 * 16 * 136 * 4 + 2 * 16 * 264 * 4;  // 51200 B

template<int RELU, int OUTBF>
__global__ void __launch_bounds__(256) gemm_bf16w_kernel(
    const uint16_t* __restrict__ A, const uint32_t* __restrict__ Bp,
    const float* __restrict__ bias, void* __restrict__ Cout,
    int M, int Nc, int K,
    long long sA, long long sB, long long sBias, long long sC)
{
    extern __shared__ uint32_t dyn[];
    uint32_t* As = dyn;                    // [2][16][136]
    uint32_t* Bs = dyn + 2 * 16 * 136;     // [2][16][264]

    int z = blockIdx.z;
    A    += (long long)z * sA;
    Bp   += (long long)z * sB;
    bias += (long long)z * sBias;

    int t    = threadIdx.x;
    int wid  = t >> 5, lane = t & 31;
    int gid  = lane >> 2, tig = lane & 3;
    int wm0  = (wid & 1) * 64;
    int wn0  = (wid >> 1) * 64;            // 4 n-warps * 64
    int m0   = blockIdx.y * 128, n0 = blockIdx.x * 256;

    int am  = t & 127, ahh = t >> 7;       // A: row am, octet ahh and ahh+2
    int bk  = t >> 4,  bn  = (t & 15) * 16;

    float acc[4][8][4];
#pragma unroll
    for (int mt = 0; mt < 4; mt++)
#pragma unroll
        for (int nt = 0; nt < 8; nt++)
#pragma unroll
            for (int r = 0; r < 4; r++) acc[mt][nt][r] = 0.f;

    auto stageA = [&](int buf, uint4 va0, uint4 va1) {
        uint32_t* as = As + buf * (16 * 136);
        as[(ahh * 4 + 0) * 136 + am] = va0.x;
        as[(ahh * 4 + 1) * 136 + am] = va0.y;
        as[(ahh * 4 + 2) * 136 + am] = va0.z;
        as[(ahh * 4 + 3) * 136 + am] = va0.w;
        as[((ahh + 2) * 4 + 0) * 136 + am] = va1.x;
        as[((ahh + 2) * 4 + 1) * 136 + am] = va1.y;
        as[((ahh + 2) * 4 + 2) * 136 + am] = va1.z;
        as[((ahh + 2) * 4 + 3) * 136 + am] = va1.w;
    };
    auto stageB = [&](int buf, const uint4* vb) {
        uint32_t* bs = Bs + buf * (16 * 264);
#pragma unroll
        for (int j = 0; j < 4; j++)
            *(uint4*)&bs[bk * 264 + bn + j * 4] = vb[j];
    };

    const int nIter = K / 32;
    {   // stage tile 0
        uint4 va0 = *(const uint4*)(A + (long long)(m0 + am) * K + ahh * 8);
        uint4 va1 = *(const uint4*)(A + (long long)(m0 + am) * K + (ahh + 2) * 8);
        uint4 vb[4];
#pragma unroll
        for (int j = 0; j < 4; j++)
            vb[j] = *(const uint4*)(Bp + (long long)bk * Nc + n0 + bn + j * 4);
        stageA(0, va0, va1);
        stageB(0, vb);
    }
    __syncthreads();

    for (int it = 0; it < nIter; ++it) {
        int cur = it & 1;
        uint4 va0, va1, vb[4];
        bool pf = (it + 1 < nIter);
        if (pf) {
            long long ka = (long long)(m0 + am) * K + (it + 1) * 32;
            va0 = *(const uint4*)(A + ka + ahh * 8);
            va1 = *(const uint4*)(A + ka + (ahh + 2) * 8);
            long long kb = (long long)(it + 1) * 16 + bk;
#pragma unroll
            for (int j = 0; j < 4; j++)
                vb[j] = *(const uint4*)(Bp + kb * Nc + n0 + bn + j * 4);
        }
        const uint32_t* as = As + cur * (16 * 136);
        const uint32_t* bs = Bs + cur * (16 * 264);
#pragma unroll
        for (int kb2 = 0; kb2 < 2; kb2++) {
            int ko = kb2 * 8;
            uint32_t af[4][4], bfr[8][2];
#pragma unroll
            for (int mt = 0; mt < 4; mt++) {
                int mm = wm0 + mt * 16 + gid;
                af[mt][0] = as[(ko + tig    ) * 136 + mm];
                af[mt][1] = as[(ko + tig    ) * 136 + mm + 8];
                af[mt][2] = as[(ko + tig + 4) * 136 + mm];
                af[mt][3] = as[(ko + tig + 4) * 136 + mm + 8];
            }
#pragma unroll
            for (int nt = 0; nt < 8; nt++) {
                int nn = wn0 + nt * 8 + gid;
                bfr[nt][0] = bs[(ko + tig    ) * 264 + nn];
                bfr[nt][1] = bs[(ko + tig + 4) * 264 + nn];
            }
#pragma unroll
            for (int mt = 0; mt < 4; mt++)
#pragma unroll
                for (int nt = 0; nt < 8; nt++) {
                    asm volatile(
                        "mma.sync.aligned.m16n8k16.row.col.f32.bf16.bf16.f32 "
                        "{%0,%1,%2,%3}, {%4,%5,%6,%7}, {%8,%9}, {%0,%1,%2,%3};"
                        : "+f"(acc[mt][nt][0]), "+f"(acc[mt][nt][1]),
                          "+f"(acc[mt][nt][2]), "+f"(acc[mt][nt][3])
                        : "r"(af[mt][0]), "r"(af[mt][1]),
                          "r"(af[mt][2]), "r"(af[mt][3]),
                          "r"(bfr[nt][0]), "r"(bfr[nt][1]));
                }
        }
        if (pf) {
            stageA(cur ^ 1, va0, va1);
            stageB(cur ^ 1, vb);
        }
        __syncthreads();
    }

#pragma unroll
    for (int mt = 0; mt < 4; mt++) {
#pragma unroll
        for (int nt = 0; nt < 8; nt++) {
            int row = m0 + wm0 + mt * 16 + gid;
            int col = n0 + wn0 + nt * 8 + 2 * tig;
            float b0 = bias[col], b1 = bias[col + 1];
            float c0 = acc[mt][nt][0] + b0;
            float c1 = acc[mt][nt][1] + b1;
            float c2 = acc[mt][nt][2] + b0;
            float c3 = acc[mt][nt][3] + b1;
            if (RELU) {
                c0 = fmaxf(c0, 0.f); c1 = fmaxf(c1, 0.f);
                c2 = fmaxf(c2, 0.f); c3 = fmaxf(c3, 0.f);
            }
            if (OUTBF) {
                uint16_t* Cb = (uint16_t*)Cout + (long long)z * sC;
                *(uint32_t*)(Cb + (long long)row * Nc + col)       = packbf2(c0, c1);
                *(uint32_t*)(Cb + (long long)(row + 8) * Nc + col) = packbf2(c2, c3);
            } else {
                float* Cf = (float*)Cout + (long long)z * sC;
                *(float2*)(Cf + (long long)row * Nc + col)       = make_float2(c0, c1);
                *(float2*)(Cf + (long long)(row + 8) * Nc + col) = make_float2(c2, c3);
            }
        }
    }
}

// ---------------- flash attention (fp32, causal; strided qkv input) ---------
constexpr int QT = 128, KT = 64;
constexpr int ATTN_SMEM = (QT * (HD + 1) + 2 * KT * HD) * 4;  // 66048 B

__global__ void __launch_bounds__(128) attn_kernel(
    const float* __restrict__ Q, const float* __restrict__ Kg,
    const float* __restrict__ Vg, int LD,
    uint32_t* __restrict__ Oh, uint32_t* __restrict__ Ol)
{
    extern __shared__ float sm[];
    float* q_s = sm;
    float* k_s = sm + QT * (HD + 1);
    float* v_s = k_s + KT * HD;

    int bh = blockIdx.y;
    int h  = bh % H, b = bh / H;
    int q0 = blockIdx.x * QT;
    int t  = threadIdx.x;
    long base = (long)b * LD + (long)h * HD;
    long rs   = (long)B * LD;    // row stride per s

    for (int f = t; f < QT * HD / 4; f += 128) {
        int r  = f / (HD / 4);
        int c4 = (f % (HD / 4)) * 4;
        float4 v = *(const float4*)(Q + (long)(q0 + r) * rs + base + c4);
        q_s[r * (HD + 1) + c4 + 0] = v.x;
        q_s[r * (HD + 1) + c4 + 1] = v.y;
        q_s[r * (HD + 1) + c4 + 2] = v.z;
        q_s[r * (HD + 1) + c4 + 3] = v.w;
    }
    __syncthreads();

    int sq = q0 + t;
    float m_run = -1e30f, l_run = 0.f;
    float acc[HD];
#pragma unroll
    for (int d = 0; d < HD; d++) acc[d] = 0.f;

    int kend = q0 + QT;
    for (int k0 = 0; k0 < kend; k0 += KT) {
        for (int f = t; f < KT * HD / 4; f += 128) {
            int r  = f / (HD / 4);
            int c4 = (f % (HD / 4)) * 4;
            *(float4*)(&k_s[r * HD + c4]) =
                *(const float4*)(Kg + (long)(k0 + r) * rs + base + c4);
            *(float4*)(&v_s[r * HD + c4]) =
                *(const float4*)(Vg + (long)(k0 + r) * rs + base + c4);
        }
        __syncthreads();

        float s[KT];
#pragma unroll
        for (int j = 0; j < KT; j++) s[j] = 0.f;
        for (int d = 0; d < HD; d++) {
            float qd = q_s[t * (HD + 1) + d];
#pragma unroll
            for (int j = 0; j < KT; j++) s[j] += qd * k_s[j * HD + d];
        }
        float mnew = m_run;
#pragma unroll
        for (int j = 0; j < KT; j++) {
            if (k0 + j > sq) s[j] = -1e9f;
            mnew = fmaxf(mnew, s[j]);
        }
        float corr = __expf(m_run - mnew);
        l_run *= corr;
#pragma unroll
        for (int d = 0; d < HD; d++) acc[d] *= corr;
        for (int j = 0; j < KT; j++) {
            float p = __expf(s[j] - mnew);
            l_run += p;
#pragma unroll
            for (int d = 0; d < HD; d++) acc[d] += p * v_s[j * HD + d];
        }
        m_run = mnew;
        __syncthreads();
    }
    float inv = 1.f / l_run;
    long off = (long)sq * (B * D) + (long)b * D + (long)h * HD;
#pragma unroll
    for (int d = 0; d < HD; d++) {
        float v = acc[d] * inv;
        uint32_t hi = f2tf32(v);
        Oh[off + d] = hi;
        Ol[off + d] = f2tf32(v - __uint_as_float(hi));
    }
}

// ---------------- gate: logits, softmax, argmax (fp32, exact) ----------------
__global__ void __launch_bounds__(256) gate_kernel(
    const float* __restrict__ tok, const float* __restrict__ gw,
    float* __restrict__ gates, int* __restrict__ eidx, float* __restrict__ gp)
{
    int n = blockIdx.x, t = threadIdx.x;
    const float* row = tok + (long)n * D;
    float p[E];
#pragma unroll
    for (int e = 0; e < E; e++) p[e] = 0.f;
    for (int d = t; d < D; d += 256) {
        float xv = row[d];
        const float* w = gw + (long)d * E;
#pragma unroll
        for (int e = 0; e < E; e++) p[e] += xv * w[e];
    }
    __shared__ float red[256 * E];
#pragma unroll
    for (int e = 0; e < E; e++) red[t * E + e] = p[e];
    __syncthreads();
    for (int st = 128; st > 0; st >>= 1) {
        if (t < st)
#pragma unroll
            for (int e = 0; e < E; e++) red[t * E + e] += red[(t + st) * E + e];
        __syncthreads();
    }
    if (t == 0) {
        float lg[E], mx = -1e30f;
#pragma unroll
        for (int e = 0; e < E; e++) { lg[e] = red[e]; mx = fmaxf(mx, lg[e]); }
        float sum = 0.f, pr[E];
#pragma unroll
        for (int e = 0; e < E; e++) { pr[e] = __expf(lg[e] - mx); sum += pr[e]; }
        float inv = 1.f / sum;
        int best = 0; float bv = -1e30f;
#pragma unroll
        for (int e = 0; e < E; e++) {
            float g = pr[e] * inv;
            gates[(long)n * E + e] = g;
            if (g > bv) { bv = g; best = e; }
        }
        eidx[n] = best;
        gp[n]   = bv;
    }
}

// ---------------- routing scan (deterministic, single block) ----------------
__global__ void __launch_bounds__(256) scan_kernel(
    const int* __restrict__ eidx, const float* __restrict__ gp,
    int* __restrict__ slot, float* __restrict__ gv, int* __restrict__ cnt)
{
    __shared__ int scnt[256][E];
    int t = threadIdx.x;
    int c[E];
#pragma unroll
    for (int e = 0; e < E; e++) c[e] = 0;
    int n0 = t * (N / 256);
    for (int i = 0; i < N / 256; i++) c[eidx[n0 + i]]++;
#pragma unroll
    for (int e = 0; e < E; e++) scnt[t][e] = c[e];
    __syncthreads();
    if (t < E) {
        int run = 0;
        for (int j = 0; j < 256; j++) { int tmp = scnt[j][t]; scnt[j][t] = run; run += tmp; }
        cnt[t] = run;
    }
    __syncthreads();
    int off[E];
#pragma unroll
    for (int e = 0; e < E; e++) off[e] = scnt[t][e];
    for (int i = 0; i < N / 256; i++) {
        int n = n0 + i;
        int e = eidx[n];
        int l = off[e]++;
        bool keep = (l < CAP);
        slot[n] = keep ? e * CAP + l : -1;
        gv[n]   = keep ? gp[n] : 0.f;
    }
}

// ---------------- l_aux (deterministic tree reduce) ----------------
__global__ void __launch_bounds__(256) laux_kernel(
    const float* __restrict__ gates, const int* __restrict__ cnt,
    float* __restrict__ out_laux)
{
    __shared__ float red[256];
    int t = threadIdx.x;
    float loc[E];
#pragma unroll
    for (int e = 0; e < E; e++) loc[e] = 0.f;
    for (int n = t; n < N; n += 256)
#pragma unroll
        for (int e = 0; e < E; e++) loc[e] += gates[(long)n * E + e];
    float total[E];
    for (int e = 0; e < E; e++) {
        red[t] = loc[e]; __syncthreads();
        for (int st = 128; st > 0; st >>= 1) {
            if (t < st) red[t] += red[t + st];
            __syncthreads();
        }
        if (t == 0) total[e] = red[0];
        __syncthreads();
    }
    if (t == 0) {
        float la = 0.f;
        for (int e = 0; e < E; e++)
            la += (total[e] / N) * ((float)cnt[e] / N);
        *out_laux = (float)E * la;
    }
}

// ---------------- dispatch / combine ----------------
__global__ void __launch_bounds__(256) dispatch_kernel(
    const float* __restrict__ tok, const int* __restrict__ slot,
    uint16_t* __restrict__ dispb)
{
    int n = blockIdx.x;
    int s = slot[n];
    if (s < 0) return;
    int t = threadIdx.x;
    float4 v = ((const float4*)(tok + (long)n * D))[t];
    uint2 o;
    o.x = packbf2(v.x, v.y);
    o.y = packbf2(v.z, v.w);
    *(uint2*)(dispb + (long)s * D + t * 4) = o;
}

__global__ void __launch_bounds__(256) combine_kernel(
    const float* __restrict__ x1, const float* __restrict__ eo,
    const int* __restrict__ slot, const float* __restrict__ gv,
    float* __restrict__ out)
{
    int n = blockIdx.x, t = threadIdx.x;
    int s = slot[n];
    float g = gv[n];
    float4 r = ((const float4*)(x1 + (long)n * D))[t];
    if (s >= 0) {
        float4 v = ((const float4*)(eo + (long)s * D))[t];
        r.x += v.x * g; r.y += v.y * g; r.z += v.z * g; r.w += v.w * g;
    }
    ((float4*)(out + (long)n * D))[t] = r;
}

// ---------------- launch ----------------
extern "C" void kernel_launch(void* const* d_in, const int* in_sizes, int n_in,
                              void* d_out, int out_size) {
    const float* x    = (const float*)d_in[0];
    const float* wq   = (const float*)d_in[2];
    const float* bq   = (const float*)d_in[3];
    const float* wk   = (const float*)d_in[4];
    const float* bk   = (const float*)d_in[5];
    const float* wv   = (const float*)d_in[6];
    const float* bv   = (const float*)d_in[7];
    const float* wo   = (const float*)d_in[8];
    const float* bo   = (const float*)d_in[9];
    const float* ln1g = (const float*)d_in[10];
    const float* ln1b = (const float*)d_in[11];
    const float* ln2g = (const float*)d_in[12];
    const float* ln2b = (const float*)d_in[13];
    const float* gw   = (const float*)d_in[14];
    const float* w1   = (const float*)d_in[15];
    const float* b1   = (const float*)d_in[16];
    const float* w2   = (const float*)d_in[17];
    const float* b2   = (const float*)d_in[18];
    float* out = (float*)d_out;

    float *qkv, *x1, *tok, *eo, *gates, *gp, *gv, *b3;
    uint32_t *xnh, *xnl, *aoh, *aol, *wqkvh, *wqkvl, *woh, *wol, *w1p, *w2p;
    uint16_t *dispb, *hb;
    int *eidx, *slot, *cnt;
    cudaGetSymbolAddress((void**)&xnh,   g_xnh);
    cudaGetSymbolAddress((void**)&xnl,   g_xnl);
    cudaGetSymbolAddress((void**)&qkv,   g_qkv);
    cudaGetSymbolAddress((void**)&aoh,   g_aoh);
    cudaGetSymbolAddress((void**)&aol,   g_aol);
    cudaGetSymbolAddress((void**)&x1,    g_x1);
    cudaGetSymbolAddress((void**)&tok,   g_tok);
    cudaGetSymbolAddress((void**)&wqkvh, g_wqkvh);
    cudaGetSymbolAddress((void**)&wqkvl, g_wqkvl);
    cudaGetSymbolAddress((void**)&b3,    g_b3);
    cudaGetSymbolAddress((void**)&woh,   g_woh);
    cudaGetSymbolAddress((void**)&wol,   g_wol);
    cudaGetSymbolAddress((void**)&dispb, g_dispb);
    cudaGetSymbolAddress((void**)&hb,    g_hb);
    cudaGetSymbolAddress((void**)&eo,    g_eo);
    cudaGetSymbolAddress((void**)&w1p,   g_w1p);
    cudaGetSymbolAddress((void**)&w2p,   g_w2p);
    cudaGetSymbolAddress((void**)&gates, g_gates);
    cudaGetSymbolAddress((void**)&gp,    g_gp);
    cudaGetSymbolAddress((void**)&gv,    g_gv);
    cudaGetSymbolAddress((void**)&eidx,  g_eidx);
    cudaGetSymbolAddress((void**)&slot,  g_slot);
    cudaGetSymbolAddress((void**)&cnt,   g_cnt);

    cudaFuncSetAttribute(attn_kernel,
                         cudaFuncAttributeMaxDynamicSharedMemorySize, ATTN_SMEM);
    cudaFuncSetAttribute(gemm_bf16w_kernel<1, 1>,
                         cudaFuncAttributeMaxDynamicSharedMemorySize, EXP_SMEM);
    cudaFuncSetAttribute(gemm_bf16w_kernel<0, 0>,
                         cudaFuncAttributeMaxDynamicSharedMemorySize, EXP_SMEM);

    // one-time prep: merged qkv weight split (q scaled by 1/8 exactly),
    // bias concat, wo split, expert weight k-pair packs
    splitw3_kernel<<<D * D / 256, 256>>>(wq, wqkvh, wqkvl, 0,     0.125f);
    splitw3_kernel<<<D * D / 256, 256>>>(wk, wqkvh, wqkvl, D,     1.0f);
    splitw3_kernel<<<D * D / 256, 256>>>(wv, wqkvh, wqkvl, 2 * D, 1.0f);
    biascat_kernel<<<D / 256, 256>>>(bq, b3,         0.125f);
    biascat_kernel<<<D / 256, 256>>>(bk, b3 + D,     1.0f);
    biascat_kernel<<<D / 256, 256>>>(bv, b3 + 2 * D, 1.0f);
    splitw_kernel<<<D * D / 256, 256>>>(wo, woh, wol);
    packw_kernel<<<dim3(F / 256, D / 2, E), 256>>>(w1, w1p, F,
        (long long)D * F, (long long)(D / 2) * F);
    packw_kernel<<<dim3(D / 256, F / 2, E), 256>>>(w2, w2p, D,
        (long long)F * D, (long long)(F / 2) * D);

    // 1) LN1 -> tf32 hi/lo
    ln_split_kernel<<<N, 256>>>(x, ln1g, ln1b, xnh, xnl);
    // 2) merged QKV projection (3xTF32, Nc=3072)
    gemm_t3s_kernel<0><<<dim3(D3 / 128, N / 128), 256>>>(
        xnh, xnl, wqkvh, wqkvl, b3, nullptr, qkv, N, D3, D);
    // 3) attention (reads strided qkv)
    attn_kernel<<<dim3(S / QT, B * H), 128, ATTN_SMEM>>>(
        qkv, qkv + D, qkv + 2 * D, D3, aoh, aol);
    // 4) output projection + residual
    gemm_t3s_kernel<1><<<dim3(D / 128, N / 128), 256>>>(
        aoh, aol, woh, wol, bo, x, x1, N, D, D);
    // 5) LN2
    ln_kernel<<<N, 256>>>(x1, ln2g, ln2b, tok);
    // 6) gate
    gate_kernel<<<N, 256>>>(tok, gw, gates, eidx, gp);
    // 7) routing scan
    scan_kernel<<<1, 256>>>(eidx, gp, slot, gv, cnt);
    // 8) l_aux -> last output element
    laux_kernel<<<1, 256>>>(gates, cnt, out + (out_size - 1));
    // 9) dispatch (writes bf16)
    dispatch_kernel<<<N, 256>>>(tok, slot, dispb);
    // 10) expert GEMM1 (relu, bf16 -> bf16)
    gemm_bf16w_kernel<1, 1><<<dim3(F / 256, CAP / 128, E), 256, EXP_SMEM>>>(
        dispb, w1p, b1, hb, CAP, F, D,
        (long long)CAP * D, (long long)(D / 2) * F, (long long)F, (long long)CAP * F);
    // 11) expert GEMM2 (bf16 -> fp32)
    gemm_bf16w_kernel<0, 0><<<dim3(D / 256, CAP / 128, E), 256, EXP_SMEM>>>(
        hb, w2p, b2, eo, CAP, D, F,
        (long long)CAP * F, (long long)(F / 2) * D, (long long)D, (long long)CAP * D);
    // 12) combine + residual -> output
    combine_kernel<<<N, 256>>>(x1, eo, slot, gv, out);
}

// round 8
// speedup vs baseline: 1.5208x; 1.5208x over previous
#include <cuda_runtime.h>
#include <cstdint>

// ---------------- problem constants ----------------
constexpr int S = 1024, B = 8, D = 1024, H = 16, F = 4096, E = 8;
constexpr int HD = D / H;           // 64
constexpr int N = S * B;            // 8192
constexpr int CAP = 4 * N / E;      // 4096
constexpr int D3 = 3 * D;           // 3072 (merged qkv width)

// ---------------- scratch (device globals; no allocations) ----------------
__device__ uint32_t g_xnh[N * D], g_xnl[N * D];      // LN1 out, tf32 hi/lo
__device__ float    g_qkv[N * D3];                   // merged q|k|v
__device__ uint32_t g_aoh[N * D], g_aol[N * D];      // attn out, tf32 hi/lo
__device__ float g_x1 [N * D];
__device__ float g_tok[N * D];
__device__ uint32_t g_wqkvh[D * D3], g_wqkvl[D * D3];
__device__ float    g_b3[D3];
__device__ uint32_t g_woh[D * D], g_wol[D * D];
__device__ uint16_t g_dispb[E * CAP * D];            // bf16 dispatched tokens
__device__ uint16_t g_hb  [134217728];               // E*CAP*F bf16 hidden
__device__ float    g_eo  [E * CAP * D];
__device__ uint32_t g_w1p [(D / 2) * F * E];         // bf16 k-pair packed w1
__device__ uint32_t g_w2p [(F / 2) * D * E];         // bf16 k-pair packed w2
__device__ float g_gates[N * E];
__device__ int   g_eidx[N];
__device__ float g_gp  [N];
__device__ int   g_slot[N];
__device__ float g_gv  [N];
__device__ int   g_cnt [E];

// ---------------- helpers ----------------
__device__ __forceinline__ uint32_t f2tf32(float f) {
    uint32_t u;
    asm("cvt.rna.tf32.f32 %0, %1;" : "=r"(u) : "f"(f));
    return u;
}
__device__ __forceinline__ uint32_t packbf2(float lo, float hi) {
    uint32_t d;
    asm("cvt.rn.bf16x2.f32 %0, %1, %2;" : "=r"(d) : "f"(hi), "f"(lo));
    return d;
}

// ---------------- weight split (with column offset + exact pow2 scale) ------
__global__ void __launch_bounds__(256) splitw3_kernel(
    const float* __restrict__ W, uint32_t* __restrict__ Wh3,
    uint32_t* __restrict__ Wl3, int colOff, float scale)
{
    int i = blockIdx.x * 256 + threadIdx.x;   // over D*D
    int d = i >> 10, e = i & 1023;
    float v = W[i] * scale;                   // scale is power of 2: exact
    uint32_t h = f2tf32(v);
    Wh3[(long long)d * D3 + colOff + e] = h;
    Wl3[(long long)d * D3 + colOff + e] = f2tf32(v - __uint_as_float(h));
}
__global__ void __launch_bounds__(256) splitw_kernel(
    const float* __restrict__ W, uint32_t* __restrict__ Wh,
    uint32_t* __restrict__ Wl)
{
    int i = blockIdx.x * 256 + threadIdx.x;
    float v = W[i];
    uint32_t h = f2tf32(v);
    Wh[i] = h;
    Wl[i] = f2tf32(v - __uint_as_float(h));
}
// fused 3-way bias concat (one launch instead of three)
__global__ void __launch_bounds__(256) biascat3_kernel(
    const float* __restrict__ bq, const float* __restrict__ bk,
    const float* __restrict__ bv, float* __restrict__ dst)
{
    int i = blockIdx.x * 256 + threadIdx.x;   // over D
    dst[i]         = bq[i] * 0.125f;
    dst[i + D]     = bk[i];
    dst[i + 2 * D] = bv[i];
}

// ---------------- LayerNorm (fp32 out) ----------------
__global__ void __launch_bounds__(256) ln_kernel(const float* __restrict__ x,
                                                 const float* __restrict__ gam,
                                                 const float* __restrict__ bet,
                                                 float* __restrict__ y) {
    int n = blockIdx.x;
    const float* row = x + (long)n * D;
    int t = threadIdx.x;
    float s = 0.f, s2 = 0.f;
    for (int d = t; d < D; d += 256) { float v = row[d]; s += v; s2 += v * v; }
    __shared__ float r1[256], r2[256];
    r1[t] = s; r2[t] = s2; __syncthreads();
    for (int st = 128; st > 0; st >>= 1) {
        if (t < st) { r1[t] += r1[t + st]; r2[t] += r2[t + st]; }
        __syncthreads();
    }
    float mean = r1[0] / D;
    float var  = r2[0] / D - mean * mean;
    float inv  = rsqrtf(var + 1e-5f);
    float* yo = y + (long)n * D;
    for (int d = t; d < D; d += 256)
        yo[d] = (row[d] - mean) * inv * gam[d] + bet[d];
}

// ---------------- LayerNorm (tf32 hi/lo out) ----------------
__global__ void __launch_bounds__(256) ln_split_kernel(
    const float* __restrict__ x, const float* __restrict__ gam,
    const float* __restrict__ bet,
    uint32_t* __restrict__ yh, uint32_t* __restrict__ yl)
{
    int n = blockIdx.x;
    const float* row = x + (long)n * D;
    int t = threadIdx.x;
    float s = 0.f, s2 = 0.f;
    for (int d = t; d < D; d += 256) { float v = row[d]; s += v; s2 += v * v; }
    __shared__ float r1[256], r2[256];
    r1[t] = s; r2[t] = s2; __syncthreads();
    for (int st = 128; st > 0; st >>= 1) {
        if (t < st) { r1[t] += r1[t + st]; r2[t] += r2[t + st]; }
        __syncthreads();
    }
    float mean = r1[0] / D;
    float var  = r2[0] / D - mean * mean;
    float inv  = rsqrtf(var + 1e-5f);
    for (int d = t; d < D; d += 256) {
        float v = (row[d] - mean) * inv * gam[d] + bet[d];
        uint32_t h = f2tf32(v);
        yh[(long)n * D + d] = h;
        yl[(long)n * D + d] = f2tf32(v - __uint_as_float(h));
    }
}

// ---------------- 3xTF32 GEMM, pre-split, single-buffer, occ=2 --------------
// C[M,Nc] = (Ah+Al)@(Bh+Bl) + bias (+ resid). Block 128x128, warp 64x32.
template<int HAS_RESID>
__global__ void __launch_bounds__(256, 2) gemm_t3s_kernel(
    const uint32_t* __restrict__ Ah, const uint32_t* __restrict__ Al,
    const uint32_t* __restrict__ Bh, const uint32_t* __restrict__ Bl,
    const float* __restrict__ bias, const float* __restrict__ resid,
    float* __restrict__ C, int M, int Nc, int K)
{
    __shared__ uint32_t As_h[16][136], As_l[16][136];
    __shared__ uint32_t Bs_h[16][136], Bs_l[16][136];

    int t    = threadIdx.x;
    int wid  = t >> 5, lane = t & 31;
    int gid  = lane >> 2, tig = lane & 3;
    int wm0  = (wid & 1) * 64;
    int wn0  = (wid >> 1) * 32;
    int m0   = blockIdx.y * 128, n0 = blockIdx.x * 128;

    float acc[4][4][4];
#pragma unroll
    for (int mt = 0; mt < 4; mt++)
#pragma unroll
        for (int nt = 0; nt < 4; nt++)
#pragma unroll
            for (int r = 0; r < 4; r++) acc[mt][nt][r] = 0.f;

    for (int k0 = 0; k0 < K; k0 += 16) {
#pragma unroll
        for (int l = 0; l < 2; l++) {
            int f  = t + l * 256;
            int r  = f >> 2;
            int c4 = (f & 3) * 4;
            uint4 vh = *(const uint4*)(Ah + (long long)(m0 + r) * K + k0 + c4);
            uint4 vl = *(const uint4*)(Al + (long long)(m0 + r) * K + k0 + c4);
            As_h[c4 + 0][r] = vh.x; As_h[c4 + 1][r] = vh.y;
            As_h[c4 + 2][r] = vh.z; As_h[c4 + 3][r] = vh.w;
            As_l[c4 + 0][r] = vl.x; As_l[c4 + 1][r] = vl.y;
            As_l[c4 + 2][r] = vl.z; As_l[c4 + 3][r] = vl.w;
        }
#pragma unroll
        for (int l = 0; l < 2; l++) {
            int f  = t + l * 256;
            int r  = f >> 5;
            int c4 = (f & 31) * 4;
            *(uint4*)(&Bs_h[r][c4]) =
                *(const uint4*)(Bh + (long long)(k0 + r) * Nc + n0 + c4);
            *(uint4*)(&Bs_l[r][c4]) =
                *(const uint4*)(Bl + (long long)(k0 + r) * Nc + n0 + c4);
        }
        __syncthreads();

#pragma unroll
        for (int kb = 0; kb < 16; kb += 8) {
            uint32_t fah[4][4], fal[4][4], fbh[4][2], fbl[4][2];
#pragma unroll
            for (int mt = 0; mt < 4; mt++) {
                int mm = wm0 + mt * 16 + gid;
                fah[mt][0] = As_h[kb + tig    ][mm];
                fah[mt][1] = As_h[kb + tig    ][mm + 8];
                fah[mt][2] = As_h[kb + tig + 4][mm];
                fah[mt][3] = As_h[kb + tig + 4][mm + 8];
                fal[mt][0] = As_l[kb + tig    ][mm];
                fal[mt][1] = As_l[kb + tig    ][mm + 8];
                fal[mt][2] = As_l[kb + tig + 4][mm];
                fal[mt][3] = As_l[kb + tig + 4][mm + 8];
            }
#pragma unroll
            for (int nt = 0; nt < 4; nt++) {
                int nn = wn0 + nt * 8 + gid;
                fbh[nt][0] = Bs_h[kb + tig    ][nn];
                fbh[nt][1] = Bs_h[kb + tig + 4][nn];
                fbl[nt][0] = Bs_l[kb + tig    ][nn];
                fbl[nt][1] = Bs_l[kb + tig + 4][nn];
            }
#pragma unroll
            for (int mt = 0; mt < 4; mt++)
#pragma unroll
                for (int nt = 0; nt < 4; nt++) {
                    asm volatile(
                        "mma.sync.aligned.m16n8k8.row.col.f32.tf32.tf32.f32 "
                        "{%0,%1,%2,%3}, {%4,%5,%6,%7}, {%8,%9}, {%0,%1,%2,%3};"
                        : "+f"(acc[mt][nt][0]), "+f"(acc[mt][nt][1]),
                          "+f"(acc[mt][nt][2]), "+f"(acc[mt][nt][3])
                        : "r"(fah[mt][0]), "r"(fah[mt][1]), "r"(fah[mt][2]), "r"(fah[mt][3]),
                          "r"(fbl[nt][0]), "r"(fbl[nt][1]));
                    asm volatile(
                        "mma.sync.aligned.m16n8k8.row.col.f32.tf32.tf32.f32 "
                        "{%0,%1,%2,%3}, {%4,%5,%6,%7}, {%8,%9}, {%0,%1,%2,%3};"
                        : "+f"(acc[mt][nt][0]), "+f"(acc[mt][nt][1]),
                          "+f"(acc[mt][nt][2]), "+f"(acc[mt][nt][3])
                        : "r"(fal[mt][0]), "r"(fal[mt][1]), "r"(fal[mt][2]), "r"(fal[mt][3]),
                          "r"(fbh[nt][0]), "r"(fbh[nt][1]));
                    asm volatile(
                        "mma.sync.aligned.m16n8k8.row.col.f32.tf32.tf32.f32 "
                        "{%0,%1,%2,%3}, {%4,%5,%6,%7}, {%8,%9}, {%0,%1,%2,%3};"
                        : "+f"(acc[mt][nt][0]), "+f"(acc[mt][nt][1]),
                          "+f"(acc[mt][nt][2]), "+f"(acc[mt][nt][3])
                        : "r"(fah[mt][0]), "r"(fah[mt][1]), "r"(fah[mt][2]), "r"(fah[mt][3]),
                          "r"(fbh[nt][0]), "r"(fbh[nt][1]));
                }
        }
        __syncthreads();
    }

#pragma unroll
    for (int mt = 0; mt < 4; mt++) {
#pragma unroll
        for (int nt = 0; nt < 4; nt++) {
            int row = m0 + wm0 + mt * 16 + gid;
            int col = n0 + wn0 + nt * 8 + 2 * tig;
            float b0 = bias[col], b1 = bias[col + 1];
            float c0 = acc[mt][nt][0] + b0;
            float c1 = acc[mt][nt][1] + b1;
            float c2 = acc[mt][nt][2] + b0;
            float c3 = acc[mt][nt][3] + b1;
            if (HAS_RESID) {
                float2 r0 = *(const float2*)(resid + (long long)row * Nc + col);
                float2 r1 = *(const float2*)(resid + (long long)(row + 8) * Nc + col);
                c0 += r0.x; c1 += r0.y; c2 += r1.x; c3 += r1.y;
            }
            *(float2*)(C + (long long)row * Nc + col)       = make_float2(c0, c1);
            *(float2*)(C + (long long)(row + 8) * Nc + col) = make_float2(c2, c3);
        }
    }
}

// ---------------- weight packing: fp32 [K][Nc] -> bf16 k-pair u32 [K/2][Nc] --
__global__ void __launch_bounds__(256) packw_kernel(
    const float* __restrict__ W, uint32_t* __restrict__ P, int Nc,
    long long sW, long long sP)
{
    int n  = blockIdx.x * 256 + threadIdx.x;
    int k2 = blockIdx.y;
    int z  = blockIdx.z;
    const float* w = W + (long long)z * sW + (long long)(2 * k2) * Nc + n;
    P[(long long)z * sP + (long long)k2 * Nc + n] = packbf2(w[0], w[Nc]);
}

// ---------------- bf16 expert GEMM: block 128x256, warp 64x64, k32 ----------
// C = op(A[M,K](bf16) @ Bp(packed bf16 pairs [K/2][Nc]) + bias)
// Early-exits tiles beyond the expert's actual token count cnt[z]:
// capacity buffer is 4x oversized, ~75% of tiles carry no live rows.
constexpr int EXP_SMEM = 2 * 16 * 136 * 4 + 2 * 16 * 264 * 4;  // 51200 B

template<int RELU, int OUTBF>
__global__ void __launch_bounds__(256) gemm_bf16w_kernel(
    const uint16_t* __restrict__ A, const uint32_t* __restrict__ Bp,
    const float* __restrict__ bias, void* __restrict__ Cout,
    const int* __restrict__ cnt,
    int M, int Nc, int K,
    long long sA, long long sB, long long sBias, long long sC)
{
    int z = blockIdx.z;
    int m0 = blockIdx.y * 128, n0 = blockIdx.x * 256;
    if (m0 >= cnt[z]) return;   // no live rows in this tile: outputs never read

    extern __shared__ uint32_t dyn[];
    uint32_t* As = dyn;                    // [2][16][136]
    uint32_t* Bs = dyn + 2 * 16 * 136;     // [2][16][264]

    A    += (long long)z * sA;
    Bp   += (long long)z * sB;
    bias += (long long)z * sBias;

    int t    = threadIdx.x;
    int wid  = t >> 5, lane = t & 31;
    int gid  = lane >> 2, tig = lane & 3;
    int wm0  = (wid & 1) * 64;
    int wn0  = (wid >> 1) * 64;            // 4 n-warps * 64

    int am  = t & 127, ahh = t >> 7;       // A: row am, octet ahh and ahh+2
    int bk  = t >> 4,  bn  = (t & 15) * 16;

    float acc[4][8][4];
#pragma unroll
    for (int mt = 0; mt < 4; mt++)
#pragma unroll
        for (int nt = 0; nt < 8; nt++)
#pragma unroll
            for (int r = 0; r < 4; r++) acc[mt][nt][r] = 0.f;

    auto stageA = [&](int buf, uint4 va0, uint4 va1) {
        uint32_t* as = As + buf * (16 * 136);
        as[(ahh * 4 + 0) * 136 + am] = va0.x;
        as[(ahh * 4 + 1) * 136 + am] = va0.y;
        as[(ahh * 4 + 2) * 136 + am] = va0.z;
        as[(ahh * 4 + 3) * 136 + am] = va0.w;
        as[((ahh + 2) * 4 + 0) * 136 + am] = va1.x;
        as[((ahh + 2) * 4 + 1) * 136 + am] = va1.y;
        as[((ahh + 2) * 4 + 2) * 136 + am] = va1.z;
        as[((ahh + 2) * 4 + 3) * 136 + am] = va1.w;
    };
    auto stageB = [&](int buf, const uint4* vb) {
        uint32_t* bs = Bs + buf * (16 * 264);
#pragma unroll
        for (int j = 0; j < 4; j++)
            *(uint4*)&bs[bk * 264 + bn + j * 4] = vb[j];
    };

    const int nIter = K / 32;
    {   // stage tile 0
        uint4 va0 = *(const uint4*)(A + (long long)(m0 + am) * K + ahh * 8);
        uint4 va1 = *(const uint4*)(A + (long long)(m0 + am) * K + (ahh + 2) * 8);
        uint4 vb[4];
#pragma unroll
        for (int j = 0; j < 4; j++)
            vb[j] = *(const uint4*)(Bp + (long long)bk * Nc + n0 + bn + j * 4);
        stageA(0, va0, va1);
        stageB(0, vb);
    }
    __syncthreads();

    for (int it = 0; it < nIter; ++it) {
        int cur = it & 1;
        uint4 va0, va1, vb[4];
        bool pf = (it + 1 < nIter);
        if (pf) {
            long long ka = (long long)(m0 + am) * K + (it + 1) * 32;
            va0 = *(const uint4*)(A + ka + ahh * 8);
            va1 = *(const uint4*)(A + ka + (ahh + 2) * 8);
            long long kb = (long long)(it + 1) * 16 + bk;
#pragma unroll
            for (int j = 0; j < 4; j++)
                vb[j] = *(const uint4*)(Bp + kb * Nc + n0 + bn + j * 4);
        }
        const uint32_t* as = As + cur * (16 * 136);
        const uint32_t* bs = Bs + cur * (16 * 264);
#pragma unroll
        for (int kb2 = 0; kb2 < 2; kb2++) {
            int ko = kb2 * 8;
            uint32_t af[4][4], bfr[8][2];
#pragma unroll
            for (int mt = 0; mt < 4; mt++) {
                int mm = wm0 + mt * 16 + gid;
                af[mt][0] = as[(ko + tig    ) * 136 + mm];
                af[mt][1] = as[(ko + tig    ) * 136 + mm + 8];
                af[mt][2] = as[(ko + tig + 4) * 136 + mm];
                af[mt][3] = as[(ko + tig + 4) * 136 + mm + 8];
            }
#pragma unroll
            for (int nt = 0; nt < 8; nt++) {
                int nn = wn0 + nt * 8 + gid;
                bfr[nt][0] = bs[(ko + tig    ) * 264 + nn];
                bfr[nt][1] = bs[(ko + tig + 4) * 264 + nn];
            }
#pragma unroll
            for (int mt = 0; mt < 4; mt++)
#pragma unroll
                for (int nt = 0; nt < 8; nt++) {
                    asm volatile(
                        "mma.sync.aligned.m16n8k16.row.col.f32.bf16.bf16.f32 "
                        "{%0,%1,%2,%3}, {%4,%5,%6,%7}, {%8,%9}, {%0,%1,%2,%3};"
                        : "+f"(acc[mt][nt][0]), "+f"(acc[mt][nt][1]),
                          "+f"(acc[mt][nt][2]), "+f"(acc[mt][nt][3])
                        : "r"(af[mt][0]), "r"(af[mt][1]),
                          "r"(af[mt][2]), "r"(af[mt][3]),
                          "r"(bfr[nt][0]), "r"(bfr[nt][1]));
                }
        }
        if (pf) {
            stageA(cur ^ 1, va0, va1);
            stageB(cur ^ 1, vb);
        }
        __syncthreads();
    }

#pragma unroll
    for (int mt = 0; mt < 4; mt++) {
#pragma unroll
        for (int nt = 0; nt < 8; nt++) {
            int row = m0 + wm0 + mt * 16 + gid;
            int col = n0 + wn0 + nt * 8 + 2 * tig;
            float b0 = bias[col], b1 = bias[col + 1];
            float c0 = acc[mt][nt][0] + b0;
            float c1 = acc[mt][nt][1] + b1;
            float c2 = acc[mt][nt][2] + b0;
            float c3 = acc[mt][nt][3] + b1;
            if (RELU) {
                c0 = fmaxf(c0, 0.f); c1 = fmaxf(c1, 0.f);
                c2 = fmaxf(c2, 0.f); c3 = fmaxf(c3, 0.f);
            }
            if (OUTBF) {
                uint16_t* Cb = (uint16_t*)Cout + (long long)z * sC;
                *(uint32_t*)(Cb + (long long)row * Nc + col)       = packbf2(c0, c1);
                *(uint32_t*)(Cb + (long long)(row + 8) * Nc + col) = packbf2(c2, c3);
            } else {
                float* Cf = (float*)Cout + (long long)z * sC;
                *(float2*)(Cf + (long long)row * Nc + col)       = make_float2(c0, c1);
                *(float2*)(Cf + (long long)(row + 8) * Nc + col) = make_float2(c2, c3);
            }
        }
    }
}

// ---------------- flash attention (fp32, causal; strided qkv input) ---------
constexpr int QT = 128, KT = 64;
constexpr int ATTN_SMEM = (QT * (HD + 1) + 2 * KT * HD) * 4;  // 66048 B

__global__ void __launch_bounds__(128) attn_kernel(
    const float* __restrict__ Q, const float* __restrict__ Kg,
    const float* __restrict__ Vg, int LD,
    uint32_t* __restrict__ Oh, uint32_t* __restrict__ Ol)
{
    extern __shared__ float sm[];
    float* q_s = sm;
    float* k_s = sm + QT * (HD + 1);
    float* v_s = k_s + KT * HD;

    int bh = blockIdx.y;
    int h  = bh % H, b = bh / H;
    int q0 = blockIdx.x * QT;
    int t  = threadIdx.x;
    long base = (long)b * LD + (long)h * HD;
    long rs   = (long)B * LD;    // row stride per s

    for (int f = t; f < QT * HD / 4; f += 128) {
        int r  = f / (HD / 4);
        int c4 = (f % (HD / 4)) * 4;
        float4 v = *(const float4*)(Q + (long)(q0 + r) * rs + base + c4);
        q_s[r * (HD + 1) + c4 + 0] = v.x;
        q_s[r * (HD + 1) + c4 + 1] = v.y;
        q_s[r * (HD + 1) + c4 + 2] = v.z;
        q_s[r * (HD + 1) + c4 + 3] = v.w;
    }
    __syncthreads();

    int sq = q0 + t;
    float m_run = -1e30f, l_run = 0.f;
    float acc[HD];
#pragma unroll
    for (int d = 0; d < HD; d++) acc[d] = 0.f;

    int kend = q0 + QT;
    for (int k0 = 0; k0 < kend; k0 += KT) {
        for (int f = t; f < KT * HD / 4; f += 128) {
            int r  = f / (HD / 4);
            int c4 = (f % (HD / 4)) * 4;
            *(float4*)(&k_s[r * HD + c4]) =
                *(const float4*)(Kg + (long)(k0 + r) * rs + base + c4);
            *(float4*)(&v_s[r * HD + c4]) =
                *(const float4*)(Vg + (long)(k0 + r) * rs + base + c4);
        }
        __syncthreads();

        float s[KT];
#pragma unroll
        for (int j = 0; j < KT; j++) s[j] = 0.f;
        for (int d = 0; d < HD; d++) {
            float qd = q_s[t * (HD + 1) + d];
#pragma unroll
            for (int j = 0; j < KT; j++) s[j] += qd * k_s[j * HD + d];
        }
        float mnew = m_run;
#pragma unroll
        for (int j = 0; j < KT; j++) {
            if (k0 + j > sq) s[j] = -1e9f;
            mnew = fmaxf(mnew, s[j]);
        }
        float corr = __expf(m_run - mnew);
        l_run *= corr;
#pragma unroll
        for (int d = 0; d < HD; d++) acc[d] *= corr;
        for (int j = 0; j < KT; j++) {
            float p = __expf(s[j] - mnew);
            l_run += p;
#pragma unroll
            for (int d = 0; d < HD; d++) acc[d] += p * v_s[j * HD + d];
        }
        m_run = mnew;
        __syncthreads();
    }
    float inv = 1.f / l_run;
    long off = (long)sq * (B * D) + (long)b * D + (long)h * HD;
#pragma unroll
    for (int d = 0; d < HD; d++) {
        float v = acc[d] * inv;
        uint32_t hi = f2tf32(v);
        Oh[off + d] = hi;
        Ol[off + d] = f2tf32(v - __uint_as_float(hi));
    }
}

// ---------------- gate: logits, softmax, argmax (fp32, exact) ----------------
__global__ void __launch_bounds__(256) gate_kernel(
    const float* __restrict__ tok, const float* __restrict__ gw,
    float* __restrict__ gates, int* __restrict__ eidx, float* __restrict__ gp)
{
    int n = blockIdx.x, t = threadIdx.x;
    const float* row = tok + (long)n * D;
    float p[E];
#pragma unroll
    for (int e = 0; e < E; e++) p[e] = 0.f;
    for (int d = t; d < D; d += 256) {
        float xv = row[d];
        const float* w = gw + (long)d * E;
#pragma unroll
        for (int e = 0; e < E; e++) p[e] += xv * w[e];
    }
    __shared__ float red[256 * E];
#pragma unroll
    for (int e = 0; e < E; e++) red[t * E + e] = p[e];
    __syncthreads();
    for (int st = 128; st > 0; st >>= 1) {
        if (t < st)
#pragma unroll
            for (int e = 0; e < E; e++) red[t * E + e] += red[(t + st) * E + e];
        __syncthreads();
    }
    if (t == 0) {
        float lg[E], mx = -1e30f;
#pragma unroll
        for (int e = 0; e < E; e++) { lg[e] = red[e]; mx = fmaxf(mx, lg[e]); }
        float sum = 0.f, pr[E];
#pragma unroll
        for (int e = 0; e < E; e++) { pr[e] = __expf(lg[e] - mx); sum += pr[e]; }
        float inv = 1.f / sum;
        int best = 0; float bv = -1e30f;
#pragma unroll
        for (int e = 0; e < E; e++) {
            float g = pr[e] * inv;
            gates[(long)n * E + e] = g;
            if (g > bv) { bv = g; best = e; }
        }
        eidx[n] = best;
        gp[n]   = bv;
    }
}

// ---------------- routing scan (deterministic, single block) ----------------
__global__ void __launch_bounds__(256) scan_kernel(
    const int* __restrict__ eidx, const float* __restrict__ gp,
    int* __restrict__ slot, float* __restrict__ gv, int* __restrict__ cnt)
{
    __shared__ int scnt[256][E];
    int t = threadIdx.x;
    int c[E];
#pragma unroll
    for (int e = 0; e < E; e++) c[e] = 0;
    int n0 = t * (N / 256);
    for (int i = 0; i < N / 256; i++) c[eidx[n0 + i]]++;
#pragma unroll
    for (int e = 0; e < E; e++) scnt[t][e] = c[e];
    __syncthreads();
    if (t < E) {
        int run = 0;
        for (int j = 0; j < 256; j++) { int tmp = scnt[j][t]; scnt[j][t] = run; run += tmp; }
        cnt[t] = run;
    }
    __syncthreads();
    int off[E];
#pragma unroll
    for (int e = 0; e < E; e++) off[e] = scnt[t][e];
    for (int i = 0; i < N / 256; i++) {
        int n = n0 + i;
        int e = eidx[n];
        int l = off[e]++;
        bool keep = (l < CAP);
        slot[n] = keep ? e * CAP + l : -1;
        gv[n]   = keep ? gp[n] : 0.f;
    }
}

// ---------------- l_aux (deterministic tree reduce) ----------------
__global__ void __launch_bounds__(256) laux_kernel(
    const float* __restrict__ gates, const int* __restrict__ cnt,
    float* __restrict__ out_laux)
{
    __shared__ float red[256];
    int t = threadIdx.x;
    float loc[E];
#pragma unroll
    for (int e = 0; e < E; e++) loc[e] = 0.f;
    for (int n = t; n < N; n += 256)
#pragma unroll
        for (int e = 0; e < E; e++) loc[e] += gates[(long)n * E + e];
    float total[E];
    for (int e = 0; e < E; e++) {
        red[t] = loc[e]; __syncthreads();
        for (int st = 128; st > 0; st >>= 1) {
            if (t < st) red[t] += red[t + st];
            __syncthreads();
        }
        if (t == 0) total[e] = red[0];
        __syncthreads();
    }
    if (t == 0) {
        float la = 0.f;
        for (int e = 0; e < E; e++)
            la += (total[e] / N) * ((float)cnt[e] / N);
        *out_laux = (float)E * la;
    }
}

// ---------------- dispatch / combine ----------------
__global__ void __launch_bounds__(256) dispatch_kernel(
    const float* __restrict__ tok, const int* __restrict__ slot,
    uint16_t* __restrict__ dispb)
{
    int n = blockIdx.x;
    int s = slot[n];
    if (s < 0) return;
    int t = threadIdx.x;
    float4 v = ((const float4*)(tok + (long)n * D))[t];
    uint2 o;
    o.x = packbf2(v.x, v.y);
    o.y = packbf2(v.z, v.w);
    *(uint2*)(dispb + (long)s * D + t * 4) = o;
}

__global__ void __launch_bounds__(256) combine_kernel(
    const float* __restrict__ x1, const float* __restrict__ eo,
    const int* __restrict__ slot, const float* __restrict__ gv,
    float* __restrict__ out)
{
    int n = blockIdx.x, t = threadIdx.x;
    int s = slot[n];
    float g = gv[n];
    float4 r = ((const float4*)(x1 + (long)n * D))[t];
    if (s >= 0) {
        float4 v = ((const float4*)(eo + (long)s * D))[t];
        r.x += v.x * g; r.y += v.y * g; r.z += v.z * g; r.w += v.w * g;
    }
    ((float4*)(out + (long)n * D))[t] = r;
}

// ---------------- launch ----------------
extern "C" void kernel_launch(void* const* d_in, const int* in_sizes, int n_in,
                              void* d_out, int out_size) {
    const float* x    = (const float*)d_in[0];
    const float* wq   = (const float*)d_in[2];
    const float* bq   = (const float*)d_in[3];
    const float* wk   = (const float*)d_in[4];
    const float* bk   = (const float*)d_in[5];
    const float* wv   = (const float*)d_in[6];
    const float* bv   = (const float*)d_in[7];
    const float* wo   = (const float*)d_in[8];
    const float* bo   = (const float*)d_in[9];
    const float* ln1g = (const float*)d_in[10];
    const float* ln1b = (const float*)d_in[11];
    const float* ln2g = (const float*)d_in[12];
    const float* ln2b = (const float*)d_in[13];
    const float* gw   = (const float*)d_in[14];
    const float* w1   = (const float*)d_in[15];
    const float* b1   = (const float*)d_in[16];
    const float* w2   = (const float*)d_in[17];
    const float* b2   = (const float*)d_in[18];
    float* out = (float*)d_out;

    float *qkv, *x1, *tok, *eo, *gates, *gp, *gv, *b3;
    uint32_t *xnh, *xnl, *aoh, *aol, *wqkvh, *wqkvl, *woh, *wol, *w1p, *w2p;
    uint16_t *dispb, *hb;
    int *eidx, *slot, *cnt;
    cudaGetSymbolAddress((void**)&xnh,   g_xnh);
    cudaGetSymbolAddress((void**)&xnl,   g_xnl);
    cudaGetSymbolAddress((void**)&qkv,   g_qkv);
    cudaGetSymbolAddress((void**)&aoh,   g_aoh);
    cudaGetSymbolAddress((void**)&aol,   g_aol);
    cudaGetSymbolAddress((void**)&x1,    g_x1);
    cudaGetSymbolAddress((void**)&tok,   g_tok);
    cudaGetSymbolAddress((void**)&wqkvh, g_wqkvh);
    cudaGetSymbolAddress((void**)&wqkvl, g_wqkvl);
    cudaGetSymbolAddress((void**)&b3,    g_b3);
    cudaGetSymbolAddress((void**)&woh,   g_woh);
    cudaGetSymbolAddress((void**)&wol,   g_wol);
    cudaGetSymbolAddress((void**)&dispb, g_dispb);
    cudaGetSymbolAddress((void**)&hb,    g_hb);
    cudaGetSymbolAddress((void**)&eo,    g_eo);
    cudaGetSymbolAddress((void**)&w1p,   g_w1p);
    cudaGetSymbolAddress((void**)&w2p,   g_w2p);
    cudaGetSymbolAddress((void**)&gates, g_gates);
    cudaGetSymbolAddress((void**)&gp,    g_gp);
    cudaGetSymbolAddress((void**)&gv,    g_gv);
    cudaGetSymbolAddress((void**)&eidx,  g_eidx);
    cudaGetSymbolAddress((void**)&slot,  g_slot);
    cudaGetSymbolAddress((void**)&cnt,   g_cnt);

    cudaFuncSetAttribute(attn_kernel,
                         cudaFuncAttributeMaxDynamicSharedMemorySize, ATTN_SMEM);
    cudaFuncSetAttribute(gemm_bf16w_kernel<1, 1>,
                         cudaFuncAttributeMaxDynamicSharedMemorySize, EXP_SMEM);
    cudaFuncSetAttribute(gemm_bf16w_kernel<0, 0>,
                         cudaFuncAttributeMaxDynamicSharedMemorySize, EXP_SMEM);

    // one-time prep: merged qkv weight split (q scaled by 1/8 exactly),
    // fused bias concat, wo split, expert weight k-pair packs
    splitw3_kernel<<<D * D / 256, 256>>>(wq, wqkvh, wqkvl, 0,     0.125f);
    splitw3_kernel<<<D * D / 256, 256>>>(wk, wqkvh, wqkvl, D,     1.0f);
    splitw3_kernel<<<D * D / 256, 256>>>(wv, wqkvh, wqkvl, 2 * D, 1.0f);
    biascat3_kernel<<<D / 256, 256>>>(bq, bk, bv, b3);
    splitw_kernel<<<D * D / 256, 256>>>(wo, woh, wol);
    packw_kernel<<<dim3(F / 256, D / 2, E), 256>>>(w1, w1p, F,
        (long long)D * F, (long long)(D / 2) * F);
    packw_kernel<<<dim3(D / 256, F / 2, E), 256>>>(w2, w2p, D,
        (long long)F * D, (long long)(F / 2) * D);

    // 1) LN1 -> tf32 hi/lo
    ln_split_kernel<<<N, 256>>>(x, ln1g, ln1b, xnh, xnl);
    // 2) merged QKV projection (3xTF32, Nc=3072)
    gemm_t3s_kernel<0><<<dim3(D3 / 128, N / 128), 256>>>(
        xnh, xnl, wqkvh, wqkvl, b3, nullptr, qkv, N, D3, D);
    // 3) attention (reads strided qkv)
    attn_kernel<<<dim3(S / QT, B * H), 128, ATTN_SMEM>>>(
        qkv, qkv + D, qkv + 2 * D, D3, aoh, aol);
    // 4) output projection + residual
    gemm_t3s_kernel<1><<<dim3(D / 128, N / 128), 256>>>(
        aoh, aol, woh, wol, bo, x, x1, N, D, D);
    // 5) LN2
    ln_kernel<<<N, 256>>>(x1, ln2g, ln2b, tok);
    // 6) gate
    gate_kernel<<<N, 256>>>(tok, gw, gates, eidx, gp);
    // 7) routing scan
    scan_kernel<<<1, 256>>>(eidx, gp, slot, gv, cnt);
    // 8) l_aux -> last output element
    laux_kernel<<<1, 256>>>(gates, cnt, out + (out_size - 1));
    // 9) dispatch (writes bf16)
    dispatch_kernel<<<N, 256>>>(tok, slot, dispb);
    // 10) expert GEMM1 (relu, bf16 -> bf16) — only live tiles compute
    gemm_bf16w_kernel<1, 1><<<dim3(F / 256, CAP / 128, E), 256, EXP_SMEM>>>(
        dispb, w1p, b1, hb, cnt, CAP, F, D,
        (long long)CAP * D, (long long)(D / 2) * F, (long long)F, (long long)CAP * F);
    // 11) expert GEMM2 (bf16 -> fp32) — only live tiles compute
    gemm_bf16w_kernel<0, 0><<<dim3(D / 256, CAP / 128, E), 256, EXP_SMEM>>>(
        hb, w2p, b2, eo, cnt, CAP, D, F,
        (long long)CAP * F, (long long)(F / 2) * D, (long long)D, (long long)CAP * D);
    // 12) combine + residual -> output
    combine_kernel<<<N, 256>>>(x1, eo, slot, gv, out);
}

// round 9
// speedup vs baseline: 1.5265x; 1.0038x over previous
#include <cuda_runtime.h>
#include <cstdint>

// ---------------- problem constants ----------------
constexpr int S = 1024, B = 8, D = 1024, H = 16, F = 4096, E = 8;
constexpr int HD = D / H;           // 64
constexpr int N = S * B;            // 8192
constexpr int CAP = 4 * N / E;      // 4096
constexpr int D3 = 3 * D;           // 3072 (merged qkv width)

// ---------------- scratch (device globals; no allocations) ----------------
__device__ uint32_t g_xnh[N * D], g_xnl[N * D];      // LN1 out, tf32 hi/lo
__device__ float    g_qkv[N * D3];                   // merged q|k|v
__device__ uint32_t g_aoh[N * D], g_aol[N * D];      // attn out, tf32 hi/lo
__device__ float g_x1 [N * D];
__device__ float g_tok[N * D];
__device__ uint32_t g_wqkvh[D * D3], g_wqkvl[D * D3];
__device__ float    g_b3[D3];
__device__ uint32_t g_woh[D * D], g_wol[D * D];
__device__ uint16_t g_dispb[E * CAP * D];            // bf16 dispatched tokens
__device__ uint16_t g_hb  [134217728];               // E*CAP*F bf16 hidden
__device__ float    g_eo  [E * CAP * D];
__device__ uint32_t g_w1p [(D / 2) * F * E];         // bf16 k-pair packed w1
__device__ uint32_t g_w2p [(F / 2) * D * E];         // bf16 k-pair packed w2
__device__ float g_gates[N * E];
__device__ int   g_eidx[N];
__device__ float g_gp  [N];
__device__ int   g_slot[N];
__device__ float g_gv  [N];
__device__ int   g_cnt [E];

// ---------------- helpers ----------------
__device__ __forceinline__ uint32_t f2tf32(float f) {
    uint32_t u;
    asm("cvt.rna.tf32.f32 %0, %1;" : "=r"(u) : "f"(f));
    return u;
}
__device__ __forceinline__ uint32_t packbf2(float lo, float hi) {
    uint32_t d;
    asm("cvt.rn.bf16x2.f32 %0, %1, %2;" : "=r"(d) : "f"(hi), "f"(lo));
    return d;
}

// ---------------- weight split (with column offset + exact pow2 scale) ------
__global__ void __launch_bounds__(256) splitw3_kernel(
    const float* __restrict__ W, uint32_t* __restrict__ Wh3,
    uint32_t* __restrict__ Wl3, int colOff, float scale)
{
    int i = blockIdx.x * 256 + threadIdx.x;   // over D*D
    int d = i >> 10, e = i & 1023;
    float v = W[i] * scale;                   // scale is power of 2: exact
    uint32_t h = f2tf32(v);
    Wh3[(long long)d * D3 + colOff + e] = h;
    Wl3[(long long)d * D3 + colOff + e] = f2tf32(v - __uint_as_float(h));
}
__global__ void __launch_bounds__(256) splitw_kernel(
    const float* __restrict__ W, uint32_t* __restrict__ Wh,
    uint32_t* __restrict__ Wl)
{
    int i = blockIdx.x * 256 + threadIdx.x;
    float v = W[i];
    uint32_t h = f2tf32(v);
    Wh[i] = h;
    Wl[i] = f2tf32(v - __uint_as_float(h));
}
// fused 3-way bias concat (one launch instead of three)
__global__ void __launch_bounds__(256) biascat3_kernel(
    const float* __restrict__ bq, const float* __restrict__ bk,
    const float* __restrict__ bv, float* __restrict__ dst)
{
    int i = blockIdx.x * 256 + threadIdx.x;   // over D
    dst[i]         = bq[i] * 0.125f;
    dst[i + D]     = bk[i];
    dst[i + 2 * D] = bv[i];
}

// ---------------- LayerNorm (fp32 out) ----------------
__global__ void __launch_bounds__(256) ln_kernel(const float* __restrict__ x,
                                                 const float* __restrict__ gam,
                                                 const float* __restrict__ bet,
                                                 float* __restrict__ y) {
    int n = blockIdx.x;
    const float* row = x + (long)n * D;
    int t = threadIdx.x;
    float s = 0.f, s2 = 0.f;
    for (int d = t; d < D; d += 256) { float v = row[d]; s += v; s2 += v * v; }
    __shared__ float r1[256], r2[256];
    r1[t] = s; r2[t] = s2; __syncthreads();
    for (int st = 128; st > 0; st >>= 1) {
        if (t < st) { r1[t] += r1[t + st]; r2[t] += r2[t + st]; }
        __syncthreads();
    }
    float mean = r1[0] / D;
    float var  = r2[0] / D - mean * mean;
    float inv  = rsqrtf(var + 1e-5f);
    float* yo = y + (long)n * D;
    for (int d = t; d < D; d += 256)
        yo[d] = (row[d] - mean) * inv * gam[d] + bet[d];
}

// ---------------- LayerNorm (tf32 hi/lo out) ----------------
__global__ void __launch_bounds__(256) ln_split_kernel(
    const float* __restrict__ x, const float* __restrict__ gam,
    const float* __restrict__ bet,
    uint32_t* __restrict__ yh, uint32_t* __restrict__ yl)
{
    int n = blockIdx.x;
    const float* row = x + (long)n * D;
    int t = threadIdx.x;
    float s = 0.f, s2 = 0.f;
    for (int d = t; d < D; d += 256) { float v = row[d]; s += v; s2 += v * v; }
    __shared__ float r1[256], r2[256];
    r1[t] = s; r2[t] = s2; __syncthreads();
    for (int st = 128; st > 0; st >>= 1) {
        if (t < st) { r1[t] += r1[t + st]; r2[t] += r2[t + st]; }
        __syncthreads();
    }
    float mean = r1[0] / D;
    float var  = r2[0] / D - mean * mean;
    float inv  = rsqrtf(var + 1e-5f);
    for (int d = t; d < D; d += 256) {
        float v = (row[d] - mean) * inv * gam[d] + bet[d];
        uint32_t h = f2tf32(v);
        yh[(long)n * D + d] = h;
        yl[(long)n * D + d] = f2tf32(v - __uint_as_float(h));
    }
}

// ---------------- 3xTF32 GEMM, pre-split, single-buffer, occ=2 --------------
// C[M,Nc] = (Ah+Al)@(Bh+Bl) + bias (+ resid). Block 128x128, warp 64x32.
template<int HAS_RESID>
__global__ void __launch_bounds__(256, 2) gemm_t3s_kernel(
    const uint32_t* __restrict__ Ah, const uint32_t* __restrict__ Al,
    const uint32_t* __restrict__ Bh, const uint32_t* __restrict__ Bl,
    const float* __restrict__ bias, const float* __restrict__ resid,
    float* __restrict__ C, int M, int Nc, int K)
{
    __shared__ uint32_t As_h[16][136], As_l[16][136];
    __shared__ uint32_t Bs_h[16][136], Bs_l[16][136];

    int t    = threadIdx.x;
    int wid  = t >> 5, lane = t & 31;
    int gid  = lane >> 2, tig = lane & 3;
    int wm0  = (wid & 1) * 64;
    int wn0  = (wid >> 1) * 32;
    int m0   = blockIdx.y * 128, n0 = blockIdx.x * 128;

    float acc[4][4][4];
#pragma unroll
    for (int mt = 0; mt < 4; mt++)
#pragma unroll
        for (int nt = 0; nt < 4; nt++)
#pragma unroll
            for (int r = 0; r < 4; r++) acc[mt][nt][r] = 0.f;

    for (int k0 = 0; k0 < K; k0 += 16) {
#pragma unroll
        for (int l = 0; l < 2; l++) {
            int f  = t + l * 256;
            int r  = f >> 2;
            int c4 = (f & 3) * 4;
            uint4 vh = *(const uint4*)(Ah + (long long)(m0 + r) * K + k0 + c4);
            uint4 vl = *(const uint4*)(Al + (long long)(m0 + r) * K + k0 + c4);
            As_h[c4 + 0][r] = vh.x; As_h[c4 + 1][r] = vh.y;
            As_h[c4 + 2][r] = vh.z; As_h[c4 + 3][r] = vh.w;
            As_l[c4 + 0][r] = vl.x; As_l[c4 + 1][r] = vl.y;
            As_l[c4 + 2][r] = vl.z; As_l[c4 + 3][r] = vl.w;
        }
#pragma unroll
        for (int l = 0; l < 2; l++) {
            int f  = t + l * 256;
            int r  = f >> 5;
            int c4 = (f & 31) * 4;
            *(uint4*)(&Bs_h[r][c4]) =
                *(const uint4*)(Bh + (long long)(k0 + r) * Nc + n0 + c4);
            *(uint4*)(&Bs_l[r][c4]) =
                *(const uint4*)(Bl + (long long)(k0 + r) * Nc + n0 + c4);
        }
        __syncthreads();

#pragma unroll
        for (int kb = 0; kb < 16; kb += 8) {
            uint32_t fah[4][4], fal[4][4], fbh[4][2], fbl[4][2];
#pragma unroll
            for (int mt = 0; mt < 4; mt++) {
                int mm = wm0 + mt * 16 + gid;
                fah[mt][0] = As_h[kb + tig    ][mm];
                fah[mt][1] = As_h[kb + tig    ][mm + 8];
                fah[mt][2] = As_h[kb + tig + 4][mm];
                fah[mt][3] = As_h[kb + tig + 4][mm + 8];
                fal[mt][0] = As_l[kb + tig    ][mm];
                fal[mt][1] = As_l[kb + tig    ][mm + 8];
                fal[mt][2] = As_l[kb + tig + 4][mm];
                fal[mt][3] = As_l[kb + tig + 4][mm + 8];
            }
#pragma unroll
            for (int nt = 0; nt < 4; nt++) {
                int nn = wn0 + nt * 8 + gid;
                fbh[nt][0] = Bs_h[kb + tig    ][nn];
                fbh[nt][1] = Bs_h[kb + tig + 4][nn];
                fbl[nt][0] = Bs_l[kb + tig    ][nn];
                fbl[nt][1] = Bs_l[kb + tig + 4][nn];
            }
#pragma unroll
            for (int mt = 0; mt < 4; mt++)
#pragma unroll
                for (int nt = 0; nt < 4; nt++) {
                    asm volatile(
                        "mma.sync.aligned.m16n8k8.row.col.f32.tf32.tf32.f32 "
                        "{%0,%1,%2,%3}, {%4,%5,%6,%7}, {%8,%9}, {%0,%1,%2,%3};"
                        : "+f"(acc[mt][nt][0]), "+f"(acc[mt][nt][1]),
                          "+f"(acc[mt][nt][2]), "+f"(acc[mt][nt][3])
                        : "r"(fah[mt][0]), "r"(fah[mt][1]), "r"(fah[mt][2]), "r"(fah[mt][3]),
                          "r"(fbl[nt][0]), "r"(fbl[nt][1]));
                    asm volatile(
                        "mma.sync.aligned.m16n8k8.row.col.f32.tf32.tf32.f32 "
                        "{%0,%1,%2,%3}, {%4,%5,%6,%7}, {%8,%9}, {%0,%1,%2,%3};"
                        : "+f"(acc[mt][nt][0]), "+f"(acc[mt][nt][1]),
                          "+f"(acc[mt][nt][2]), "+f"(acc[mt][nt][3])
                        : "r"(fal[mt][0]), "r"(fal[mt][1]), "r"(fal[mt][2]), "r"(fal[mt][3]),
                          "r"(fbh[nt][0]), "r"(fbh[nt][1]));
                    asm volatile(
                        "mma.sync.aligned.m16n8k8.row.col.f32.tf32.tf32.f32 "
                        "{%0,%1,%2,%3}, {%4,%5,%6,%7}, {%8,%9}, {%0,%1,%2,%3};"
                        : "+f"(acc[mt][nt][0]), "+f"(acc[mt][nt][1]),
                          "+f"(acc[mt][nt][2]), "+f"(acc[mt][nt][3])
                        : "r"(fah[mt][0]), "r"(fah[mt][1]), "r"(fah[mt][2]), "r"(fah[mt][3]),
                          "r"(fbh[nt][0]), "r"(fbh[nt][1]));
                }
        }
        __syncthreads();
    }

#pragma unroll
    for (int mt = 0; mt < 4; mt++) {
#pragma unroll
        for (int nt = 0; nt < 4; nt++) {
            int row = m0 + wm0 + mt * 16 + gid;
            int col = n0 + wn0 + nt * 8 + 2 * tig;
            float b0 = bias[col], b1 = bias[col + 1];
            float c0 = acc[mt][nt][0] + b0;
            float c1 = acc[mt][nt][1] + b1;
            float c2 = acc[mt][nt][2] + b0;
            float c3 = acc[mt][nt][3] + b1;
            if (HAS_RESID) {
                float2 r0 = *(const float2*)(resid + (long long)row * Nc + col);
                float2 r1 = *(const float2*)(resid + (long long)(row + 8) * Nc + col);
                c0 += r0.x; c1 += r0.y; c2 += r1.x; c3 += r1.y;
            }
            *(float2*)(C + (long long)row * Nc + col)       = make_float2(c0, c1);
            *(float2*)(C + (long long)(row + 8) * Nc + col) = make_float2(c2, c3);
        }
    }
}

// ---------------- weight packing: fp32 [K][Nc] -> bf16 k-pair u32 [K/2][Nc] --
__global__ void __launch_bounds__(256) packw_kernel(
    const float* __restrict__ W, uint32_t* __restrict__ P, int Nc,
    long long sW, long long sP)
{
    int n  = blockIdx.x * 256 + threadIdx.x;
    int k2 = blockIdx.y;
    int z  = blockIdx.z;
    const float* w = W + (long long)z * sW + (long long)(2 * k2) * Nc + n;
    P[(long long)z * sP + (long long)k2 * Nc + n] = packbf2(w[0], w[Nc]);
}

// ---------------- bf16 expert GEMM: block 128x256, warp 64x64, k32 ----------
// C = op(A[M,K](bf16) @ Bp(packed bf16 pairs [K/2][Nc]) + bias)
// Early-exits tiles beyond the expert's actual token count cnt[z]:
// capacity buffer is 4x oversized, ~75% of tiles carry no live rows.
constexpr int EXP_SMEM = 2 * 16 * 136 * 4 + 2 * 16 * 264 * 4;  // 51200 B

template<int RELU, int OUTBF>
__global__ void __launch_bounds__(256) gemm_bf16w_kernel(
    const uint16_t* __restrict__ A, const uint32_t* __restrict__ Bp,
    const float* __restrict__ bias, void* __restrict__ Cout,
    const int* __restrict__ cnt,
    int M, int Nc, int K,
    long long sA, long long sB, long long sBias, long long sC)
{
    int z = blockIdx.z;
    int m0 = blockIdx.y * 128, n0 = blockIdx.x * 256;
    if (m0 >= cnt[z]) return;   // no live rows in this tile: outputs never read

    extern __shared__ uint32_t dyn[];
    uint32_t* As = dyn;                    // [2][16][136]
    uint32_t* Bs = dyn + 2 * 16 * 136;     // [2][16][264]

    A    += (long long)z * sA;
    Bp   += (long long)z * sB;
    bias += (long long)z * sBias;

    int t    = threadIdx.x;
    int wid  = t >> 5, lane = t & 31;
    int gid  = lane >> 2, tig = lane & 3;
    int wm0  = (wid & 1) * 64;
    int wn0  = (wid >> 1) * 64;            // 4 n-warps * 64

    int am  = t & 127, ahh = t >> 7;       // A: row am, octet ahh and ahh+2
    int bk  = t >> 4,  bn  = (t & 15) * 16;

    float acc[4][8][4];
#pragma unroll
    for (int mt = 0; mt < 4; mt++)
#pragma unroll
        for (int nt = 0; nt < 8; nt++)
#pragma unroll
            for (int r = 0; r < 4; r++) acc[mt][nt][r] = 0.f;

    auto stageA = [&](int buf, uint4 va0, uint4 va1) {
        uint32_t* as = As + buf * (16 * 136);
        as[(ahh * 4 + 0) * 136 + am] = va0.x;
        as[(ahh * 4 + 1) * 136 + am] = va0.y;
        as[(ahh * 4 + 2) * 136 + am] = va0.z;
        as[(ahh * 4 + 3) * 136 + am] = va0.w;
        as[((ahh + 2) * 4 + 0) * 136 + am] = va1.x;
        as[((ahh + 2) * 4 + 1) * 136 + am] = va1.y;
        as[((ahh + 2) * 4 + 2) * 136 + am] = va1.z;
        as[((ahh + 2) * 4 + 3) * 136 + am] = va1.w;
    };
    auto stageB = [&](int buf, const uint4* vb) {
        uint32_t* bs = Bs + buf * (16 * 264);
#pragma unroll
        for (int j = 0; j < 4; j++)
            *(uint4*)&bs[bk * 264 + bn + j * 4] = vb[j];
    };

    const int nIter = K / 32;
    {   // stage tile 0
        uint4 va0 = *(const uint4*)(A + (long long)(m0 + am) * K + ahh * 8);
        uint4 va1 = *(const uint4*)(A + (long long)(m0 + am) * K + (ahh + 2) * 8);
        uint4 vb[4];
#pragma unroll
        for (int j = 0; j < 4; j++)
            vb[j] = *(const uint4*)(Bp + (long long)bk * Nc + n0 + bn + j * 4);
        stageA(0, va0, va1);
        stageB(0, vb);
    }
    __syncthreads();

    for (int it = 0; it < nIter; ++it) {
        int cur = it & 1;
        uint4 va0, va1, vb[4];
        bool pf = (it + 1 < nIter);
        if (pf) {
            long long ka = (long long)(m0 + am) * K + (it + 1) * 32;
            va0 = *(const uint4*)(A + ka + ahh * 8);
            va1 = *(const uint4*)(A + ka + (ahh + 2) * 8);
            long long kb = (long long)(it + 1) * 16 + bk;
#pragma unroll
            for (int j = 0; j < 4; j++)
                vb[j] = *(const uint4*)(Bp + kb * Nc + n0 + bn + j * 4);
        }
        const uint32_t* as = As + cur * (16 * 136);
        const uint32_t* bs = Bs + cur * (16 * 264);
#pragma unroll
        for (int kb2 = 0; kb2 < 2; kb2++) {
            int ko = kb2 * 8;
            uint32_t af[4][4], bfr[8][2];
#pragma unroll
            for (int mt = 0; mt < 4; mt++) {
                int mm = wm0 + mt * 16 + gid;
                af[mt][0] = as[(ko + tig    ) * 136 + mm];
                af[mt][1] = as[(ko + tig    ) * 136 + mm + 8];
                af[mt][2] = as[(ko + tig + 4) * 136 + mm];
                af[mt][3] = as[(ko + tig + 4) * 136 + mm + 8];
            }
#pragma unroll
            for (int nt = 0; nt < 8; nt++) {
                int nn = wn0 + nt * 8 + gid;
                bfr[nt][0] = bs[(ko + tig    ) * 264 + nn];
                bfr[nt][1] = bs[(ko + tig + 4) * 264 + nn];
            }
#pragma unroll
            for (int mt = 0; mt < 4; mt++)
#pragma unroll
                for (int nt = 0; nt < 8; nt++) {
                    asm volatile(
                        "mma.sync.aligned.m16n8k16.row.col.f32.bf16.bf16.f32 "
                        "{%0,%1,%2,%3}, {%4,%5,%6,%7}, {%8,%9}, {%0,%1,%2,%3};"
                        : "+f"(acc[mt][nt][0]), "+f"(acc[mt][nt][1]),
                          "+f"(acc[mt][nt][2]), "+f"(acc[mt][nt][3])
                        : "r"(af[mt][0]), "r"(af[mt][1]),
                          "r"(af[mt][2]), "r"(af[mt][3]),
                          "r"(bfr[nt][0]), "r"(bfr[nt][1]));
                }
        }
        if (pf) {
            stageA(cur ^ 1, va0, va1);
            stageB(cur ^ 1, vb);
        }
        __syncthreads();
    }

#pragma unroll
    for (int mt = 0; mt < 4; mt++) {
#pragma unroll
        for (int nt = 0; nt < 8; nt++) {
            int row = m0 + wm0 + mt * 16 + gid;
            int col = n0 + wn0 + nt * 8 + 2 * tig;
            float b0 = bias[col], b1 = bias[col + 1];
            float c0 = acc[mt][nt][0] + b0;
            float c1 = acc[mt][nt][1] + b1;
            float c2 = acc[mt][nt][2] + b0;
            float c3 = acc[mt][nt][3] + b1;
            if (RELU) {
                c0 = fmaxf(c0, 0.f); c1 = fmaxf(c1, 0.f);
                c2 = fmaxf(c2, 0.f); c3 = fmaxf(c3, 0.f);
            }
            if (OUTBF) {
                uint16_t* Cb = (uint16_t*)Cout + (long long)z * sC;
                *(uint32_t*)(Cb + (long long)row * Nc + col)       = packbf2(c0, c1);
                *(uint32_t*)(Cb + (long long)(row + 8) * Nc + col) = packbf2(c2, c3);
            } else {
                float* Cf = (float*)Cout + (long long)z * sC;
                *(float2*)(Cf + (long long)row * Nc + col)       = make_float2(c0, c1);
                *(float2*)(Cf + (long long)(row + 8) * Nc + col) = make_float2(c2, c3);
            }
        }
    }
}

// ---------------- flash attention (fp32, causal; strided qkv input) ---------
constexpr int QT = 128, KT = 64;
constexpr int ATTN_SMEM = (QT * (HD + 1) + 2 * KT * HD) * 4;  // 66048 B

__global__ void __launch_bounds__(128) attn_kernel(
    const float* __restrict__ Q, const float* __restrict__ Kg,
    const float* __restrict__ Vg, int LD,
    uint32_t* __restrict__ Oh, uint32_t* __restrict__ Ol)
{
    extern __shared__ float sm[];
    float* q_s = sm;
    float* k_s = sm + QT * (HD + 1);
    float* v_s = k_s + KT * HD;

    int bh = blockIdx.y;
    int h  = bh % H, b = bh / H;
    int q0 = blockIdx.x * QT;
    int t  = threadIdx.x;
    long base = (long)b * LD + (long)h * HD;
    long rs   = (long)B * LD;    // row stride per s

    for (int f = t; f < QT * HD / 4; f += 128) {
        int r  = f / (HD / 4);
        int c4 = (f % (HD / 4)) * 4;
        float4 v = *(const float4*)(Q + (long)(q0 + r) * rs + base + c4);
        q_s[r * (HD + 1) + c4 + 0] = v.x;
        q_s[r * (HD + 1) + c4 + 1] = v.y;
        q_s[r * (HD + 1) + c4 + 2] = v.z;
        q_s[r * (HD + 1) + c4 + 3] = v.w;
    }
    __syncthreads();

    int sq = q0 + t;
    float m_run = -1e30f, l_run = 0.f;
    float acc[HD];
#pragma unroll
    for (int d = 0; d < HD; d++) acc[d] = 0.f;

    int kend = q0 + QT;
    for (int k0 = 0; k0 < kend; k0 += KT) {
        for (int f = t; f < KT * HD / 4; f += 128) {
            int r  = f / (HD / 4);
            int c4 = (f % (HD / 4)) * 4;
            *(float4*)(&k_s[r * HD + c4]) =
                *(const float4*)(Kg + (long)(k0 + r) * rs + base + c4);
            *(float4*)(&v_s[r * HD + c4]) =
                *(const float4*)(Vg + (long)(k0 + r) * rs + base + c4);
        }
        __syncthreads();

        float s[KT];
#pragma unroll
        for (int j = 0; j < KT; j++) s[j] = 0.f;
        for (int d = 0; d < HD; d++) {
            float qd = q_s[t * (HD + 1) + d];
#pragma unroll
            for (int j = 0; j < KT; j++) s[j] += qd * k_s[j * HD + d];
        }
        float mnew = m_run;
#pragma unroll
        for (int j = 0; j < KT; j++) {
            if (k0 + j > sq) s[j] = -1e9f;
            mnew = fmaxf(mnew, s[j]);
        }
        float corr = __expf(m_run - mnew);
        l_run *= corr;
#pragma unroll
        for (int d = 0; d < HD; d++) acc[d] *= corr;
        for (int j = 0; j < KT; j++) {
            float p = __expf(s[j] - mnew);
            l_run += p;
#pragma unroll
            for (int d = 0; d < HD; d++) acc[d] += p * v_s[j * HD + d];
        }
        m_run = mnew;
        __syncthreads();
    }
    float inv = 1.f / l_run;
    long off = (long)sq * (B * D) + (long)b * D + (long)h * HD;
#pragma unroll
    for (int d = 0; d < HD; d++) {
        float v = acc[d] * inv;
        uint32_t hi = f2tf32(v);
        Oh[off + d] = hi;
        Ol[off + d] = f2tf32(v - __uint_as_float(hi));
    }
}

// ---------------- gate: logits, softmax, argmax (fp32, exact) ----------------
__global__ void __launch_bounds__(256) gate_kernel(
    const float* __restrict__ tok, const float* __restrict__ gw,
    float* __restrict__ gates, int* __restrict__ eidx, float* __restrict__ gp)
{
    int n = blockIdx.x, t = threadIdx.x;
    const float* row = tok + (long)n * D;
    float p[E];
#pragma unroll
    for (int e = 0; e < E; e++) p[e] = 0.f;
    for (int d = t; d < D; d += 256) {
        float xv = row[d];
        const float* w = gw + (long)d * E;
#pragma unroll
        for (int e = 0; e < E; e++) p[e] += xv * w[e];
    }
    __shared__ float red[256 * E];
#pragma unroll
    for (int e = 0; e < E; e++) red[t * E + e] = p[e];
    __syncthreads();
    for (int st = 128; st > 0; st >>= 1) {
        if (t < st)
#pragma unroll
            for (int e = 0; e < E; e++) red[t * E + e] += red[(t + st) * E + e];
        __syncthreads();
    }
    if (t == 0) {
        float lg[E], mx = -1e30f;
#pragma unroll
        for (int e = 0; e < E; e++) { lg[e] = red[e]; mx = fmaxf(mx, lg[e]); }
        float sum = 0.f, pr[E];
#pragma unroll
        for (int e = 0; e < E; e++) { pr[e] = __expf(lg[e] - mx); sum += pr[e]; }
        float inv = 1.f / sum;
        int best = 0; float bv = -1e30f;
#pragma unroll
        for (int e = 0; e < E; e++) {
            float g = pr[e] * inv;
            gates[(long)n * E + e] = g;
            if (g > bv) { bv = g; best = e; }
        }
        eidx[n] = best;
        gp[n]   = bv;
    }
}

// ---------------- routing scan (deterministic, single block) ----------------
__global__ void __launch_bounds__(256) scan_kernel(
    const int* __restrict__ eidx, const float* __restrict__ gp,
    int* __restrict__ slot, float* __restrict__ gv, int* __restrict__ cnt)
{
    __shared__ int scnt[256][E];
    int t = threadIdx.x;
    int c[E];
#pragma unroll
    for (int e = 0; e < E; e++) c[e] = 0;
    int n0 = t * (N / 256);
    for (int i = 0; i < N / 256; i++) c[eidx[n0 + i]]++;
#pragma unroll
    for (int e = 0; e < E; e++) scnt[t][e] = c[e];
    __syncthreads();
    if (t < E) {
        int run = 0;
        for (int j = 0; j < 256; j++) { int tmp = scnt[j][t]; scnt[j][t] = run; run += tmp; }
        cnt[t] = run;
    }
    __syncthreads();
    int off[E];
#pragma unroll
    for (int e = 0; e < E; e++) off[e] = scnt[t][e];
    for (int i = 0; i < N / 256; i++) {
        int n = n0 + i;
        int e = eidx[n];
        int l = off[e]++;
        bool keep = (l < CAP);
        slot[n] = keep ? e * CAP + l : -1;
        gv[n]   = keep ? gp[n] : 0.f;
    }
}

// ---------------- l_aux (deterministic tree reduce) ----------------
__global__ void __launch_bounds__(256) laux_kernel(
    const float* __restrict__ gates, const int* __restrict__ cnt,
    float* __restrict__ out_laux)
{
    __shared__ float red[256];
    int t = threadIdx.x;
    float loc[E];
#pragma unroll
    for (int e = 0; e < E; e++) loc[e] = 0.f;
    for (int n = t; n < N; n += 256)
#pragma unroll
        for (int e = 0; e < E; e++) loc[e] += gates[(long)n * E + e];
    float total[E];
    for (int e = 0; e < E; e++) {
        red[t] = loc[e]; __syncthreads();
        for (int st = 128; st > 0; st >>= 1) {
            if (t < st) red[t] += red[t + st];
            __syncthreads();
        }
        if (t == 0) total[e] = red[0];
        __syncthreads();
    }
    if (t == 0) {
        float la = 0.f;
        for (int e = 0; e < E; e++)
            la += (total[e] / N) * ((float)cnt[e] / N);
        *out_laux = (float)E * la;
    }
}

// ---------------- dispatch / combine ----------------
__global__ void __launch_bounds__(256) dispatch_kernel(
    const float* __restrict__ tok, const int* __restrict__ slot,
    uint16_t* __restrict__ dispb)
{
    int n = blockIdx.x;
    int s = slot[n];
    if (s < 0) return;
    int t = threadIdx.x;
    float4 v = ((const float4*)(tok + (long)n * D))[t];
    uint2 o;
    o.x = packbf2(v.x, v.y);
    o.y = packbf2(v.z, v.w);
    *(uint2*)(dispb + (long)s * D + t * 4) = o;
}

__global__ void __launch_bounds__(256) combine_kernel(
    const float* __restrict__ x1, const float* __restrict__ eo,
    const int* __restrict__ slot, const float* __restrict__ gv,
    float* __restrict__ out)
{
    int n = blockIdx.x, t = threadIdx.x;
    int s = slot[n];
    float g = gv[n];
    float4 r = ((const float4*)(x1 + (long)n * D))[t];
    if (s >= 0) {
        float4 v = ((const float4*)(eo + (long)s * D))[t];
        r.x += v.x * g; r.y += v.y * g; r.z += v.z * g; r.w += v.w * g;
    }
    ((float4*)(out + (long)n * D))[t] = r;
}

// ---------------- launch ----------------
extern "C" void kernel_launch(void* const* d_in, const int* in_sizes, int n_in,
                              void* d_out, int out_size) {
    const float* x    = (const float*)d_in[0];
    const float* wq   = (const float*)d_in[2];
    const float* bq   = (const float*)d_in[3];
    const float* wk   = (const float*)d_in[4];
    const float* bk   = (const float*)d_in[5];
    const float* wv   = (const float*)d_in[6];
    const float* bv   = (const float*)d_in[7];
    const float* wo   = (const float*)d_in[8];
    const float* bo   = (const float*)d_in[9];
    const float* ln1g = (const float*)d_in[10];
    const float* ln1b = (const float*)d_in[11];
    const float* ln2g = (const float*)d_in[12];
    const float* ln2b = (const float*)d_in[13];
    const float* gw   = (const float*)d_in[14];
    const float* w1   = (const float*)d_in[15];
    const float* b1   = (const float*)d_in[16];
    const float* w2   = (const float*)d_in[17];
    const float* b2   = (const float*)d_in[18];
    float* out = (float*)d_out;

    float *qkv, *x1, *tok, *eo, *gates, *gp, *gv, *b3;
    uint32_t *xnh, *xnl, *aoh, *aol, *wqkvh, *wqkvl, *woh, *wol, *w1p, *w2p;
    uint16_t *dispb, *hb;
    int *eidx, *slot, *cnt;
    cudaGetSymbolAddress((void**)&xnh,   g_xnh);
    cudaGetSymbolAddress((void**)&xnl,   g_xnl);
    cudaGetSymbolAddress((void**)&qkv,   g_qkv);
    cudaGetSymbolAddress((void**)&aoh,   g_aoh);
    cudaGetSymbolAddress((void**)&aol,   g_aol);
    cudaGetSymbolAddress((void**)&x1,    g_x1);
    cudaGetSymbolAddress((void**)&tok,   g_tok);
    cudaGetSymbolAddress((void**)&wqkvh, g_wqkvh);
    cudaGetSymbolAddress((void**)&wqkvl, g_wqkvl);
    cudaGetSymbolAddress((void**)&b3,    g_b3);
    cudaGetSymbolAddress((void**)&woh,   g_woh);
    cudaGetSymbolAddress((void**)&wol,   g_wol);
    cudaGetSymbolAddress((void**)&dispb, g_dispb);
    cudaGetSymbolAddress((void**)&hb,    g_hb);
    cudaGetSymbolAddress((void**)&eo,    g_eo);
    cudaGetSymbolAddress((void**)&w1p,   g_w1p);
    cudaGetSymbolAddress((void**)&w2p,   g_w2p);
    cudaGetSymbolAddress((void**)&gates, g_gates);
    cudaGetSymbolAddress((void**)&gp,    g_gp);
    cudaGetSymbolAddress((void**)&gv,    g_gv);
    cudaGetSymbolAddress((void**)&eidx,  g_eidx);
    cudaGetSymbolAddress((void**)&slot,  g_slot);
    cudaGetSymbolAddress((void**)&cnt,   g_cnt);

    cudaFuncSetAttribute(attn_kernel,
                         cudaFuncAttributeMaxDynamicSharedMemorySize, ATTN_SMEM);
    cudaFuncSetAttribute(gemm_bf16w_kernel<1, 1>,
                         cudaFuncAttributeMaxDynamicSharedMemorySize, EXP_SMEM);
    cudaFuncSetAttribute(gemm_bf16w_kernel<0, 0>,
                         cudaFuncAttributeMaxDynamicSharedMemorySize, EXP_SMEM);

    // one-time prep: merged qkv weight split (q scaled by 1/8 exactly),
    // fused bias concat, wo split, expert weight k-pair packs
    splitw3_kernel<<<D * D / 256, 256>>>(wq, wqkvh, wqkvl, 0,     0.125f);
    splitw3_kernel<<<D * D / 256, 256>>>(wk, wqkvh, wqkvl, D,     1.0f);
    splitw3_kernel<<<D * D / 256, 256>>>(wv, wqkvh, wqkvl, 2 * D, 1.0f);
    biascat3_kernel<<<D / 256, 256>>>(bq, bk, bv, b3);
    splitw_kernel<<<D * D / 256, 256>>>(wo, woh, wol);
    packw_kernel<<<dim3(F / 256, D / 2, E), 256>>>(w1, w1p, F,
        (long long)D * F, (long long)(D / 2) * F);
    packw_kernel<<<dim3(D / 256, F / 2, E), 256>>>(w2, w2p, D,
        (long long)F * D, (long long)(F / 2) * D);

    // 1) LN1 -> tf32 hi/lo
    ln_split_kernel<<<N, 256>>>(x, ln1g, ln1b, xnh, xnl);
    // 2) merged QKV projection (3xTF32, Nc=3072)
    gemm_t3s_kernel<0><<<dim3(D3 / 128, N / 128), 256>>>(
        xnh, xnl, wqkvh, wqkvl, b3, nullptr, qkv, N, D3, D);
    // 3) attention (reads strided qkv)
    attn_kernel<<<dim3(S / QT, B * H), 128, ATTN_SMEM>>>(
        qkv, qkv + D, qkv + 2 * D, D3, aoh, aol);
    // 4) output projection + residual
    gemm_t3s_kernel<1><<<dim3(D / 128, N / 128), 256>>>(
        aoh, aol, woh, wol, bo, x, x1, N, D, D);
    // 5) LN2
    ln_kernel<<<N, 256>>>(x1, ln2g, ln2b, tok);
    // 6) gate
    gate_kernel<<<N, 256>>>(tok, gw, gates, eidx, gp);
    // 7) routing scan
    scan_kernel<<<1, 256>>>(eidx, gp, slot, gv, cnt);
    // 8) l_aux -> last output element
    laux_kernel<<<1, 256>>>(gates, cnt, out + (out_size - 1));
    // 9) dispatch (writes bf16)
    dispatch_kernel<<<N, 256>>>(tok, slot, dispb);
    // 10) expert GEMM1 (relu, bf16 -> bf16) — only live tiles compute
    gemm_bf16w_kernel<1, 1><<<dim3(F / 256, CAP / 128, E), 256, EXP_SMEM>>>(
        dispb, w1p, b1, hb, cnt, CAP, F, D,
        (long long)CAP * D, (long long)(D / 2) * F, (long long)F, (long long)CAP * F);
    // 11) expert GEMM2 (bf16 -> fp32) — only live tiles compute
    gemm_bf16w_kernel<0, 0><<<dim3(D / 256, CAP / 128, E), 256, EXP_SMEM>>>(
        hb, w2p, b2, eo, cnt, CAP, D, F,
        (long long)CAP * F, (long long)(F / 2) * D, (long long)D, (long long)CAP * D);
    // 12) combine + residual -> output
    combine_kernel<<<N, 256>>>(x1, eo, slot, gv, out);
}

// round 13
// speedup vs baseline: 1.9231x; 1.2598x over previous
#include <cuda_runtime.h>
#include <cstdint>

// ---------------- problem constants ----------------
constexpr int S = 1024, B = 8, D = 1024, H = 16, F = 4096, E = 8;
constexpr int HD = D / H;           // 64
constexpr int N = S * B;            // 8192
constexpr int CAP = 4 * N / E;      // 4096
constexpr int D3 = 3 * D;           // 3072 (merged qkv width)
constexpr int Dp = D / 2;           // pair count per row

// ---------------- scratch (device globals; no allocations) ----------------
__device__ uint32_t g_xnh[N * Dp], g_xnl[N * Dp];    // LN1 out, bf16-pair hi/lo
__device__ float    g_qkv[N * D3];                   // merged q|k|v
__device__ uint32_t g_aoh[N * Dp], g_aol[N * Dp];    // attn out, bf16-pair hi/lo
__device__ float g_x1 [N * D];
__device__ float g_tok[N * D];
__device__ uint32_t g_wqkvh[Dp * D3], g_wqkvl[Dp * D3];  // bf16 k-pair hi/lo
__device__ float    g_b3[D3];
__device__ uint32_t g_woh[Dp * D], g_wol[Dp * D];
__device__ uint16_t g_dispb[E * CAP * D];            // bf16 dispatched tokens
__device__ uint16_t g_hb  [134217728];               // E*CAP*F bf16 hidden
__device__ float    g_eo  [E * CAP * D];
__device__ uint32_t g_w1p [(D / 2) * F * E];         // bf16 k-pair packed w1
__device__ uint32_t g_w2p [(F / 2) * D * E];         // bf16 k-pair packed w2
__device__ float g_gates[N * E];
__device__ int   g_eidx[N];
__device__ float g_gp  [N];
__device__ int   g_slot[N];
__device__ float g_gv  [N];
__device__ int   g_cnt [E];

// ---------------- helpers ----------------
__device__ __forceinline__ uint32_t packbf2(float lo, float hi) {
    uint32_t d;
    asm("cvt.rn.bf16x2.f32 %0, %1, %2;" : "=r"(d) : "f"(hi), "f"(lo));
    return d;
}
__device__ __forceinline__ uint16_t f2bf(float f) {
    uint16_t u;
    asm("cvt.rn.bf16.f32 %0, %1;" : "=h"(u) : "f"(f));
    return u;
}
__device__ __forceinline__ float bf2f(uint16_t h) {
    return __uint_as_float((uint32_t)h << 16);
}
// split v into bf16 hi + bf16 lo
__device__ __forceinline__ void bfsplit(float v, uint16_t& h, uint16_t& l) {
    h = f2bf(v);
    l = f2bf(v - bf2f(h));
}

// ---------------- weight split: fp32 [K][NcSrc] -> bf16-pair hi/lo ----------
// Ph/Pl: [K/2][NcDst] u32, pair = (k=2k2, k=2k2+1). scale is exact pow2.
__global__ void __launch_bounds__(256) splitwp_kernel(
    const float* __restrict__ W, uint32_t* __restrict__ Ph,
    uint32_t* __restrict__ Pl, int NcSrc, int NcDst, int colOff, float scale)
{
    int n  = blockIdx.x * 256 + threadIdx.x;
    int k2 = blockIdx.y;
    float v0 = W[(long long)(2 * k2)     * NcSrc + n] * scale;
    float v1 = W[(long long)(2 * k2 + 1) * NcSrc + n] * scale;
    uint16_t h0, l0, h1, l1;
    bfsplit(v0, h0, l0);
    bfsplit(v1, h1, l1);
    long long o = (long long)k2 * NcDst + colOff + n;
    Ph[o] = ((uint32_t)h1 << 16) | h0;
    Pl[o] = ((uint32_t)l1 << 16) | l0;
}
// fused 3-way bias concat
__global__ void __launch_bounds__(256) biascat3_kernel(
    const float* __restrict__ bq, const float* __restrict__ bk,
    const float* __restrict__ bv, float* __restrict__ dst)
{
    int i = blockIdx.x * 256 + threadIdx.x;
    dst[i]         = bq[i] * 0.125f;
    dst[i + D]     = bk[i];
    dst[i + 2 * D] = bv[i];
}

// ---------------- LayerNorm (fp32 out) ----------------
__global__ void __launch_bounds__(256) ln_kernel(const float* __restrict__ x,
                                                 const float* __restrict__ gam,
                                                 const float* __restrict__ bet,
                                                 float* __restrict__ y) {
    int n = blockIdx.x;
    const float* row = x + (long)n * D;
    int t = threadIdx.x;
    float s = 0.f, s2 = 0.f;
    for (int d = t; d < D; d += 256) { float v = row[d]; s += v; s2 += v * v; }
    __shared__ float r1[256], r2[256];
    r1[t] = s; r2[t] = s2; __syncthreads();
    for (int st = 128; st > 0; st >>= 1) {
        if (t < st) { r1[t] += r1[t + st]; r2[t] += r2[t + st]; }
        __syncthreads();
    }
    float mean = r1[0] / D;
    float var  = r2[0] / D - mean * mean;
    float inv  = rsqrtf(var + 1e-5f);
    float* yo = y + (long)n * D;
    for (int d = t; d < D; d += 256)
        yo[d] = (row[d] - mean) * inv * gam[d] + bet[d];
}

// ---------------- LayerNorm (bf16-pair hi/lo out) ----------------
__global__ void __launch_bounds__(256) ln_splitp_kernel(
    const float* __restrict__ x, const float* __restrict__ gam,
    const float* __restrict__ bet,
    uint32_t* __restrict__ yh, uint32_t* __restrict__ yl)
{
    int n = blockIdx.x;
    const float* row = x + (long)n * D;
    int t = threadIdx.x;
    float s = 0.f, s2 = 0.f;
    for (int d = t; d < D; d += 256) { float v = row[d]; s += v; s2 += v * v; }
    __shared__ float r1[256], r2[256];
    r1[t] = s; r2[t] = s2; __syncthreads();
    for (int st = 128; st > 0; st >>= 1) {
        if (t < st) { r1[t] += r1[t + st]; r2[t] += r2[t + st]; }
        __syncthreads();
    }
    float mean = r1[0] / D;
    float var  = r2[0] / D - mean * mean;
    float inv  = rsqrtf(var + 1e-5f);
    // thread t handles elements 4t..4t+3 -> pairs 2t, 2t+1
    float4 v4 = *(const float4*)(row + 4 * t);
    float4 g4 = *(const float4*)(gam + 4 * t);
    float4 b4 = *(const float4*)(bet + 4 * t);
    float v0 = (v4.x - mean) * inv * g4.x + b4.x;
    float v1 = (v4.y - mean) * inv * g4.y + b4.y;
    float v2 = (v4.z - mean) * inv * g4.z + b4.z;
    float v3 = (v4.w - mean) * inv * g4.w + b4.w;
    uint16_t h0, l0, h1, l1, h2, l2, h3, l3;
    bfsplit(v0, h0, l0); bfsplit(v1, h1, l1);
    bfsplit(v2, h2, l2); bfsplit(v3, h3, l3);
    long long o = (long long)n * Dp + 2 * t;
    yh[o]     = ((uint32_t)h1 << 16) | h0;
    yh[o + 1] = ((uint32_t)h3 << 16) | h2;
    yl[o]     = ((uint32_t)l1 << 16) | l0;
    yl[o + 1] = ((uint32_t)l3 << 16) | l2;
}

// ---------------- bf16x3 GEMM (projections) ----------------------------------
// C[M,Nc] = (Ah+Al)@(Bh+Bl) + bias (+ resid). A,B bf16-pair-packed hi/lo.
// Block 128x128, warp 64x32, k16 chunks, single-buffer, occ=2.
template<int HAS_RESID>
__global__ void __launch_bounds__(256, 2) gemm_b3_kernel(
    const uint32_t* __restrict__ Aph, const uint32_t* __restrict__ Apl,
    const uint32_t* __restrict__ Bph, const uint32_t* __restrict__ Bpl,
    const float* __restrict__ bias, const float* __restrict__ resid,
    float* __restrict__ C, int M, int Nc, int K)
{
    __shared__ uint32_t Ash[8][136], Asl[8][136];   // pair-rows x m
    __shared__ uint32_t Bsh[8][136], Bsl[8][136];   // pair-rows x n

    int t    = threadIdx.x;
    int wid  = t >> 5, lane = t & 31;
    int gid  = lane >> 2, tig = lane & 3;
    int wm0  = (wid & 1) * 64;
    int wn0  = (wid >> 1) * 32;
    int m0   = blockIdx.y * 128, n0 = blockIdx.x * 128;
    int Kp   = K >> 1;

    // staging coords
    int arow = t >> 1, apg = (t & 1) * 4;       // A: one uint4 = 4 pairs
    int brow = t >> 5, bcol = (t & 31) * 4;     // B: one uint4 = 4 cols

    float acc[4][4][4];
#pragma unroll
    for (int mt = 0; mt < 4; mt++)
#pragma unroll
        for (int nt = 0; nt < 4; nt++)
#pragma unroll
            for (int r = 0; r < 4; r++) acc[mt][nt][r] = 0.f;

    for (int kp0 = 0; kp0 < Kp; kp0 += 8) {     // 16 k-values per chunk
        {
            uint4 vh = *(const uint4*)(Aph + (long long)(m0 + arow) * Kp + kp0 + apg);
            uint4 vl = *(const uint4*)(Apl + (long long)(m0 + arow) * Kp + kp0 + apg);
            Ash[apg + 0][arow] = vh.x; Ash[apg + 1][arow] = vh.y;
            Ash[apg + 2][arow] = vh.z; Ash[apg + 3][arow] = vh.w;
            Asl[apg + 0][arow] = vl.x; Asl[apg + 1][arow] = vl.y;
            Asl[apg + 2][arow] = vl.z; Asl[apg + 3][arow] = vl.w;
        }
        {
            *(uint4*)&Bsh[brow][bcol] =
                *(const uint4*)(Bph + (long long)(kp0 + brow) * Nc + n0 + bcol);
            *(uint4*)&Bsl[brow][bcol] =
                *(const uint4*)(Bpl + (long long)(kp0 + brow) * Nc + n0 + bcol);
        }
        __syncthreads();

        uint32_t fah[4][4], fal[4][4], fbh[4][2], fbl[4][2];
#pragma unroll
        for (int mt = 0; mt < 4; mt++) {
            int mm = wm0 + mt * 16 + gid;
            fah[mt][0] = Ash[tig    ][mm];
            fah[mt][1] = Ash[tig    ][mm + 8];
            fah[mt][2] = Ash[tig + 4][mm];
            fah[mt][3] = Ash[tig + 4][mm + 8];
            fal[mt][0] = Asl[tig    ][mm];
            fal[mt][1] = Asl[tig    ][mm + 8];
            fal[mt][2] = Asl[tig + 4][mm];
            fal[mt][3] = Asl[tig + 4][mm + 8];
        }
#pragma unroll
        for (int nt = 0; nt < 4; nt++) {
            int nn = wn0 + nt * 8 + gid;
            fbh[nt][0] = Bsh[tig    ][nn];
            fbh[nt][1] = Bsh[tig + 4][nn];
            fbl[nt][0] = Bsl[tig    ][nn];
            fbl[nt][1] = Bsl[tig + 4][nn];
        }
#pragma unroll
        for (int mt = 0; mt < 4; mt++)
#pragma unroll
            for (int nt = 0; nt < 4; nt++) {
                asm volatile(
                    "mma.sync.aligned.m16n8k16.row.col.f32.bf16.bf16.f32 "
                    "{%0,%1,%2,%3}, {%4,%5,%6,%7}, {%8,%9}, {%0,%1,%2,%3};"
                    : "+f"(acc[mt][nt][0]), "+f"(acc[mt][nt][1]),
                      "+f"(acc[mt][nt][2]), "+f"(acc[mt][nt][3])
                    : "r"(fah[mt][0]), "r"(fah[mt][1]), "r"(fah[mt][2]), "r"(fah[mt][3]),
                      "r"(fbl[nt][0]), "r"(fbl[nt][1]));
                asm volatile(
                    "mma.sync.aligned.m16n8k16.row.col.f32.bf16.bf16.f32 "
                    "{%0,%1,%2,%3}, {%4,%5,%6,%7}, {%8,%9}, {%0,%1,%2,%3};"
                    : "+f"(acc[mt][nt][0]), "+f"(acc[mt][nt][1]),
                      "+f"(acc[mt][nt][2]), "+f"(acc[mt][nt][3])
                    : "r"(fal[mt][0]), "r"(fal[mt][1]), "r"(fal[mt][2]), "r"(fal[mt][3]),
                      "r"(fbh[nt][0]), "r"(fbh[nt][1]));
                asm volatile(
                    "mma.sync.aligned.m16n8k16.row.col.f32.bf16.bf16.f32 "
                    "{%0,%1,%2,%3}, {%4,%5,%6,%7}, {%8,%9}, {%0,%1,%2,%3};"
                    : "+f"(acc[mt][nt][0]), "+f"(acc[mt][nt][1]),
                      "+f"(acc[mt][nt][2]), "+f"(acc[mt][nt][3])
                    : "r"(fah[mt][0]), "r"(fah[mt][1]), "r"(fah[mt][2]), "r"(fah[mt][3]),
                      "r"(fbh[nt][0]), "r"(fbh[nt][1]));
            }
        __syncthreads();
    }

#pragma unroll
    for (int mt = 0; mt < 4; mt++) {
#pragma unroll
        for (int nt = 0; nt < 4; nt++) {
            int row = m0 + wm0 + mt * 16 + gid;
            int col = n0 + wn0 + nt * 8 + 2 * tig;
            float b0 = bias[col], b1 = bias[col + 1];
            float c0 = acc[mt][nt][0] + b0;
            float c1 = acc[mt][nt][1] + b1;
            float c2 = acc[mt][nt][2] + b0;
            float c3 = acc[mt][nt][3] + b1;
            if (HAS_RESID) {
                float2 r0 = *(const float2*)(resid + (long long)row * Nc + col);
                float2 r1 = *(const float2*)(resid + (long long)(row + 8) * Nc + col);
                c0 += r0.x; c1 += r0.y; c2 += r1.x; c3 += r1.y;
            }
            *(float2*)(C + (long long)row * Nc + col)       = make_float2(c0, c1);
            *(float2*)(C + (long long)(row + 8) * Nc + col) = make_float2(c2, c3);
        }
    }
}

// ---------------- weight packing: fp32 [K][Nc] -> bf16 k-pair u32 [K/2][Nc] --
__global__ void __launch_bounds__(256) packw_kernel(
    const float* __restrict__ W, uint32_t* __restrict__ P, int Nc,
    long long sW, long long sP)
{
    int n  = blockIdx.x * 256 + threadIdx.x;
    int k2 = blockIdx.y;
    int z  = blockIdx.z;
    const float* w = W + (long long)z * sW + (long long)(2 * k2) * Nc + n;
    P[(long long)z * sP + (long long)k2 * Nc + n] = packbf2(w[0], w[Nc]);
}

// ---------------- bf16 expert GEMM: block 128x256, warp 64x64, k32 ----------
constexpr int EXP_SMEM = 2 * 16 * 136 * 4 + 2 * 16 * 264 * 4;  // 51200 B

template<int RELU, int OUTBF>
__global__ void __launch_bounds__(256) gemm_bf16w_kernel(
    const uint16_t* __restrict__ A, const uint32_t* __restrict__ Bp,
    const float* __restrict__ bias, void* __restrict__ Cout,
    const int* __restrict__ cnt,
    int M, int Nc, int K,
    long long sA, long long sB, long long sBias, long long sC)
{
    int z = blockIdx.z;
    int m0 = blockIdx.y * 128, n0 = blockIdx.x * 256;
    if (m0 >= cnt[z]) return;   // no live rows in this tile: outputs never read

    extern __shared__ uint32_t dyn[];
    uint32_t* As = dyn;                    // [2][16][136]
    uint32_t* Bs = dyn + 2 * 16 * 136;     // [2][16][264]

    A    += (long long)z * sA;
    Bp   += (long long)z * sB;
    bias += (long long)z * sBias;

    int t    = threadIdx.x;
    int wid  = t >> 5, lane = t & 31;
    int gid  = lane >> 2, tig = lane & 3;
    int wm0  = (wid & 1) * 64;
    int wn0  = (wid >> 1) * 64;

    int am  = t & 127, ahh = t >> 7;
    int bk  = t >> 4,  bn  = (t & 15) * 16;

    float acc[4][8][4];
#pragma unroll
    for (int mt = 0; mt < 4; mt++)
#pragma unroll
        for (int nt = 0; nt < 8; nt++)
#pragma unroll
            for (int r = 0; r < 4; r++) acc[mt][nt][r] = 0.f;

    auto stageA = [&](int buf, uint4 va0, uint4 va1) {
        uint32_t* as = As + buf * (16 * 136);
        as[(ahh * 4 + 0) * 136 + am] = va0.x;
        as[(ahh * 4 + 1) * 136 + am] = va0.y;
        as[(ahh * 4 + 2) * 136 + am] = va0.z;
        as[(ahh * 4 + 3) * 136 + am] = va0.w;
        as[((ahh + 2) * 4 + 0) * 136 + am] = va1.x;
        as[((ahh + 2) * 4 + 1) * 136 + am] = va1.y;
        as[((ahh + 2) * 4 + 2) * 136 + am] = va1.z;
        as[((ahh + 2) * 4 + 3) * 136 + am] = va1.w;
    };
    auto stageB = [&](int buf, const uint4* vb) {
        uint32_t* bs = Bs + buf * (16 * 264);
#pragma unroll
        for (int j = 0; j < 4; j++)
            *(uint4*)&bs[bk * 264 + bn + j * 4] = vb[j];
    };

    const int nIter = K / 32;
    {
        uint4 va0 = *(const uint4*)(A + (long long)(m0 + am) * K + ahh * 8);
        uint4 va1 = *(const uint4*)(A + (long long)(m0 + am) * K + (ahh + 2) * 8);
        uint4 vb[4];
#pragma unroll
        for (int j = 0; j < 4; j++)
            vb[j] = *(const uint4*)(Bp + (long long)bk * Nc + n0 + bn + j * 4);
        stageA(0, va0, va1);
        stageB(0, vb);
    }
    __syncthreads();

    for (int it = 0; it < nIter; ++it) {
        int cur = it & 1;
        uint4 va0, va1, vb[4];
        bool pf = (it + 1 < nIter);
        if (pf) {
            long long ka = (long long)(m0 + am) * K + (it + 1) * 32;
            va0 = *(const uint4*)(A + ka + ahh * 8);
            va1 = *(const uint4*)(A + ka + (ahh + 2) * 8);
            long long kb = (long long)(it + 1) * 16 + bk;
#pragma unroll
            for (int j = 0; j < 4; j++)
                vb[j] = *(const uint4*)(Bp + kb * Nc + n0 + bn + j * 4);
        }
        const uint32_t* as = As + cur * (16 * 136);
        const uint32_t* bs = Bs + cur * (16 * 264);
#pragma unroll
        for (int kb2 = 0; kb2 < 2; kb2++) {
            int ko = kb2 * 8;
            uint32_t af[4][4], bfr[8][2];
#pragma unroll
            for (int mt = 0; mt < 4; mt++) {
                int mm = wm0 + mt * 16 + gid;
                af[mt][0] = as[(ko + tig    ) * 136 + mm];
                af[mt][1] = as[(ko + tig    ) * 136 + mm + 8];
                af[mt][2] = as[(ko + tig + 4) * 136 + mm];
                af[mt][3] = as[(ko + tig + 4) * 136 + mm + 8];
            }
#pragma unroll
            for (int nt = 0; nt < 8; nt++) {
                int nn = wn0 + nt * 8 + gid;
                bfr[nt][0] = bs[(ko + tig    ) * 264 + nn];
                bfr[nt][1] = bs[(ko + tig + 4) * 264 + nn];
            }
#pragma unroll
            for (int mt = 0; mt < 4; mt++)
#pragma unroll
                for (int nt = 0; nt < 8; nt++) {
                    asm volatile(
                        "mma.sync.aligned.m16n8k16.row.col.f32.bf16.bf16.f32 "
                        "{%0,%1,%2,%3}, {%4,%5,%6,%7}, {%8,%9}, {%0,%1,%2,%3};"
                        : "+f"(acc[mt][nt][0]), "+f"(acc[mt][nt][1]),
                          "+f"(acc[mt][nt][2]), "+f"(acc[mt][nt][3])
                        : "r"(af[mt][0]), "r"(af[mt][1]),
                          "r"(af[mt][2]), "r"(af[mt][3]),
                          "r"(bfr[nt][0]), "r"(bfr[nt][1]));
                }
        }
        if (pf) {
            stageA(cur ^ 1, va0, va1);
            stageB(cur ^ 1, vb);
        }
        __syncthreads();
    }

#pragma unroll
    for (int mt = 0; mt < 4; mt++) {
#pragma unroll
        for (int nt = 0; nt < 8; nt++) {
            int row = m0 + wm0 + mt * 16 + gid;
            int col = n0 + wn0 + nt * 8 + 2 * tig;
            float b0 = bias[col], b1 = bias[col + 1];
            float c0 = acc[mt][nt][0] + b0;
            float c1 = acc[mt][nt][1] + b1;
            float c2 = acc[mt][nt][2] + b0;
            float c3 = acc[mt][nt][3] + b1;
            if (RELU) {
                c0 = fmaxf(c0, 0.f); c1 = fmaxf(c1, 0.f);
                c2 = fmaxf(c2, 0.f); c3 = fmaxf(c3, 0.f);
            }
            if (OUTBF) {
                uint16_t* Cb = (uint16_t*)Cout + (long long)z * sC;
                *(uint32_t*)(Cb + (long long)row * Nc + col)       = packbf2(c0, c1);
                *(uint32_t*)(Cb + (long long)(row + 8) * Nc + col) = packbf2(c2, c3);
            } else {
                float* Cf = (float*)Cout + (long long)z * sC;
                *(float2*)(Cf + (long long)row * Nc + col)       = make_float2(c0, c1);
                *(float2*)(Cf + (long long)(row + 8) * Nc + col) = make_float2(c2, c3);
            }
        }
    }
}

// ---------------- flash attention (fp32; emits bf16-pair hi/lo) -------------
constexpr int QT = 128, KT = 64;
constexpr int ATTN_SMEM = (QT * (HD + 1) + 2 * KT * HD) * 4;  // 66048 B

__global__ void __launch_bounds__(128) attn_kernel(
    const float* __restrict__ Q, const float* __restrict__ Kg,
    const float* __restrict__ Vg, int LD,
    uint32_t* __restrict__ Ohp, uint32_t* __restrict__ Olp)
{
    extern __shared__ float sm[];
    float* q_s = sm;
    float* k_s = sm + QT * (HD + 1);
    float* v_s = k_s + KT * HD;

    int bh = blockIdx.y;
    int h  = bh % H, b = bh / H;
    int q0 = blockIdx.x * QT;
    int t  = threadIdx.x;
    long base = (long)b * LD + (long)h * HD;
    long rs   = (long)B * LD;

    for (int f = t; f < QT * HD / 4; f += 128) {
        int r  = f / (HD / 4);
        int c4 = (f % (HD / 4)) * 4;
        float4 v = *(const float4*)(Q + (long)(q0 + r) * rs + base + c4);
        q_s[r * (HD + 1) + c4 + 0] = v.x;
        q_s[r * (HD + 1) + c4 + 1] = v.y;
        q_s[r * (HD + 1) + c4 + 2] = v.z;
        q_s[r * (HD + 1) + c4 + 3] = v.w;
    }
    __syncthreads();

    int sq = q0 + t;
    float m_run = -1e30f, l_run = 0.f;
    float acc[HD];
#pragma unroll
    for (int d = 0; d < HD; d++) acc[d] = 0.f;

    int kend = q0 + QT;
    for (int k0 = 0; k0 < kend; k0 += KT) {
        for (int f = t; f < KT * HD / 4; f += 128) {
            int r  = f / (HD / 4);
            int c4 = (f % (HD / 4)) * 4;
            *(float4*)(&k_s[r * HD + c4]) =
                *(const float4*)(Kg + (long)(k0 + r) * rs + base + c4);
            *(float4*)(&v_s[r * HD + c4]) =
                *(const float4*)(Vg + (long)(k0 + r) * rs + base + c4);
        }
        __syncthreads();

        float s[KT];
#pragma unroll
        for (int j = 0; j < KT; j++) s[j] = 0.f;
        for (int d = 0; d < HD; d++) {
            float qd = q_s[t * (HD + 1) + d];
#pragma unroll
            for (int j = 0; j < KT; j++) s[j] += qd * k_s[j * HD + d];
        }
        float mnew = m_run;
#pragma unroll
        for (int j = 0; j < KT; j++) {
            if (k0 + j > sq) s[j] = -1e9f;
            mnew = fmaxf(mnew, s[j]);
        }
        float corr = __expf(m_run - mnew);
        l_run *= corr;
#pragma unroll
        for (int d = 0; d < HD; d++) acc[d] *= corr;
        for (int j = 0; j < KT; j++) {
            float p = __expf(s[j] - mnew);
            l_run += p;
#pragma unroll
            for (int d = 0; d < HD; d++) acc[d] += p * v_s[j * HD + d];
        }
        m_run = mnew;
        __syncthreads();
    }
    float inv = 1.f / l_run;
    long offp = ((long)sq * (B * D) + (long)b * D + (long)h * HD) >> 1;
#pragma unroll
    for (int d = 0; d < HD; d += 2) {
        float v0 = acc[d] * inv, v1 = acc[d + 1] * inv;
        uint16_t h0, l0, h1, l1;
        bfsplit(v0, h0, l0);
        bfsplit(v1, h1, l1);
        Ohp[offp + (d >> 1)] = ((uint32_t)h1 << 16) | h0;
        Olp[offp + (d >> 1)] = ((uint32_t)l1 << 16) | l0;
    }
}

// ---------------- gate: logits, softmax, argmax (fp32, exact) ----------------
__global__ void __launch_bounds__(256) gate_kernel(
    const float* __restrict__ tok, const float* __restrict__ gw,
    float* __restrict__ gates, int* __restrict__ eidx, float* __restrict__ gp)
{
    int n = blockIdx.x, t = threadIdx.x;
    const float* row = tok + (long)n * D;
    float p[E];
#pragma unroll
    for (int e = 0; e < E; e++) p[e] = 0.f;
    for (int d = t; d < D; d += 256) {
        float xv = row[d];
        const float* w = gw + (long)d * E;
#pragma unroll
        for (int e = 0; e < E; e++) p[e] += xv * w[e];
    }
    __shared__ float red[256 * E];
#pragma unroll
    for (int e = 0; e < E; e++) red[t * E + e] = p[e];
    __syncthreads();
    for (int st = 128; st > 0; st >>= 1) {
        if (t < st)
#pragma unroll
            for (int e = 0; e < E; e++) red[t * E + e] += red[(t + st) * E + e];
        __syncthreads();
    }
    if (t == 0) {
        float lg[E], mx = -1e30f;
#pragma unroll
        for (int e = 0; e < E; e++) { lg[e] = red[e]; mx = fmaxf(mx, lg[e]); }
        float sum = 0.f, pr[E];
#pragma unroll
        for (int e = 0; e < E; e++) { pr[e] = __expf(lg[e] - mx); sum += pr[e]; }
        float inv = 1.f / sum;
        int best = 0; float bv = -1e30f;
#pragma unroll
        for (int e = 0; e < E; e++) {
            float g = pr[e] * inv;
            gates[(long)n * E + e] = g;
            if (g > bv) { bv = g; best = e; }
        }
        eidx[n] = best;
        gp[n]   = bv;
    }
}

// ---------------- routing scan (deterministic, single block) ----------------
__global__ void __launch_bounds__(256) scan_kernel(
    const int* __restrict__ eidx, const float* __restrict__ gp,
    int* __restrict__ slot, float* __restrict__ gv, int* __restrict__ cnt)
{
    __shared__ int scnt[256][E];
    int t = threadIdx.x;
    int c[E];
#pragma unroll
    for (int e = 0; e < E; e++) c[e] = 0;
    int n0 = t * (N / 256);
    for (int i = 0; i < N / 256; i++) c[eidx[n0 + i]]++;
#pragma unroll
    for (int e = 0; e < E; e++) scnt[t][e] = c[e];
    __syncthreads();
    if (t < E) {
        int run = 0;
        for (int j = 0; j < 256; j++) { int tmp = scnt[j][t]; scnt[j][t] = run; run += tmp; }
        cnt[t] = run;
    }
    __syncthreads();
    int off[E];
#pragma unroll
    for (int e = 0; e < E; e++) off[e] = scnt[t][e];
    for (int i = 0; i < N / 256; i++) {
        int n = n0 + i;
        int e = eidx[n];
        int l = off[e]++;
        bool keep = (l < CAP);
        slot[n] = keep ? e * CAP + l : -1;
        gv[n]   = keep ? gp[n] : 0.f;
    }
}

// ---------------- l_aux (deterministic tree reduce) ----------------
__global__ void __launch_bounds__(256) laux_kernel(
    const float* __restrict__ gates, const int* __restrict__ cnt,
    float* __restrict__ out_laux)
{
    __shared__ float red[256];
    int t = threadIdx.x;
    float loc[E];
#pragma unroll
    for (int e = 0; e < E; e++) loc[e] = 0.f;
    for (int n = t; n < N; n += 256)
#pragma unroll
        for (int e = 0; e < E; e++) loc[e] += gates[(long)n * E + e];
    float total[E];
    for (int e = 0; e < E; e++) {
        red[t] = loc[e]; __syncthreads();
        for (int st = 128; st > 0; st >>= 1) {
            if (t < st) red[t] += red[t + st];
            __syncthreads();
        }
        if (t == 0) total[e] = red[0];
        __syncthreads();
    }
    if (t == 0) {
        float la = 0.f;
        for (int e = 0; e < E; e++)
            la += (total[e] / N) * ((float)cnt[e] / N);
        *out_laux = (float)E * la;
    }
}

// ---------------- dispatch / combine ----------------
__global__ void __launch_bounds__(256) dispatch_kernel(
    const float* __restrict__ tok, const int* __restrict__ slot,
    uint16_t* __restrict__ dispb)
{
    int n = blockIdx.x;
    int s = slot[n];
    if (s < 0) return;
    int t = threadIdx.x;
    float4 v = ((const float4*)(tok + (long)n * D))[t];
    uint2 o;
    o.x = packbf2(v.x, v.y);
    o.y = packbf2(v.z, v.w);
    *(uint2*)(dispb + (long)s * D + t * 4) = o;
}

__global__ void __launch_bounds__(256) combine_kernel(
    const float* __restrict__ x1, const float* __restrict__ eo,
    const int* __restrict__ slot, const float* __restrict__ gv,
    float* __restrict__ out)
{
    int n = blockIdx.x, t = threadIdx.x;
    int s = slot[n];
    float g = gv[n];
    float4 r = ((const float4*)(x1 + (long)n * D))[t];
    if (s >= 0) {
        float4 v = ((const float4*)(eo + (long)s * D))[t];
        r.x += v.x * g; r.y += v.y * g; r.z += v.z * g; r.w += v.w * g;
    }
    ((float4*)(out + (long)n * D))[t] = r;
}

// ---------------- launch ----------------
extern "C" void kernel_launch(void* const* d_in, const int* in_sizes, int n_in,
                              void* d_out, int out_size) {
    const float* x    = (const float*)d_in[0];
    const float* wq   = (const float*)d_in[2];
    const float* bq   = (const float*)d_in[3];
    const float* wk   = (const float*)d_in[4];
    const float* bk   = (const float*)d_in[5];
    const float* wv   = (const float*)d_in[6];
    const float* bv   = (const float*)d_in[7];
    const float* wo   = (const float*)d_in[8];
    const float* bo   = (const float*)d_in[9];
    const float* ln1g = (const float*)d_in[10];
    const float* ln1b = (const float*)d_in[11];
    const float* ln2g = (const float*)d_in[12];
    const float* ln2b = (const float*)d_in[13];
    const float* gw   = (const float*)d_in[14];
    const float* w1   = (const float*)d_in[15];
    const float* b1   = (const float*)d_in[16];
    const float* w2   = (const float*)d_in[17];
    const float* b2   = (const float*)d_in[18];
    float* out = (float*)d_out;

    float *qkv, *x1, *tok, *eo, *gates, *gp, *gv, *b3;
    uint32_t *xnh, *xnl, *aoh, *aol, *wqkvh, *wqkvl, *woh, *wol, *w1p, *w2p;
    uint16_t *dispb, *hb;
    int *eidx, *slot, *cnt;
    cudaGetSymbolAddress((void**)&xnh,   g_xnh);
    cudaGetSymbolAddress((void**)&xnl,   g_xnl);
    cudaGetSymbolAddress((void**)&qkv,   g_qkv);
    cudaGetSymbolAddress((void**)&aoh,   g_aoh);
    cudaGetSymbolAddress((void**)&aol,   g_aol);
    cudaGetSymbolAddress((void**)&x1,    g_x1);
    cudaGetSymbolAddress((void**)&tok,   g_tok);
    cudaGetSymbolAddress((void**)&wqkvh, g_wqkvh);
    cudaGetSymbolAddress((void**)&wqkvl, g_wqkvl);
    cudaGetSymbolAddress((void**)&b3,    g_b3);
    cudaGetSymbolAddress((void**)&woh,   g_woh);
    cudaGetSymbolAddress((void**)&wol,   g_wol);
    cudaGetSymbolAddress((void**)&dispb, g_dispb);
    cudaGetSymbolAddress((void**)&hb,    g_hb);
    cudaGetSymbolAddress((void**)&eo,    g_eo);
    cudaGetSymbolAddress((void**)&w1p,   g_w1p);
    cudaGetSymbolAddress((void**)&w2p,   g_w2p);
    cudaGetSymbolAddress((void**)&gates, g_gates);
    cudaGetSymbolAddress((void**)&gp,    g_gp);
    cudaGetSymbolAddress((void**)&gv,    g_gv);
    cudaGetSymbolAddress((void**)&eidx,  g_eidx);
    cudaGetSymbolAddress((void**)&slot,  g_slot);
    cudaGetSymbolAddress((void**)&cnt,   g_cnt);

    cudaFuncSetAttribute(attn_kernel,
                         cudaFuncAttributeMaxDynamicSharedMemorySize, ATTN_SMEM);
    cudaFuncSetAttribute(gemm_bf16w_kernel<1, 1>,
                         cudaFuncAttributeMaxDynamicSharedMemorySize, EXP_SMEM);
    cudaFuncSetAttribute(gemm_bf16w_kernel<0, 0>,
                         cudaFuncAttributeMaxDynamicSharedMemorySize, EXP_SMEM);

    // one-time prep: bf16-pair weight splits (q scaled by 1/8 exactly),
    // fused bias concat, expert weight k-pair packs
    splitwp_kernel<<<dim3(D / 256, Dp), 256>>>(wq, wqkvh, wqkvl, D, D3, 0,     0.125f);
    splitwp_kernel<<<dim3(D / 256, Dp), 256>>>(wk, wqkvh, wqkvl, D, D3, D,     1.0f);
    splitwp_kernel<<<dim3(D / 256, Dp), 256>>>(wv, wqkvh, wqkvl, D, D3, 2 * D, 1.0f);
    biascat3_kernel<<<D / 256, 256>>>(bq, bk, bv, b3);
    splitwp_kernel<<<dim3(D / 256, Dp), 256>>>(wo, woh, wol, D, D, 0, 1.0f);
    packw_kernel<<<dim3(F / 256, D / 2, E), 256>>>(w1, w1p, F,
        (long long)D * F, (long long)(D / 2) * F);
    packw_kernel<<<dim3(D / 256, F / 2, E), 256>>>(w2, w2p, D,
        (long long)F * D, (long long)(F / 2) * D);

    // 1) LN1 -> bf16-pair hi/lo
    ln_splitp_kernel<<<N, 256>>>(x, ln1g, ln1b, xnh, xnl);
    // 2) merged QKV projection (bf16x3, Nc=3072)
    gemm_b3_kernel<0><<<dim3(D3 / 128, N / 128), 256>>>(
        xnh, xnl, wqkvh, wqkvl, b3, nullptr, qkv, N, D3, D);
    // 3) attention (reads strided qkv; emits bf16-pair hi/lo)
    attn_kernel<<<dim3(S / QT, B * H), 128, ATTN_SMEM>>>(
        qkv, qkv + D, qkv + 2 * D, D3, aoh, aol);
    // 4) output projection + residual (bf16x3)
    gemm_b3_kernel<1><<<dim3(D / 128, N / 128), 256>>>(
        aoh, aol, woh, wol, bo, x, x1, N, D, D);
    // 5) LN2
    ln_kernel<<<N, 256>>>(x1, ln2g, ln2b, tok);
    // 6) gate
    gate_kernel<<<N, 256>>>(tok, gw, gates, eidx, gp);
    // 7) routing scan
    scan_kernel<<<1, 256>>>(eidx, gp, slot, gv, cnt);
    // 8) l_aux -> last output element
    laux_kernel<<<1, 256>>>(gates, cnt, out + (out_size - 1));
    // 9) dispatch (writes bf16)
    dispatch_kernel<<<N, 256>>>(tok, slot, dispb);
    // 10) expert GEMM1 (relu, bf16 -> bf16) — only live tiles compute
    gemm_bf16w_kernel<1, 1><<<dim3(F / 256, CAP / 128, E), 256, EXP_SMEM>>>(
        dispb, w1p, b1, hb, cnt, CAP, F, D,
        (long long)CAP * D, (long long)(D / 2) * F, (long long)F, (long long)CAP * F);
    // 11) expert GEMM2 (bf16 -> fp32) — only live tiles compute
    gemm_bf16w_kernel<0, 0><<<dim3(D / 256, CAP / 128, E), 256, EXP_SMEM>>>(
        hb, w2p, b2, eo, cnt, CAP, D, F,
        (long long)CAP * F, (long long)(F / 2) * D, (long long)D, (long long)CAP * D);
    // 12) combine + residual -> output
    combine_kernel<<<N, 256>>>(x1, eo, slot, gv, out);
}

// round 16
// speedup vs baseline: 2.7696x; 1.4402x over previous
#include <cuda_runtime.h>
#include <cstdint>

// ---------------- problem constants ----------------
constexpr int S = 1024, B = 8, D = 1024, H = 16, F = 4096, E = 8;
constexpr int HD = D / H;           // 64
constexpr int N = S * B;            // 8192
constexpr int CAP = 4 * N / E;      // 4096
constexpr int D3 = 3 * D;           // 3072 (merged qkv width)
constexpr int Dp = D / 2;           // pair count per row

// ---------------- scratch (device globals; no allocations) ----------------
__device__ uint32_t g_xnh[N * Dp], g_xnl[N * Dp];    // LN1 out, bf16-pair hi/lo
__device__ float    g_qkv[N * D3];                   // merged q|k|v
__device__ uint32_t g_aoh[N * Dp], g_aol[N * Dp];    // attn out, bf16-pair hi/lo
__device__ float g_x1 [N * D];
__device__ float g_tok[N * D];
__device__ uint32_t g_wqkvh[Dp * D3], g_wqkvl[Dp * D3];  // bf16 k-pair hi/lo
__device__ float    g_b3[D3];
__device__ uint32_t g_woh[Dp * D], g_wol[Dp * D];
__device__ uint32_t g_kh2[B * H * 32 * S], g_kl2[B * H * 32 * S];   // K hi/lo [bh][dp][s]
__device__ uint32_t g_vh2[B * H * (S / 2) * HD], g_vl2[B * H * (S / 2) * HD]; // V [bh][kp][d]
__device__ uint16_t g_dispb[E * CAP * D];            // bf16 dispatched tokens
__device__ uint16_t g_hb  [134217728];               // E*CAP*F bf16 hidden
__device__ float    g_eo  [E * CAP * D];
__device__ uint32_t g_w1p [(D / 2) * F * E];         // bf16 k-pair packed w1
__device__ uint32_t g_w2p [(F / 2) * D * E];         // bf16 k-pair packed w2
__device__ float g_gates[N * E];
__device__ int   g_eidx[N];
__device__ float g_gp  [N];
__device__ int   g_slot[N];
__device__ float g_gv  [N];
__device__ int   g_cnt [E];

// ---------------- helpers ----------------
__device__ __forceinline__ uint32_t packbf2(float lo, float hi) {
    uint32_t d;
    asm("cvt.rn.bf16x2.f32 %0, %1, %2;" : "=r"(d) : "f"(hi), "f"(lo));
    return d;
}
__device__ __forceinline__ uint16_t f2bf(float f) {
    uint16_t u;
    asm("cvt.rn.bf16.f32 %0, %1;" : "=h"(u) : "f"(f));
    return u;
}
__device__ __forceinline__ float bf2f(uint16_t h) {
    return __uint_as_float((uint32_t)h << 16);
}
__device__ __forceinline__ void bfsplit(float v, uint16_t& h, uint16_t& l) {
    h = f2bf(v);
    l = f2bf(v - bf2f(h));
}
__device__ __forceinline__ uint32_t packsplit_h(float a, float b) {
    uint16_t ha = f2bf(a), hb = f2bf(b);
    return ((uint32_t)hb << 16) | ha;
}
__device__ __forceinline__ uint32_t packsplit_l(float a, float b) {
    uint16_t ha = f2bf(a), hb = f2bf(b);
    uint16_t la = f2bf(a - bf2f(ha)), lb = f2bf(b - bf2f(hb));
    return ((uint32_t)lb << 16) | la;
}

#define MMA_BF16(acc, a, b0, b1) \
    asm volatile("mma.sync.aligned.m16n8k16.row.col.f32.bf16.bf16.f32 " \
        "{%0,%1,%2,%3}, {%4,%5,%6,%7}, {%8,%9}, {%0,%1,%2,%3};" \
        : "+f"((acc)[0]), "+f"((acc)[1]), "+f"((acc)[2]), "+f"((acc)[3]) \
        : "r"((a)[0]), "r"((a)[1]), "r"((a)[2]), "r"((a)[3]), "r"(b0), "r"(b1))

// ---------------- weight split: fp32 [K][NcSrc] -> bf16-pair hi/lo ----------
__global__ void __launch_bounds__(256) splitwp_kernel(
    const float* __restrict__ W, uint32_t* __restrict__ Ph,
    uint32_t* __restrict__ Pl, int NcSrc, int NcDst, int colOff, float scale)
{
    int n  = blockIdx.x * 256 + threadIdx.x;
    int k2 = blockIdx.y;
    float v0 = W[(long long)(2 * k2)     * NcSrc + n] * scale;
    float v1 = W[(long long)(2 * k2 + 1) * NcSrc + n] * scale;
    long long o = (long long)k2 * NcDst + colOff + n;
    Ph[o] = packsplit_h(v0, v1);
    Pl[o] = packsplit_l(v0, v1);
}
__global__ void __launch_bounds__(256) biascat3_kernel(
    const float* __restrict__ bq, const float* __restrict__ bk,
    const float* __restrict__ bv, float* __restrict__ dst)
{
    int i = blockIdx.x * 256 + threadIdx.x;
    dst[i]         = bq[i] * 0.125f;
    dst[i + D]     = bk[i];
    dst[i + 2 * D] = bv[i];
}

// ---------------- LayerNorm (fp32 out) ----------------
__global__ void __launch_bounds__(256) ln_kernel(const float* __restrict__ x,
                                                 const float* __restrict__ gam,
                                                 const float* __restrict__ bet,
                                                 float* __restrict__ y) {
    int n = blockIdx.x;
    const float* row = x + (long)n * D;
    int t = threadIdx.x;
    float s = 0.f, s2 = 0.f;
    for (int d = t; d < D; d += 256) { float v = row[d]; s += v; s2 += v * v; }
    __shared__ float r1[256], r2[256];
    r1[t] = s; r2[t] = s2; __syncthreads();
    for (int st = 128; st > 0; st >>= 1) {
        if (t < st) { r1[t] += r1[t + st]; r2[t] += r2[t + st]; }
        __syncthreads();
    }
    float mean = r1[0] / D;
    float var  = r2[0] / D - mean * mean;
    float inv  = rsqrtf(var + 1e-5f);
    float* yo = y + (long)n * D;
    for (int d = t; d < D; d += 256)
        yo[d] = (row[d] - mean) * inv * gam[d] + bet[d];
}

// ---------------- LayerNorm (bf16-pair hi/lo out) ----------------
__global__ void __launch_bounds__(256) ln_splitp_kernel(
    const float* __restrict__ x, const float* __restrict__ gam,
    const float* __restrict__ bet,
    uint32_t* __restrict__ yh, uint32_t* __restrict__ yl)
{
    int n = blockIdx.x;
    const float* row = x + (long)n * D;
    int t = threadIdx.x;
    float s = 0.f, s2 = 0.f;
    for (int d = t; d < D; d += 256) { float v = row[d]; s += v; s2 += v * v; }
    __shared__ float r1[256], r2[256];
    r1[t] = s; r2[t] = s2; __syncthreads();
    for (int st = 128; st > 0; st >>= 1) {
        if (t < st) { r1[t] += r1[t + st]; r2[t] += r2[t + st]; }
        __syncthreads();
    }
    float mean = r1[0] / D;
    float var  = r2[0] / D - mean * mean;
    float inv  = rsqrtf(var + 1e-5f);
    float4 v4 = *(const float4*)(row + 4 * t);
    float4 g4 = *(const float4*)(gam + 4 * t);
    float4 b4 = *(const float4*)(bet + 4 * t);
    float v0 = (v4.x - mean) * inv * g4.x + b4.x;
    float v1 = (v4.y - mean) * inv * g4.y + b4.y;
    float v2 = (v4.z - mean) * inv * g4.z + b4.z;
    float v3 = (v4.w - mean) * inv * g4.w + b4.w;
    long long o = (long long)n * Dp + 2 * t;
    yh[o]     = packsplit_h(v0, v1);
    yh[o + 1] = packsplit_h(v2, v3);
    yl[o]     = packsplit_l(v0, v1);
    yl[o + 1] = packsplit_l(v2, v3);
}

// ---------------- bf16x3 GEMM (projections) ----------------------------------
template<int HAS_RESID>
__global__ void __launch_bounds__(256, 2) gemm_b3_kernel(
    const uint32_t* __restrict__ Aph, const uint32_t* __restrict__ Apl,
    const uint32_t* __restrict__ Bph, const uint32_t* __restrict__ Bpl,
    const float* __restrict__ bias, const float* __restrict__ resid,
    float* __restrict__ C, int M, int Nc, int K)
{
    __shared__ uint32_t Ash[8][136], Asl[8][136];
    __shared__ uint32_t Bsh[8][136], Bsl[8][136];

    int t    = threadIdx.x;
    int wid  = t >> 5, lane = t & 31;
    int gid  = lane >> 2, tig = lane & 3;
    int wm0  = (wid & 1) * 64;
    int wn0  = (wid >> 1) * 32;
    int m0   = blockIdx.y * 128, n0 = blockIdx.x * 128;
    int Kp   = K >> 1;

    int arow = t >> 1, apg = (t & 1) * 4;
    int brow = t >> 5, bcol = (t & 31) * 4;

    float acc[4][4][4];
#pragma unroll
    for (int mt = 0; mt < 4; mt++)
#pragma unroll
        for (int nt = 0; nt < 4; nt++)
#pragma unroll
            for (int r = 0; r < 4; r++) acc[mt][nt][r] = 0.f;

    for (int kp0 = 0; kp0 < Kp; kp0 += 8) {
        {
            uint4 vh = *(const uint4*)(Aph + (long long)(m0 + arow) * Kp + kp0 + apg);
            uint4 vl = *(const uint4*)(Apl + (long long)(m0 + arow) * Kp + kp0 + apg);
            Ash[apg + 0][arow] = vh.x; Ash[apg + 1][arow] = vh.y;
            Ash[apg + 2][arow] = vh.z; Ash[apg + 3][arow] = vh.w;
            Asl[apg + 0][arow] = vl.x; Asl[apg + 1][arow] = vl.y;
            Asl[apg + 2][arow] = vl.z; Asl[apg + 3][arow] = vl.w;
        }
        {
            *(uint4*)&Bsh[brow][bcol] =
                *(const uint4*)(Bph + (long long)(kp0 + brow) * Nc + n0 + bcol);
            *(uint4*)&Bsl[brow][bcol] =
                *(const uint4*)(Bpl + (long long)(kp0 + brow) * Nc + n0 + bcol);
        }
        __syncthreads();

        uint32_t fah[4][4], fal[4][4], fbh[4][2], fbl[4][2];
#pragma unroll
        for (int mt = 0; mt < 4; mt++) {
            int mm = wm0 + mt * 16 + gid;
            fah[mt][0] = Ash[tig    ][mm];
            fah[mt][1] = Ash[tig    ][mm + 8];
            fah[mt][2] = Ash[tig + 4][mm];
            fah[mt][3] = Ash[tig + 4][mm + 8];
            fal[mt][0] = Asl[tig    ][mm];
            fal[mt][1] = Asl[tig    ][mm + 8];
            fal[mt][2] = Asl[tig + 4][mm];
            fal[mt][3] = Asl[tig + 4][mm + 8];
        }
#pragma unroll
        for (int nt = 0; nt < 4; nt++) {
            int nn = wn0 + nt * 8 + gid;
            fbh[nt][0] = Bsh[tig    ][nn];
            fbh[nt][1] = Bsh[tig + 4][nn];
            fbl[nt][0] = Bsl[tig    ][nn];
            fbl[nt][1] = Bsl[tig + 4][nn];
        }
#pragma unroll
        for (int mt = 0; mt < 4; mt++)
#pragma unroll
            for (int nt = 0; nt < 4; nt++) {
                MMA_BF16(acc[mt][nt], fah[mt], fbl[nt][0], fbl[nt][1]);
                MMA_BF16(acc[mt][nt], fal[mt], fbh[nt][0], fbh[nt][1]);
                MMA_BF16(acc[mt][nt], fah[mt], fbh[nt][0], fbh[nt][1]);
            }
        __syncthreads();
    }

#pragma unroll
    for (int mt = 0; mt < 4; mt++) {
#pragma unroll
        for (int nt = 0; nt < 4; nt++) {
            int row = m0 + wm0 + mt * 16 + gid;
            int col = n0 + wn0 + nt * 8 + 2 * tig;
            float b0 = bias[col], b1 = bias[col + 1];
            float c0 = acc[mt][nt][0] + b0;
            float c1 = acc[mt][nt][1] + b1;
            float c2 = acc[mt][nt][2] + b0;
            float c3 = acc[mt][nt][3] + b1;
            if (HAS_RESID) {
                float2 r0 = *(const float2*)(resid + (long long)row * Nc + col);
                float2 r1 = *(const float2*)(resid + (long long)(row + 8) * Nc + col);
                c0 += r0.x; c1 += r0.y; c2 += r1.x; c3 += r1.y;
            }
            *(float2*)(C + (long long)row * Nc + col)       = make_float2(c0, c1);
            *(float2*)(C + (long long)(row + 8) * Nc + col) = make_float2(c2, c3);
        }
    }
}

// ---------------- K/V conversion: fp32 qkv -> packed bf16-pair hi/lo planes -
// K: [bh][dpair 32][s 1024]   (pairs along d)
__global__ void __launch_bounds__(256) convk_kernel(
    const float* __restrict__ qkv, uint32_t* __restrict__ Kh,
    uint32_t* __restrict__ Kl)
{
    __shared__ uint32_t th[32][33], tl[32][33];
    int bh = blockIdx.y, h = bh & (H - 1), b = bh >> 4;
    int s0 = blockIdx.x * 32;
    int tx = threadIdx.x & 31, ty = threadIdx.x >> 5;
    for (int i = ty; i < 32; i += 8) {
        int s = s0 + i;
        float2 v = *(const float2*)(qkv + ((long)s * B + b) * D3 + D + h * HD + 2 * tx);
        th[i][tx] = packsplit_h(v.x, v.y);
        tl[i][tx] = packsplit_l(v.x, v.y);
    }
    __syncthreads();
    long obase = (long)bh * 32 * S;
    for (int i = ty; i < 32; i += 8) {
        Kh[obase + (long)i * S + s0 + tx] = th[tx][i];
        Kl[obase + (long)i * S + s0 + tx] = tl[tx][i];
    }
}
// V: [bh][keypair 512][d 64]   (pairs along s)
__global__ void __launch_bounds__(256) convv_kernel(
    const float* __restrict__ qkv, uint32_t* __restrict__ Vh,
    uint32_t* __restrict__ Vl)
{
    int bh = blockIdx.y, h = bh & (H - 1), b = bh >> 4;
    int t = threadIdx.x;
    int kp = blockIdx.x * 4 + (t >> 6);
    int d  = t & 63;
    float v0 = qkv[((long)(2 * kp)     * B + b) * D3 + 2 * D + h * HD + d];
    float v1 = qkv[((long)(2 * kp + 1) * B + b) * D3 + 2 * D + h * HD + d];
    long o = (long)bh * (S / 2) * HD + (long)kp * HD + d;
    Vh[o] = packsplit_h(v0, v1);
    Vl[o] = packsplit_l(v0, v1);
}

// ---------------- tensor-core flash attention (bf16 hi/lo x3) ---------------
// Block: 128 q rows, 8 warps (warp w -> rows q0+16w+{gid,gid+8}); KT=64 keys.
__global__ void __launch_bounds__(256) attn_tc_kernel(
    const float* __restrict__ Qg,
    const uint32_t* __restrict__ Kh, const uint32_t* __restrict__ Kl,
    const uint32_t* __restrict__ Vh, const uint32_t* __restrict__ Vl,
    uint32_t* __restrict__ Ohp, uint32_t* __restrict__ Olp)
{
    __shared__ uint32_t Ksh[32][72], Ksl[32][72], Vsh[32][72], Vsl[32][72];

    int bh = blockIdx.y, h = bh & (H - 1), b = bh >> 4;
    int q0 = blockIdx.x * 128;
    int t = threadIdx.x, wid = t >> 5, lane = t & 31;
    int gid = lane >> 2, tig = lane & 3;

    long kbase = (long)bh * 32 * S;
    long vbase = (long)bh * (S / 2) * HD;

    int r0 = q0 + wid * 16 + gid;
    int r1 = r0 + 8;

    // Q fragments (hi/lo) in registers
    uint32_t qfh[4][4], qfl[4][4];
    {
        long ro0 = ((long)r0 * B + b) * D3 + h * HD;
        long ro1 = ((long)r1 * B + b) * D3 + h * HD;
#pragma unroll
        for (int kc = 0; kc < 4; kc++) {
            int p0 = kc * 8 + tig, p1 = p0 + 4;
            float2 x0 = *(const float2*)(Qg + ro0 + 2 * p0);
            float2 x1 = *(const float2*)(Qg + ro1 + 2 * p0);
            float2 x2 = *(const float2*)(Qg + ro0 + 2 * p1);
            float2 x3 = *(const float2*)(Qg + ro1 + 2 * p1);
            qfh[kc][0] = packsplit_h(x0.x, x0.y); qfl[kc][0] = packsplit_l(x0.x, x0.y);
            qfh[kc][1] = packsplit_h(x1.x, x1.y); qfl[kc][1] = packsplit_l(x1.x, x1.y);
            qfh[kc][2] = packsplit_h(x2.x, x2.y); qfl[kc][2] = packsplit_l(x2.x, x2.y);
            qfh[kc][3] = packsplit_h(x3.x, x3.y); qfl[kc][3] = packsplit_l(x3.x, x3.y);
        }
    }

    float o[8][4];
#pragma unroll
    for (int nt = 0; nt < 8; nt++)
#pragma unroll
        for (int j = 0; j < 4; j++) o[nt][j] = 0.f;
    float m0 = -1e30f, m1 = -1e30f, l0 = 0.f, l1 = 0.f;

    int kend = q0 + 128;
    for (int k0 = 0; k0 < kend; k0 += 64) {
        // stage K/V hi/lo tiles (coalesced; [.][72] stride -> conflict-free LDS)
#pragma unroll
        for (int i = 0; i < 8; i++) {
            int idx = t + i * 256;
            int row = idx >> 6, col = idx & 63;
            Ksh[row][col] = Kh[kbase + (long)row * S + k0 + col];
            Ksl[row][col] = Kl[kbase + (long)row * S + k0 + col];
            Vsh[row][col] = Vh[vbase + (long)((k0 >> 1) + row) * HD + col];
            Vsl[row][col] = Vl[vbase + (long)((k0 >> 1) + row) * HD + col];
        }
        __syncthreads();

        bool active = (k0 <= q0 + wid * 16 + 15);  // warp-uniform causal skip
        if (active) {
            // ---- S = Q K^T (3-term hi/lo) ----
            float sacc[8][4];
#pragma unroll
            for (int nt = 0; nt < 8; nt++)
#pragma unroll
                for (int j = 0; j < 4; j++) sacc[nt][j] = 0.f;
#pragma unroll
            for (int kc = 0; kc < 4; kc++) {
#pragma unroll
                for (int nt = 0; nt < 8; nt++) {
                    int nn = nt * 8 + gid;
                    uint32_t bh0 = Ksh[kc * 8 + tig][nn];
                    uint32_t bh1 = Ksh[kc * 8 + tig + 4][nn];
                    uint32_t bl0 = Ksl[kc * 8 + tig][nn];
                    uint32_t bl1 = Ksl[kc * 8 + tig + 4][nn];
                    MMA_BF16(sacc[nt], qfh[kc], bl0, bl1);
                    MMA_BF16(sacc[nt], qfl[kc], bh0, bh1);
                    MMA_BF16(sacc[nt], qfh[kc], bh0, bh1);
                }
            }
            // ---- causal mask + online softmax ----
            float mloc0 = -1e30f, mloc1 = -1e30f;
#pragma unroll
            for (int nt = 0; nt < 8; nt++) {
                int c0 = k0 + nt * 8 + 2 * tig, c1 = c0 + 1;
                if (c0 > r0) sacc[nt][0] = -1e9f;
                if (c1 > r0) sacc[nt][1] = -1e9f;
                if (c0 > r1) sacc[nt][2] = -1e9f;
                if (c1 > r1) sacc[nt][3] = -1e9f;
                mloc0 = fmaxf(mloc0, fmaxf(sacc[nt][0], sacc[nt][1]));
                mloc1 = fmaxf(mloc1, fmaxf(sacc[nt][2], sacc[nt][3]));
            }
            mloc0 = fmaxf(mloc0, __shfl_xor_sync(0xffffffffu, mloc0, 1));
            mloc0 = fmaxf(mloc0, __shfl_xor_sync(0xffffffffu, mloc0, 2));
            mloc1 = fmaxf(mloc1, __shfl_xor_sync(0xffffffffu, mloc1, 1));
            mloc1 = fmaxf(mloc1, __shfl_xor_sync(0xffffffffu, mloc1, 2));
            float mn0 = fmaxf(m0, mloc0), mn1 = fmaxf(m1, mloc1);
            float cr0 = __expf(m0 - mn0), cr1 = __expf(m1 - mn1);
            l0 *= cr0; l1 *= cr1;
#pragma unroll
            for (int nt = 0; nt < 8; nt++) {
                o[nt][0] *= cr0; o[nt][1] *= cr0;
                o[nt][2] *= cr1; o[nt][3] *= cr1;
            }
#pragma unroll
            for (int nt = 0; nt < 8; nt++) {
                float p0 = __expf(sacc[nt][0] - mn0);
                float p1 = __expf(sacc[nt][1] - mn0);
                float p2 = __expf(sacc[nt][2] - mn1);
                float p3 = __expf(sacc[nt][3] - mn1);
                l0 += p0 + p1; l1 += p2 + p3;
                sacc[nt][0] = p0; sacc[nt][1] = p1;
                sacc[nt][2] = p2; sacc[nt][3] = p3;
            }
            m0 = mn0; m1 = mn1;
            // ---- O += P V (3-term hi/lo; S-frag -> P A-frag, register direct)
#pragma unroll
            for (int kc2 = 0; kc2 < 4; kc2++) {
                int fA = 2 * kc2, fB = fA + 1;
                uint32_t pah[4], pal[4];
                pah[0] = packsplit_h(sacc[fA][0], sacc[fA][1]);
                pal[0] = packsplit_l(sacc[fA][0], sacc[fA][1]);
                pah[1] = packsplit_h(sacc[fA][2], sacc[fA][3]);
                pal[1] = packsplit_l(sacc[fA][2], sacc[fA][3]);
                pah[2] = packsplit_h(sacc[fB][0], sacc[fB][1]);
                pal[2] = packsplit_l(sacc[fB][0], sacc[fB][1]);
                pah[3] = packsplit_h(sacc[fB][2], sacc[fB][3]);
                pal[3] = packsplit_l(sacc[fB][2], sacc[fB][3]);
#pragma unroll
                for (int nt = 0; nt < 8; nt++) {
                    int nn = nt * 8 + gid;
                    uint32_t vh0 = Vsh[kc2 * 8 + tig][nn];
                    uint32_t vh1 = Vsh[kc2 * 8 + tig + 4][nn];
                    uint32_t vl0 = Vsl[kc2 * 8 + tig][nn];
                    uint32_t vl1 = Vsl[kc2 * 8 + tig + 4][nn];
                    MMA_BF16(o[nt], pah, vl0, vl1);
                    MMA_BF16(o[nt], pal, vh0, vh1);
                    MMA_BF16(o[nt], pah, vh0, vh1);
                }
            }
        }
        __syncthreads();
    }
    // finalize: row sums across quad, normalize, emit bf16-pair hi/lo
    l0 += __shfl_xor_sync(0xffffffffu, l0, 1);
    l0 += __shfl_xor_sync(0xffffffffu, l0, 2);
    l1 += __shfl_xor_sync(0xffffffffu, l1, 1);
    l1 += __shfl_xor_sync(0xffffffffu, l1, 2);
    float i0 = 1.f / l0, i1 = 1.f / l1;
    long t0 = (long)r0 * B + b, t1 = (long)r1 * B + b;
#pragma unroll
    for (int nt = 0; nt < 8; nt++) {
        int dpair = h * 32 + nt * 4 + tig;
        float v0 = o[nt][0] * i0, v1 = o[nt][1] * i0;
        float v2 = o[nt][2] * i1, v3 = o[nt][3] * i1;
        Ohp[t0 * Dp + dpair] = packsplit_h(v0, v1);
        Olp[t0 * Dp + dpair] = packsplit_l(v0, v1);
        Ohp[t1 * Dp + dpair] = packsplit_h(v2, v3);
        Olp[t1 * Dp + dpair] = packsplit_l(v2, v3);
    }
}

// ---------------- weight packing: fp32 [K][Nc] -> bf16 k-pair u32 [K/2][Nc] --
__global__ void __launch_bounds__(256) packw_kernel(
    const float* __restrict__ W, uint32_t* __restrict__ P, int Nc,
    long long sW, long long sP)
{
    int n  = blockIdx.x * 256 + threadIdx.x;
    int k2 = blockIdx.y;
    int z  = blockIdx.z;
    const float* w = W + (long long)z * sW + (long long)(2 * k2) * Nc + n;
    P[(long long)z * sP + (long long)k2 * Nc + n] = packbf2(w[0], w[Nc]);
}

// ---------------- bf16 expert GEMM: block 128x256, warp 64x64, k32 ----------
constexpr int EXP_SMEM = 2 * 16 * 136 * 4 + 2 * 16 * 264 * 4;  // 51200 B

template<int RELU, int OUTBF>
__global__ void __launch_bounds__(256) gemm_bf16w_kernel(
    const uint16_t* __restrict__ A, const uint32_t* __restrict__ Bp,
    const float* __restrict__ bias, void* __restrict__ Cout,
    const int* __restrict__ cnt,
    int M, int Nc, int K,
    long long sA, long long sB, long long sBias, long long sC)
{
    int z = blockIdx.z;
    int m0 = blockIdx.y * 128, n0 = blockIdx.x * 256;
    if (m0 >= cnt[z]) return;

    extern __shared__ uint32_t dyn[];
    uint32_t* As = dyn;
    uint32_t* Bs = dyn + 2 * 16 * 136;

    A    += (long long)z * sA;
    Bp   += (long long)z * sB;
    bias += (long long)z * sBias;

    int t    = threadIdx.x;
    int wid  = t >> 5, lane = t & 31;
    int gid  = lane >> 2, tig = lane & 3;
    int wm0  = (wid & 1) * 64;
    int wn0  = (wid >> 1) * 64;

    int am  = t & 127, ahh = t >> 7;
    int bk  = t >> 4,  bn  = (t & 15) * 16;

    float acc[4][8][4];
#pragma unroll
    for (int mt = 0; mt < 4; mt++)
#pragma unroll
        for (int nt = 0; nt < 8; nt++)
#pragma unroll
            for (int r = 0; r < 4; r++) acc[mt][nt][r] = 0.f;

    auto stageA = [&](int buf, uint4 va0, uint4 va1) {
        uint32_t* as = As + buf * (16 * 136);
        as[(ahh * 4 + 0) * 136 + am] = va0.x;
        as[(ahh * 4 + 1) * 136 + am] = va0.y;
        as[(ahh * 4 + 2) * 136 + am] = va0.z;
        as[(ahh * 4 + 3) * 136 + am] = va0.w;
        as[((ahh + 2) * 4 + 0) * 136 + am] = va1.x;
        as[((ahh + 2) * 4 + 1) * 136 + am] = va1.y;
        as[((ahh + 2) * 4 + 2) * 136 + am] = va1.z;
        as[((ahh + 2) * 4 + 3) * 136 + am] = va1.w;
    };
    auto stageB = [&](int buf, const uint4* vb) {
        uint32_t* bs = Bs + buf * (16 * 264);
#pragma unroll
        for (int j = 0; j < 4; j++)
            *(uint4*)&bs[bk * 264 + bn + j * 4] = vb[j];
    };

    const int nIter = K / 32;
    {
        uint4 va0 = *(const uint4*)(A + (long long)(m0 + am) * K + ahh * 8);
        uint4 va1 = *(const uint4*)(A + (long long)(m0 + am) * K + (ahh + 2) * 8);
        uint4 vb[4];
#pragma unroll
        for (int j = 0; j < 4; j++)
            vb[j] = *(const uint4*)(Bp + (long long)bk * Nc + n0 + bn + j * 4);
        stageA(0, va0, va1);
        stageB(0, vb);
    }
    __syncthreads();

    for (int it = 0; it < nIter; ++it) {
        int cur = it & 1;
        uint4 va0, va1, vb[4];
        bool pf = (it + 1 < nIter);
        if (pf) {
            long long ka = (long long)(m0 + am) * K + (it + 1) * 32;
            va0 = *(const uint4*)(A + ka + ahh * 8);
            va1 = *(const uint4*)(A + ka + (ahh + 2) * 8);
            long long kb = (long long)(it + 1) * 16 + bk;
#pragma unroll
            for (int j = 0; j < 4; j++)
                vb[j] = *(const uint4*)(Bp + kb * Nc + n0 + bn + j * 4);
        }
        const uint32_t* as = As + cur * (16 * 136);
        const uint32_t* bs = Bs + cur * (16 * 264);
#pragma unroll
        for (int kb2 = 0; kb2 < 2; kb2++) {
            int ko = kb2 * 8;
            uint32_t af[4][4], bfr[8][2];
#pragma unroll
            for (int mt = 0; mt < 4; mt++) {
                int mm = wm0 + mt * 16 + gid;
                af[mt][0] = as[(ko + tig    ) * 136 + mm];
                af[mt][1] = as[(ko + tig    ) * 136 + mm + 8];
                af[mt][2] = as[(ko + tig + 4) * 136 + mm];
                af[mt][3] = as[(ko + tig + 4) * 136 + mm + 8];
            }
#pragma unroll
            for (int nt = 0; nt < 8; nt++) {
                int nn = wn0 + nt * 8 + gid;
                bfr[nt][0] = bs[(ko + tig    ) * 264 + nn];
                bfr[nt][1] = bs[(ko + tig + 4) * 264 + nn];
            }
#pragma unroll
            for (int mt = 0; mt < 4; mt++)
#pragma unroll
                for (int nt = 0; nt < 8; nt++)
                    MMA_BF16(acc[mt][nt], af[mt], bfr[nt][0], bfr[nt][1]);
        }
        if (pf) {
            stageA(cur ^ 1, va0, va1);
            stageB(cur ^ 1, vb);
        }
        __syncthreads();
    }

#pragma unroll
    for (int mt = 0; mt < 4; mt++) {
#pragma unroll
        for (int nt = 0; nt < 8; nt++) {
            int row = m0 + wm0 + mt * 16 + gid;
            int col = n0 + wn0 + nt * 8 + 2 * tig;
            float b0 = bias[col], b1 = bias[col + 1];
            float c0 = acc[mt][nt][0] + b0;
            float c1 = acc[mt][nt][1] + b1;
            float c2 = acc[mt][nt][2] + b0;
            float c3 = acc[mt][nt][3] + b1;
            if (RELU) {
                c0 = fmaxf(c0, 0.f); c1 = fmaxf(c1, 0.f);
                c2 = fmaxf(c2, 0.f); c3 = fmaxf(c3, 0.f);
            }
            if (OUTBF) {
                uint16_t* Cb = (uint16_t*)Cout + (long long)z * sC;
                *(uint32_t*)(Cb + (long long)row * Nc + col)       = packbf2(c0, c1);
                *(uint32_t*)(Cb + (long long)(row + 8) * Nc + col) = packbf2(c2, c3);
            } else {
                float* Cf = (float*)Cout + (long long)z * sC;
                *(float2*)(Cf + (long long)row * Nc + col)       = make_float2(c0, c1);
                *(float2*)(Cf + (long long)(row + 8) * Nc + col) = make_float2(c2, c3);
            }
        }
    }
}

// ---------------- gate: logits, softmax, argmax (fp32, exact) ----------------
__global__ void __launch_bounds__(256) gate_kernel(
    const float* __restrict__ tok, const float* __restrict__ gw,
    float* __restrict__ gates, int* __restrict__ eidx, float* __restrict__ gp)
{
    int n = blockIdx.x, t = threadIdx.x;
    const float* row = tok + (long)n * D;
    float p[E];
#pragma unroll
    for (int e = 0; e < E; e++) p[e] = 0.f;
    for (int d = t; d < D; d += 256) {
        float xv = row[d];
        const float* w = gw + (long)d * E;
#pragma unroll
        for (int e = 0; e < E; e++) p[e] += xv * w[e];
    }
    __shared__ float red[256 * E];
#pragma unroll
    for (int e = 0; e < E; e++) red[t * E + e] = p[e];
    __syncthreads();
    for (int st = 128; st > 0; st >>= 1) {
        if (t < st)
#pragma unroll
            for (int e = 0; e < E; e++) red[t * E + e] += red[(t + st) * E + e];
        __syncthreads();
    }
    if (t == 0) {
        float lg[E], mx = -1e30f;
#pragma unroll
        for (int e = 0; e < E; e++) { lg[e] = red[e]; mx = fmaxf(mx, lg[e]); }
        float sum = 0.f, pr[E];
#pragma unroll
        for (int e = 0; e < E; e++) { pr[e] = __expf(lg[e] - mx); sum += pr[e]; }
        float inv = 1.f / sum;
        int best = 0; float bv = -1e30f;
#pragma unroll
        for (int e = 0; e < E; e++) {
            float g = pr[e] * inv;
            gates[(long)n * E + e] = g;
            if (g > bv) { bv = g; best = e; }
        }
        eidx[n] = best;
        gp[n]   = bv;
    }
}

// ---------------- routing scan (deterministic, single block) ----------------
__global__ void __launch_bounds__(256) scan_kernel(
    const int* __restrict__ eidx, const float* __restrict__ gp,
    int* __restrict__ slot, float* __restrict__ gv, int* __restrict__ cnt)
{
    __shared__ int scnt[256][E];
    int t = threadIdx.x;
    int c[E];
#pragma unroll
    for (int e = 0; e < E; e++) c[e] = 0;
    int n0 = t * (N / 256);
    for (int i = 0; i < N / 256; i++) c[eidx[n0 + i]]++;
#pragma unroll
    for (int e = 0; e < E; e++) scnt[t][e] = c[e];
    __syncthreads();
    if (t < E) {
        int run = 0;
        for (int j = 0; j < 256; j++) { int tmp = scnt[j][t]; scnt[j][t] = run; run += tmp; }
        cnt[t] = run;
    }
    __syncthreads();
    int off[E];
#pragma unroll
    for (int e = 0; e < E; e++) off[e] = scnt[t][e];
    for (int i = 0; i < N / 256; i++) {
        int n = n0 + i;
        int e = eidx[n];
        int l = off[e]++;
        bool keep = (l < CAP);
        slot[n] = keep ? e * CAP + l : -1;
        gv[n]   = keep ? gp[n] : 0.f;
    }
}

// ---------------- l_aux (deterministic tree reduce) ----------------
__global__ void __launch_bounds__(256) laux_kernel(
    const float* __restrict__ gates, const int* __restrict__ cnt,
    float* __restrict__ out_laux)
{
    __shared__ float red[256];
    int t = threadIdx.x;
    float loc[E];
#pragma unroll
    for (int e = 0; e < E; e++) loc[e] = 0.f;
    for (int n = t; n < N; n += 256)
#pragma unroll
        for (int e = 0; e < E; e++) loc[e] += gates[(long)n * E + e];
    float total[E];
    for (int e = 0; e < E; e++) {
        red[t] = loc[e]; __syncthreads();
        for (int st = 128; st > 0; st >>= 1) {
            if (t < st) red[t] += red[t + st];
            __syncthreads();
        }
        if (t == 0) total[e] = red[0];
        __syncthreads();
    }
    if (t == 0) {
        float la = 0.f;
        for (int e = 0; e < E; e++)
            la += (total[e] / N) * ((float)cnt[e] / N);
        *out_laux = (float)E * la;
    }
}

// ---------------- dispatch / combine ----------------
__global__ void __launch_bounds__(256) dispatch_kernel(
    const float* __restrict__ tok, const int* __restrict__ slot,
    uint16_t* __restrict__ dispb)
{
    int n = blockIdx.x;
    int s = slot[n];
    if (s < 0) return;
    int t = threadIdx.x;
    float4 v = ((const float4*)(tok + (long)n * D))[t];
    uint2 o;
    o.x = packbf2(v.x, v.y);
    o.y = packbf2(v.z, v.w);
    *(uint2*)(dispb + (long)s * D + t * 4) = o;
}

__global__ void __launch_bounds__(256) combine_kernel(
    const float* __restrict__ x1, const float* __restrict__ eo,
    const int* __restrict__ slot, const float* __restrict__ gv,
    float* __restrict__ out)
{
    int n = blockIdx.x, t = threadIdx.x;
    int s = slot[n];
    float g = gv[n];
    float4 r = ((const float4*)(x1 + (long)n * D))[t];
    if (s >= 0) {
        float4 v = ((const float4*)(eo + (long)s * D))[t];
        r.x += v.x * g; r.y += v.y * g; r.z += v.z * g; r.w += v.w * g;
    }
    ((float4*)(out + (long)n * D))[t] = r;
}

// ---------------- launch ----------------
extern "C" void kernel_launch(void* const* d_in, const int* in_sizes, int n_in,
                              void* d_out, int out_size) {
    const float* x    = (const float*)d_in[0];
    const float* wq   = (const float*)d_in[2];
    const float* bq   = (const float*)d_in[3];
    const float* wk   = (const float*)d_in[4];
    const float* bk   = (const float*)d_in[5];
    const float* wv   = (const float*)d_in[6];
    const float* bv   = (const float*)d_in[7];
    const float* wo   = (const float*)d_in[8];
    const float* bo   = (const float*)d_in[9];
    const float* ln1g = (const float*)d_in[10];
    const float* ln1b = (const float*)d_in[11];
    const float* ln2g = (const float*)d_in[12];
    const float* ln2b = (const float*)d_in[13];
    const float* gw   = (const float*)d_in[14];
    const float* w1   = (const float*)d_in[15];
    const float* b1   = (const float*)d_in[16];
    const float* w2   = (const float*)d_in[17];
    const float* b2   = (const float*)d_in[18];
    float* out = (float*)d_out;

    float *qkv, *x1, *tok, *eo, *gates, *gp, *gv, *b3;
    uint32_t *xnh, *xnl, *aoh, *aol, *wqkvh, *wqkvl, *woh, *wol, *w1p, *w2p;
    uint32_t *kh2, *kl2, *vh2, *vl2;
    uint16_t *dispb, *hb;
    int *eidx, *slot, *cnt;
    cudaGetSymbolAddress((void**)&xnh,   g_xnh);
    cudaGetSymbolAddress((void**)&xnl,   g_xnl);
    cudaGetSymbolAddress((void**)&qkv,   g_qkv);
    cudaGetSymbolAddress((void**)&aoh,   g_aoh);
    cudaGetSymbolAddress((void**)&aol,   g_aol);
    cudaGetSymbolAddress((void**)&x1,    g_x1);
    cudaGetSymbolAddress((void**)&tok,   g_tok);
    cudaGetSymbolAddress((void**)&wqkvh, g_wqkvh);
    cudaGetSymbolAddress((void**)&wqkvl, g_wqkvl);
    cudaGetSymbolAddress((void**)&b3,    g_b3);
    cudaGetSymbolAddress((void**)&woh,   g_woh);
    cudaGetSymbolAddress((void**)&wol,   g_wol);
    cudaGetSymbolAddress((void**)&kh2,   g_kh2);
    cudaGetSymbolAddress((void**)&kl2,   g_kl2);
    cudaGetSymbolAddress((void**)&vh2,   g_vh2);
    cudaGetSymbolAddress((void**)&vl2,   g_vl2);
    cudaGetSymbolAddress((void**)&dispb, g_dispb);
    cudaGetSymbolAddress((void**)&hb,    g_hb);
    cudaGetSymbolAddress((void**)&eo,    g_eo);
    cudaGetSymbolAddress((void**)&w1p,   g_w1p);
    cudaGetSymbolAddress((void**)&w2p,   g_w2p);
    cudaGetSymbolAddress((void**)&gates, g_gates);
    cudaGetSymbolAddress((void**)&gp,    g_gp);
    cudaGetSymbolAddress((void**)&gv,    g_gv);
    cudaGetSymbolAddress((void**)&eidx,  g_eidx);
    cudaGetSymbolAddress((void**)&slot,  g_slot);
    cudaGetSymbolAddress((void**)&cnt,   g_cnt);

    cudaFuncSetAttribute(gemm_bf16w_kernel<1, 1>,
                         cudaFuncAttributeMaxDynamicSharedMemorySize, EXP_SMEM);
    cudaFuncSetAttribute(gemm_bf16w_kernel<0, 0>,
                         cudaFuncAttributeMaxDynamicSharedMemorySize, EXP_SMEM);

    // one-time prep
    splitwp_kernel<<<dim3(D / 256, Dp), 256>>>(wq, wqkvh, wqkvl, D, D3, 0,     0.125f);
    splitwp_kernel<<<dim3(D / 256, Dp), 256>>>(wk, wqkvh, wqkvl, D, D3, D,     1.0f);
    splitwp_kernel<<<dim3(D / 256, Dp), 256>>>(wv, wqkvh, wqkvl, D, D3, 2 * D, 1.0f);
    biascat3_kernel<<<D / 256, 256>>>(bq, bk, bv, b3);
    splitwp_kernel<<<dim3(D / 256, Dp), 256>>>(wo, woh, wol, D, D, 0, 1.0f);
    packw_kernel<<<dim3(F / 256, D / 2, E), 256>>>(w1, w1p, F,
        (long long)D * F, (long long)(D / 2) * F);
    packw_kernel<<<dim3(D / 256, F / 2, E), 256>>>(w2, w2p, D,
        (long long)F * D, (long long)(F / 2) * D);

    // 1) LN1 -> bf16-pair hi/lo
    ln_splitp_kernel<<<N, 256>>>(x, ln1g, ln1b, xnh, xnl);
    // 2) merged QKV projection (bf16x3, Nc=3072)
    gemm_b3_kernel<0><<<dim3(D3 / 128, N / 128), 256>>>(
        xnh, xnl, wqkvh, wqkvl, b3, nullptr, qkv, N, D3, D);
    // 3a) K/V -> packed bf16-pair hi/lo planes
    convk_kernel<<<dim3(S / 32, B * H), 256>>>(qkv, kh2, kl2);
    convv_kernel<<<dim3(S / 8,  B * H), 256>>>(qkv, vh2, vl2);
    // 3b) tensor-core flash attention
    attn_tc_kernel<<<dim3(S / 128, B * H), 256>>>(
        qkv, kh2, kl2, vh2, vl2, aoh, aol);
    // 4) output projection + residual (bf16x3)
    gemm_b3_kernel<1><<<dim3(D / 128, N / 128), 256>>>(
        aoh, aol, woh, wol, bo, x, x1, N, D, D);
    // 5) LN2
    ln_kernel<<<N, 256>>>(x1, ln2g, ln2b, tok);
    // 6) gate
    gate_kernel<<<N, 256>>>(tok, gw, gates, eidx, gp);
    // 7) routing scan
    scan_kernel<<<1, 256>>>(eidx, gp, slot, gv, cnt);
    // 8) l_aux -> last output element
    laux_kernel<<<1, 256>>>(gates, cnt, out + (out_size - 1));
    // 9) dispatch (writes bf16)
    dispatch_kernel<<<N, 256>>>(tok, slot, dispb);
    // 10) expert GEMM1 (relu, bf16 -> bf16) — only live tiles compute
    gemm_bf16w_kernel<1, 1><<<dim3(F / 256, CAP / 128, E), 256, EXP_SMEM>>>(
        dispb, w1p, b1, hb, cnt, CAP, F, D,
        (long long)CAP * D, (long long)(D / 2) * F, (long long)F, (long long)CAP * F);
    // 11) expert GEMM2 (bf16 -> fp32) — only live tiles compute
    gemm_bf16w_kernel<0, 0><<<dim3(D / 256, CAP / 128, E), 256, EXP_SMEM>>>(
        hb, w2p, b2, eo, cnt, CAP, D, F,
        (long long)CAP * F, (long long)(F / 2) * D, (long long)D, (long long)CAP * D);
    // 12) combine + residual -> output
    combine_kernel<<<N, 256>>>(x1, eo, slot, gv, out);
}

// round 17
// speedup vs baseline: 2.7801x; 1.0038x over previous
#include <cuda_runtime.h>
#include <cstdint>

// ---------------- problem constants ----------------
constexpr int S = 1024, B = 8, D = 1024, H = 16, F = 4096, E = 8;
constexpr int HD = D / H;           // 64
constexpr int N = S * B;            // 8192
constexpr int CAP = 4 * N / E;      // 4096
constexpr int D3 = 3 * D;           // 3072 (merged qkv width)
constexpr int Dp = D / 2;           // pair count per row

// ---------------- scratch (device globals; no allocations) ----------------
__device__ uint32_t g_xnh[N * Dp], g_xnl[N * Dp];    // LN1 out, bf16-pair hi/lo
__device__ float    g_qkv[N * D3];                   // merged q|k|v
__device__ uint32_t g_aoh[N * Dp], g_aol[N * Dp];    // attn out, bf16-pair hi/lo
__device__ float g_x1 [N * D];
__device__ float g_tok[N * D];
__device__ uint32_t g_wqkvh[Dp * D3], g_wqkvl[Dp * D3];  // bf16 k-pair hi/lo
__device__ float    g_b3[D3];
__device__ uint32_t g_woh[Dp * D], g_wol[Dp * D];
__device__ uint32_t g_kh2[B * H * 32 * S], g_kl2[B * H * 32 * S];   // K hi/lo [bh][dp][s]
__device__ uint32_t g_vh2[B * H * (S / 2) * HD], g_vl2[B * H * (S / 2) * HD]; // V [bh][kp][d]
__device__ uint16_t g_dispb[E * CAP * D];            // bf16 dispatched tokens
__device__ uint16_t g_hb  [134217728];               // E*CAP*F bf16 hidden
__device__ float    g_eo  [E * CAP * D];
__device__ uint32_t g_w1p [(D / 2) * F * E];         // bf16 k-pair packed w1
__device__ uint32_t g_w2p [(F / 2) * D * E];         // bf16 k-pair packed w2
__device__ float g_gates[N * E];
__device__ int   g_eidx[N];
__device__ float g_gp  [N];
__device__ int   g_slot[N];
__device__ float g_gv  [N];
__device__ int   g_cnt [E];

// ---------------- helpers ----------------
__device__ __forceinline__ uint32_t packbf2(float lo, float hi) {
    uint32_t d;
    asm("cvt.rn.bf16x2.f32 %0, %1, %2;" : "=r"(d) : "f"(hi), "f"(lo));
    return d;
}
__device__ __forceinline__ uint16_t f2bf(float f) {
    uint16_t u;
    asm("cvt.rn.bf16.f32 %0, %1;" : "=h"(u) : "f"(f));
    return u;
}
__device__ __forceinline__ float bf2f(uint16_t h) {
    return __uint_as_float((uint32_t)h << 16);
}
__device__ __forceinline__ uint32_t packsplit_h(float a, float b) {
    uint16_t ha = f2bf(a), hb = f2bf(b);
    return ((uint32_t)hb << 16) | ha;
}
__device__ __forceinline__ uint32_t packsplit_l(float a, float b) {
    uint16_t ha = f2bf(a), hb = f2bf(b);
    uint16_t la = f2bf(a - bf2f(ha)), lb = f2bf(b - bf2f(hb));
    return ((uint32_t)lb << 16) | la;
}

#define MMA_BF16(acc, a, b0, b1) \
    asm volatile("mma.sync.aligned.m16n8k16.row.col.f32.bf16.bf16.f32 " \
        "{%0,%1,%2,%3}, {%4,%5,%6,%7}, {%8,%9}, {%0,%1,%2,%3};" \
        : "+f"((acc)[0]), "+f"((acc)[1]), "+f"((acc)[2]), "+f"((acc)[3]) \
        : "r"((a)[0]), "r"((a)[1]), "r"((a)[2]), "r"((a)[3]), "r"(b0), "r"(b1))

// ---------------- merged QKV weight split (grid.z selects wq/wk/wv) ---------
__global__ void __launch_bounds__(256) splitwp3_kernel(
    const float* __restrict__ Wq, const float* __restrict__ Wk,
    const float* __restrict__ Wv,
    uint32_t* __restrict__ Ph, uint32_t* __restrict__ Pl)
{
    int z  = blockIdx.z;
    const float* W = (z == 0) ? Wq : (z == 1) ? Wk : Wv;
    float scale    = (z == 0) ? 0.125f : 1.0f;
    int n  = blockIdx.x * 256 + threadIdx.x;
    int k2 = blockIdx.y;
    float v0 = W[(long long)(2 * k2)     * D + n] * scale;
    float v1 = W[(long long)(2 * k2 + 1) * D + n] * scale;
    long long o = (long long)k2 * D3 + z * D + n;
    Ph[o] = packsplit_h(v0, v1);
    Pl[o] = packsplit_l(v0, v1);
}
// single-weight split (wo)
__global__ void __launch_bounds__(256) splitwp_kernel(
    const float* __restrict__ W, uint32_t* __restrict__ Ph,
    uint32_t* __restrict__ Pl)
{
    int n  = blockIdx.x * 256 + threadIdx.x;
    int k2 = blockIdx.y;
    float v0 = W[(long long)(2 * k2)     * D + n];
    float v1 = W[(long long)(2 * k2 + 1) * D + n];
    long long o = (long long)k2 * D + n;
    Ph[o] = packsplit_h(v0, v1);
    Pl[o] = packsplit_l(v0, v1);
}
__global__ void __launch_bounds__(256) biascat3_kernel(
    const float* __restrict__ bq, const float* __restrict__ bk,
    const float* __restrict__ bv, float* __restrict__ dst)
{
    int i = blockIdx.x * 256 + threadIdx.x;
    dst[i]         = bq[i] * 0.125f;
    dst[i + D]     = bk[i];
    dst[i + 2 * D] = bv[i];
}

// ---------------- LayerNorm2 + gate (fused; bitwise-identical order) --------
__global__ void __launch_bounds__(256) ln_gate_kernel(
    const float* __restrict__ x, const float* __restrict__ gam,
    const float* __restrict__ bet, const float* __restrict__ gw,
    float* __restrict__ tok,
    float* __restrict__ gates, int* __restrict__ eidx, float* __restrict__ gp)
{
    int n = blockIdx.x;
    const float* row = x + (long)n * D;
    int t = threadIdx.x;
    float s = 0.f, s2 = 0.f;
    for (int d = t; d < D; d += 256) { float v = row[d]; s += v; s2 += v * v; }
    __shared__ float r1[256], r2[256];
    r1[t] = s; r2[t] = s2; __syncthreads();
    for (int st = 128; st > 0; st >>= 1) {
        if (t < st) { r1[t] += r1[t + st]; r2[t] += r2[t + st]; }
        __syncthreads();
    }
    float mean = r1[0] / D;
    float var  = r2[0] / D - mean * mean;
    float inv  = rsqrtf(var + 1e-5f);
    // LN output + gate partial dot in the SAME strided order as the old kernels
    float p[E];
#pragma unroll
    for (int e = 0; e < E; e++) p[e] = 0.f;
    float* yo = tok + (long)n * D;
    for (int d = t; d < D; d += 256) {
        float v = (row[d] - mean) * inv * gam[d] + bet[d];
        yo[d] = v;
        const float* w = gw + (long)d * E;
#pragma unroll
        for (int e = 0; e < E; e++) p[e] += v * w[e];
    }
    __shared__ float red[256 * E];
    __syncthreads();
#pragma unroll
    for (int e = 0; e < E; e++) red[t * E + e] = p[e];
    __syncthreads();
    for (int st = 128; st > 0; st >>= 1) {
        if (t < st)
#pragma unroll
            for (int e = 0; e < E; e++) red[t * E + e] += red[(t + st) * E + e];
        __syncthreads();
    }
    if (t == 0) {
        float lg[E], mx = -1e30f;
#pragma unroll
        for (int e = 0; e < E; e++) { lg[e] = red[e]; mx = fmaxf(mx, lg[e]); }
        float sum = 0.f, pr[E];
#pragma unroll
        for (int e = 0; e < E; e++) { pr[e] = __expf(lg[e] - mx); sum += pr[e]; }
        float invs = 1.f / sum;
        int best = 0; float bv = -1e30f;
#pragma unroll
        for (int e = 0; e < E; e++) {
            float g = pr[e] * invs;
            gates[(long)n * E + e] = g;
            if (g > bv) { bv = g; best = e; }
        }
        eidx[n] = best;
        gp[n]   = bv;
    }
}

// ---------------- LayerNorm1 (bf16-pair hi/lo out) ----------------
__global__ void __launch_bounds__(256) ln_splitp_kernel(
    const float* __restrict__ x, const float* __restrict__ gam,
    const float* __restrict__ bet,
    uint32_t* __restrict__ yh, uint32_t* __restrict__ yl)
{
    int n = blockIdx.x;
    const float* row = x + (long)n * D;
    int t = threadIdx.x;
    float s = 0.f, s2 = 0.f;
    for (int d = t; d < D; d += 256) { float v = row[d]; s += v; s2 += v * v; }
    __shared__ float r1[256], r2[256];
    r1[t] = s; r2[t] = s2; __syncthreads();
    for (int st = 128; st > 0; st >>= 1) {
        if (t < st) { r1[t] += r1[t + st]; r2[t] += r2[t + st]; }
        __syncthreads();
    }
    float mean = r1[0] / D;
    float var  = r2[0] / D - mean * mean;
    float inv  = rsqrtf(var + 1e-5f);
    float4 v4 = *(const float4*)(row + 4 * t);
    float4 g4 = *(const float4*)(gam + 4 * t);
    float4 b4 = *(const float4*)(bet + 4 * t);
    float v0 = (v4.x - mean) * inv * g4.x + b4.x;
    float v1 = (v4.y - mean) * inv * g4.y + b4.y;
    float v2 = (v4.z - mean) * inv * g4.z + b4.z;
    float v3 = (v4.w - mean) * inv * g4.w + b4.w;
    long long o = (long long)n * Dp + 2 * t;
    yh[o]     = packsplit_h(v0, v1);
    yh[o + 1] = packsplit_h(v2, v3);
    yl[o]     = packsplit_l(v0, v1);
    yl[o + 1] = packsplit_l(v2, v3);
}

// ---------------- bf16x3 GEMM (projections) ----------------------------------
template<int HAS_RESID>
__global__ void __launch_bounds__(256, 2) gemm_b3_kernel(
    const uint32_t* __restrict__ Aph, const uint32_t* __restrict__ Apl,
    const uint32_t* __restrict__ Bph, const uint32_t* __restrict__ Bpl,
    const float* __restrict__ bias, const float* __restrict__ resid,
    float* __restrict__ C, int M, int Nc, int K)
{
    __shared__ uint32_t Ash[8][136], Asl[8][136];
    __shared__ uint32_t Bsh[8][136], Bsl[8][136];

    int t    = threadIdx.x;
    int wid  = t >> 5, lane = t & 31;
    int gid  = lane >> 2, tig = lane & 3;
    int wm0  = (wid & 1) * 64;
    int wn0  = (wid >> 1) * 32;
    int m0   = blockIdx.y * 128, n0 = blockIdx.x * 128;
    int Kp   = K >> 1;

    int arow = t >> 1, apg = (t & 1) * 4;
    int brow = t >> 5, bcol = (t & 31) * 4;

    float acc[4][4][4];
#pragma unroll
    for (int mt = 0; mt < 4; mt++)
#pragma unroll
        for (int nt = 0; nt < 4; nt++)
#pragma unroll
            for (int r = 0; r < 4; r++) acc[mt][nt][r] = 0.f;

    for (int kp0 = 0; kp0 < Kp; kp0 += 8) {
        {
            uint4 vh = *(const uint4*)(Aph + (long long)(m0 + arow) * Kp + kp0 + apg);
            uint4 vl = *(const uint4*)(Apl + (long long)(m0 + arow) * Kp + kp0 + apg);
            Ash[apg + 0][arow] = vh.x; Ash[apg + 1][arow] = vh.y;
            Ash[apg + 2][arow] = vh.z; Ash[apg + 3][arow] = vh.w;
            Asl[apg + 0][arow] = vl.x; Asl[apg + 1][arow] = vl.y;
            Asl[apg + 2][arow] = vl.z; Asl[apg + 3][arow] = vl.w;
        }
        {
            *(uint4*)&Bsh[brow][bcol] =
                *(const uint4*)(Bph + (long long)(kp0 + brow) * Nc + n0 + bcol);
            *(uint4*)&Bsl[brow][bcol] =
                *(const uint4*)(Bpl + (long long)(kp0 + brow) * Nc + n0 + bcol);
        }
        __syncthreads();

        uint32_t fah[4][4], fal[4][4], fbh[4][2], fbl[4][2];
#pragma unroll
        for (int mt = 0; mt < 4; mt++) {
            int mm = wm0 + mt * 16 + gid;
            fah[mt][0] = Ash[tig    ][mm];
            fah[mt][1] = Ash[tig    ][mm + 8];
            fah[mt][2] = Ash[tig + 4][mm];
            fah[mt][3] = Ash[tig + 4][mm + 8];
            fal[mt][0] = Asl[tig    ][mm];
            fal[mt][1] = Asl[tig    ][mm + 8];
            fal[mt][2] = Asl[tig + 4][mm];
            fal[mt][3] = Asl[tig + 4][mm + 8];
        }
#pragma unroll
        for (int nt = 0; nt < 4; nt++) {
            int nn = wn0 + nt * 8 + gid;
            fbh[nt][0] = Bsh[tig    ][nn];
            fbh[nt][1] = Bsh[tig + 4][nn];
            fbl[nt][0] = Bsl[tig    ][nn];
            fbl[nt][1] = Bsl[tig + 4][nn];
        }
#pragma unroll
        for (int mt = 0; mt < 4; mt++)
#pragma unroll
            for (int nt = 0; nt < 4; nt++) {
                MMA_BF16(acc[mt][nt], fah[mt], fbl[nt][0], fbl[nt][1]);
                MMA_BF16(acc[mt][nt], fal[mt], fbh[nt][0], fbh[nt][1]);
                MMA_BF16(acc[mt][nt], fah[mt], fbh[nt][0], fbh[nt][1]);
            }
        __syncthreads();
    }

#pragma unroll
    for (int mt = 0; mt < 4; mt++) {
#pragma unroll
        for (int nt = 0; nt < 4; nt++) {
            int row = m0 + wm0 + mt * 16 + gid;
            int col = n0 + wn0 + nt * 8 + 2 * tig;
            float b0 = bias[col], b1 = bias[col + 1];
            float c0 = acc[mt][nt][0] + b0;
            float c1 = acc[mt][nt][1] + b1;
            float c2 = acc[mt][nt][2] + b0;
            float c3 = acc[mt][nt][3] + b1;
            if (HAS_RESID) {
                float2 r0 = *(const float2*)(resid + (long long)row * Nc + col);
                float2 r1 = *(const float2*)(resid + (long long)(row + 8) * Nc + col);
                c0 += r0.x; c1 += r0.y; c2 += r1.x; c3 += r1.y;
            }
            *(float2*)(C + (long long)row * Nc + col)       = make_float2(c0, c1);
            *(float2*)(C + (long long)(row + 8) * Nc + col) = make_float2(c2, c3);
        }
    }
}

// ---------------- K/V conversion: fp32 qkv -> packed bf16-pair hi/lo planes -
__global__ void __launch_bounds__(256) convk_kernel(
    const float* __restrict__ qkv, uint32_t* __restrict__ Kh,
    uint32_t* __restrict__ Kl)
{
    __shared__ uint32_t th[32][33], tl[32][33];
    int bh = blockIdx.y, h = bh & (H - 1), b = bh >> 4;
    int s0 = blockIdx.x * 32;
    int tx = threadIdx.x & 31, ty = threadIdx.x >> 5;
    for (int i = ty; i < 32; i += 8) {
        int s = s0 + i;
        float2 v = *(const float2*)(qkv + ((long)s * B + b) * D3 + D + h * HD + 2 * tx);
        th[i][tx] = packsplit_h(v.x, v.y);
        tl[i][tx] = packsplit_l(v.x, v.y);
    }
    __syncthreads();
    long obase = (long)bh * 32 * S;
    for (int i = ty; i < 32; i += 8) {
        Kh[obase + (long)i * S + s0 + tx] = th[tx][i];
        Kl[obase + (long)i * S + s0 + tx] = tl[tx][i];
    }
}
__global__ void __launch_bounds__(256) convv_kernel(
    const float* __restrict__ qkv, uint32_t* __restrict__ Vh,
    uint32_t* __restrict__ Vl)
{
    int bh = blockIdx.y, h = bh & (H - 1), b = bh >> 4;
    int t = threadIdx.x;
    int kp = blockIdx.x * 4 + (t >> 6);
    int d  = t & 63;
    float v0 = qkv[((long)(2 * kp)     * B + b) * D3 + 2 * D + h * HD + d];
    float v1 = qkv[((long)(2 * kp + 1) * B + b) * D3 + 2 * D + h * HD + d];
    long o = (long)bh * (S / 2) * HD + (long)kp * HD + d;
    Vh[o] = packsplit_h(v0, v1);
    Vl[o] = packsplit_l(v0, v1);
}

// ---------------- tensor-core flash attention (bf16 hi/lo x3) ---------------
__global__ void __launch_bounds__(256) attn_tc_kernel(
    const float* __restrict__ Qg,
    const uint32_t* __restrict__ Kh, const uint32_t* __restrict__ Kl,
    const uint32_t* __restrict__ Vh, const uint32_t* __restrict__ Vl,
    uint32_t* __restrict__ Ohp, uint32_t* __restrict__ Olp)
{
    __shared__ uint32_t Ksh[32][72], Ksl[32][72], Vsh[32][72], Vsl[32][72];

    int bh = blockIdx.y, h = bh & (H - 1), b = bh >> 4;
    int q0 = blockIdx.x * 128;
    int t = threadIdx.x, wid = t >> 5, lane = t & 31;
    int gid = lane >> 2, tig = lane & 3;

    long kbase = (long)bh * 32 * S;
    long vbase = (long)bh * (S / 2) * HD;

    int r0 = q0 + wid * 16 + gid;
    int r1 = r0 + 8;

    uint32_t qfh[4][4], qfl[4][4];
    {
        long ro0 = ((long)r0 * B + b) * D3 + h * HD;
        long ro1 = ((long)r1 * B + b) * D3 + h * HD;
#pragma unroll
        for (int kc = 0; kc < 4; kc++) {
            int p0 = kc * 8 + tig, p1 = p0 + 4;
            float2 x0 = *(const float2*)(Qg + ro0 + 2 * p0);
            float2 x1 = *(const float2*)(Qg + ro1 + 2 * p0);
            float2 x2 = *(const float2*)(Qg + ro0 + 2 * p1);
            float2 x3 = *(const float2*)(Qg + ro1 + 2 * p1);
            qfh[kc][0] = packsplit_h(x0.x, x0.y); qfl[kc][0] = packsplit_l(x0.x, x0.y);
            qfh[kc][1] = packsplit_h(x1.x, x1.y); qfl[kc][1] = packsplit_l(x1.x, x1.y);
            qfh[kc][2] = packsplit_h(x2.x, x2.y); qfl[kc][2] = packsplit_l(x2.x, x2.y);
            qfh[kc][3] = packsplit_h(x3.x, x3.y); qfl[kc][3] = packsplit_l(x3.x, x3.y);
        }
    }

    float o[8][4];
#pragma unroll
    for (int nt = 0; nt < 8; nt++)
#pragma unroll
        for (int j = 0; j < 4; j++) o[nt][j] = 0.f;
    float m0 = -1e30f, m1 = -1e30f, l0 = 0.f, l1 = 0.f;

    int kend = q0 + 128;
    for (int k0 = 0; k0 < kend; k0 += 64) {
#pragma unroll
        for (int i = 0; i < 8; i++) {
            int idx = t + i * 256;
            int row = idx >> 6, col = idx & 63;
            Ksh[row][col] = Kh[kbase + (long)row * S + k0 + col];
            Ksl[row][col] = Kl[kbase + (long)row * S + k0 + col];
            Vsh[row][col] = Vh[vbase + (long)((k0 >> 1) + row) * HD + col];
            Vsl[row][col] = Vl[vbase + (long)((k0 >> 1) + row) * HD + col];
        }
        __syncthreads();

        bool active = (k0 <= q0 + wid * 16 + 15);
        if (active) {
            float sacc[8][4];
#pragma unroll
            for (int nt = 0; nt < 8; nt++)
#pragma unroll
                for (int j = 0; j < 4; j++) sacc[nt][j] = 0.f;
#pragma unroll
            for (int kc = 0; kc < 4; kc++) {
#pragma unroll
                for (int nt = 0; nt < 8; nt++) {
                    int nn = nt * 8 + gid;
                    uint32_t bh0 = Ksh[kc * 8 + tig][nn];
                    uint32_t bh1 = Ksh[kc * 8 + tig + 4][nn];
                    uint32_t bl0 = Ksl[kc * 8 + tig][nn];
                    uint32_t bl1 = Ksl[kc * 8 + tig + 4][nn];
                    MMA_BF16(sacc[nt], qfh[kc], bl0, bl1);
                    MMA_BF16(sacc[nt], qfl[kc], bh0, bh1);
                    MMA_BF16(sacc[nt], qfh[kc], bh0, bh1);
                }
            }
            float mloc0 = -1e30f, mloc1 = -1e30f;
#pragma unroll
            for (int nt = 0; nt < 8; nt++) {
                int c0 = k0 + nt * 8 + 2 * tig, c1 = c0 + 1;
                if (c0 > r0) sacc[nt][0] = -1e9f;
                if (c1 > r0) sacc[nt][1] = -1e9f;
                if (c0 > r1) sacc[nt][2] = -1e9f;
                if (c1 > r1) sacc[nt][3] = -1e9f;
                mloc0 = fmaxf(mloc0, fmaxf(sacc[nt][0], sacc[nt][1]));
                mloc1 = fmaxf(mloc1, fmaxf(sacc[nt][2], sacc[nt][3]));
            }
            mloc0 = fmaxf(mloc0, __shfl_xor_sync(0xffffffffu, mloc0, 1));
            mloc0 = fmaxf(mloc0, __shfl_xor_sync(0xffffffffu, mloc0, 2));
            mloc1 = fmaxf(mloc1, __shfl_xor_sync(0xffffffffu, mloc1, 1));
            mloc1 = fmaxf(mloc1, __shfl_xor_sync(0xffffffffu, mloc1, 2));
            float mn0 = fmaxf(m0, mloc0), mn1 = fmaxf(m1, mloc1);
            float cr0 = __expf(m0 - mn0), cr1 = __expf(m1 - mn1);
            l0 *= cr0; l1 *= cr1;
#pragma unroll
            for (int nt = 0; nt < 8; nt++) {
                o[nt][0] *= cr0; o[nt][1] *= cr0;
                o[nt][2] *= cr1; o[nt][3] *= cr1;
            }
#pragma unroll
            for (int nt = 0; nt < 8; nt++) {
                float p0 = __expf(sacc[nt][0] - mn0);
                float p1 = __expf(sacc[nt][1] - mn0);
                float p2 = __expf(sacc[nt][2] - mn1);
                float p3 = __expf(sacc[nt][3] - mn1);
                l0 += p0 + p1; l1 += p2 + p3;
                sacc[nt][0] = p0; sacc[nt][1] = p1;
                sacc[nt][2] = p2; sacc[nt][3] = p3;
            }
            m0 = mn0; m1 = mn1;
#pragma unroll
            for (int kc2 = 0; kc2 < 4; kc2++) {
                int fA = 2 * kc2, fB = fA + 1;
                uint32_t pah[4], pal[4];
                pah[0] = packsplit_h(sacc[fA][0], sacc[fA][1]);
                pal[0] = packsplit_l(sacc[fA][0], sacc[fA][1]);
                pah[1] = packsplit_h(sacc[fA][2], sacc[fA][3]);
                pal[1] = packsplit_l(sacc[fA][2], sacc[fA][3]);
                pah[2] = packsplit_h(sacc[fB][0], sacc[fB][1]);
                pal[2] = packsplit_l(sacc[fB][0], sacc[fB][1]);
                pah[3] = packsplit_h(sacc[fB][2], sacc[fB][3]);
                pal[3] = packsplit_l(sacc[fB][2], sacc[fB][3]);
#pragma unroll
                for (int nt = 0; nt < 8; nt++) {
                    int nn = nt * 8 + gid;
                    uint32_t vh0 = Vsh[kc2 * 8 + tig][nn];
                    uint32_t vh1 = Vsh[kc2 * 8 + tig + 4][nn];
                    uint32_t vl0 = Vsl[kc2 * 8 + tig][nn];
                    uint32_t vl1 = Vsl[kc2 * 8 + tig + 4][nn];
                    MMA_BF16(o[nt], pah, vl0, vl1);
                    MMA_BF16(o[nt], pal, vh0, vh1);
                    MMA_BF16(o[nt], pah, vh0, vh1);
                }
            }
        }
        __syncthreads();
    }
    l0 += __shfl_xor_sync(0xffffffffu, l0, 1);
    l0 += __shfl_xor_sync(0xffffffffu, l0, 2);
    l1 += __shfl_xor_sync(0xffffffffu, l1, 1);
    l1 += __shfl_xor_sync(0xffffffffu, l1, 2);
    float i0 = 1.f / l0, i1 = 1.f / l1;
    long t0 = (long)r0 * B + b, t1 = (long)r1 * B + b;
#pragma unroll
    for (int nt = 0; nt < 8; nt++) {
        int dpair = h * 32 + nt * 4 + tig;
        float v0 = o[nt][0] * i0, v1 = o[nt][1] * i0;
        float v2 = o[nt][2] * i1, v3 = o[nt][3] * i1;
        Ohp[t0 * Dp + dpair] = packsplit_h(v0, v1);
        Olp[t0 * Dp + dpair] = packsplit_l(v0, v1);
        Ohp[t1 * Dp + dpair] = packsplit_h(v2, v3);
        Olp[t1 * Dp + dpair] = packsplit_l(v2, v3);
    }
}

// ---------------- weight packing: fp32 [K][Nc] -> bf16 k-pair u32 [K/2][Nc] --
__global__ void __launch_bounds__(256) packw_kernel(
    const float* __restrict__ W, uint32_t* __restrict__ P, int Nc,
    long long sW, long long sP)
{
    int n  = blockIdx.x * 256 + threadIdx.x;
    int k2 = blockIdx.y;
    int z  = blockIdx.z;
    const float* w = W + (long long)z * sW + (long long)(2 * k2) * Nc + n;
    P[(long long)z * sP + (long long)k2 * Nc + n] = packbf2(w[0], w[Nc]);
}

// ---------------- bf16 expert GEMM: block 128x256, warp 64x64, k32 ----------
constexpr int EXP_SMEM = 2 * 16 * 136 * 4 + 2 * 16 * 264 * 4;  // 51200 B

template<int RELU, int OUTBF>
__global__ void __launch_bounds__(256) gemm_bf16w_kernel(
    const uint16_t* __restrict__ A, const uint32_t* __restrict__ Bp,
    const float* __restrict__ bias, void* __restrict__ Cout,
    const int* __restrict__ cnt,
    int M, int Nc, int K,
    long long sA, long long sB, long long sBias, long long sC)
{
    int z = blockIdx.z;
    int m0 = blockIdx.y * 128, n0 = blockIdx.x * 256;
    if (m0 >= cnt[z]) return;

    extern __shared__ uint32_t dyn[];
    uint32_t* As = dyn;
    uint32_t* Bs = dyn + 2 * 16 * 136;

    A    += (long long)z * sA;
    Bp   += (long long)z * sB;
    bias += (long long)z * sBias;

    int t    = threadIdx.x;
    int wid  = t >> 5, lane = t & 31;
    int gid  = lane >> 2, tig = lane & 3;
    int wm0  = (wid & 1) * 64;
    int wn0  = (wid >> 1) * 64;

    int am  = t & 127, ahh = t >> 7;
    int bk  = t >> 4,  bn  = (t & 15) * 16;

    float acc[4][8][4];
#pragma unroll
    for (int mt = 0; mt < 4; mt++)
#pragma unroll
        for (int nt = 0; nt < 8; nt++)
#pragma unroll
            for (int r = 0; r < 4; r++) acc[mt][nt][r] = 0.f;

    auto stageA = [&](int buf, uint4 va0, uint4 va1) {
        uint32_t* as = As + buf * (16 * 136);
        as[(ahh * 4 + 0) * 136 + am] = va0.x;
        as[(ahh * 4 + 1) * 136 + am] = va0.y;
        as[(ahh * 4 + 2) * 136 + am] = va0.z;
        as[(ahh * 4 + 3) * 136 + am] = va0.w;
        as[((ahh + 2) * 4 + 0) * 136 + am] = va1.x;
        as[((ahh + 2) * 4 + 1) * 136 + am] = va1.y;
        as[((ahh + 2) * 4 + 2) * 136 + am] = va1.z;
        as[((ahh + 2) * 4 + 3) * 136 + am] = va1.w;
    };
    auto stageB = [&](int buf, const uint4* vb) {
        uint32_t* bs = Bs + buf * (16 * 264);
#pragma unroll
        for (int j = 0; j < 4; j++)
            *(uint4*)&bs[bk * 264 + bn + j * 4] = vb[j];
    };

    const int nIter = K / 32;
    {
        uint4 va0 = *(const uint4*)(A + (long long)(m0 + am) * K + ahh * 8);
        uint4 va1 = *(const uint4*)(A + (long long)(m0 + am) * K + (ahh + 2) * 8);
        uint4 vb[4];
#pragma unroll
        for (int j = 0; j < 4; j++)
            vb[j] = *(const uint4*)(Bp + (long long)bk * Nc + n0 + bn + j * 4);
        stageA(0, va0, va1);
        stageB(0, vb);
    }
    __syncthreads();

    for (int it = 0; it < nIter; ++it) {
        int cur = it & 1;
        uint4 va0, va1, vb[4];
        bool pf = (it + 1 < nIter);
        if (pf) {
            long long ka = (long long)(m0 + am) * K + (it + 1) * 32;
            va0 = *(const uint4*)(A + ka + ahh * 8);
            va1 = *(const uint4*)(A + ka + (ahh + 2) * 8);
            long long kb = (long long)(it + 1) * 16 + bk;
#pragma unroll
            for (int j = 0; j < 4; j++)
                vb[j] = *(const uint4*)(Bp + kb * Nc + n0 + bn + j * 4);
        }
        const uint32_t* as = As + cur * (16 * 136);
        const uint32_t* bs = Bs + cur * (16 * 264);
#pragma unroll
        for (int kb2 = 0; kb2 < 2; kb2++) {
            int ko = kb2 * 8;
            uint32_t af[4][4], bfr[8][2];
#pragma unroll
            for (int mt = 0; mt < 4; mt++) {
                int mm = wm0 + mt * 16 + gid;
                af[mt][0] = as[(ko + tig    ) * 136 + mm];
                af[mt][1] = as[(ko + tig    ) * 136 + mm + 8];
                af[mt][2] = as[(ko + tig + 4) * 136 + mm];
                af[mt][3] = as[(ko + tig + 4) * 136 + mm + 8];
            }
#pragma unroll
            for (int nt = 0; nt < 8; nt++) {
                int nn = wn0 + nt * 8 + gid;
                bfr[nt][0] = bs[(ko + tig    ) * 264 + nn];
                bfr[nt][1] = bs[(ko + tig + 4) * 264 + nn];
            }
#pragma unroll
            for (int mt = 0; mt < 4; mt++)
#pragma unroll
                for (int nt = 0; nt < 8; nt++)
                    MMA_BF16(acc[mt][nt], af[mt], bfr[nt][0], bfr[nt][1]);
        }
        if (pf) {
            stageA(cur ^ 1, va0, va1);
            stageB(cur ^ 1, vb);
        }
        __syncthreads();
    }

#pragma unroll
    for (int mt = 0; mt < 4; mt++) {
#pragma unroll
        for (int nt = 0; nt < 8; nt++) {
            int row = m0 + wm0 + mt * 16 + gid;
            int col = n0 + wn0 + nt * 8 + 2 * tig;
            float b0 = bias[col], b1 = bias[col + 1];
            float c0 = acc[mt][nt][0] + b0;
            float c1 = acc[mt][nt][1] + b1;
            float c2 = acc[mt][nt][2] + b0;
            float c3 = acc[mt][nt][3] + b1;
            if (RELU) {
                c0 = fmaxf(c0, 0.f); c1 = fmaxf(c1, 0.f);
                c2 = fmaxf(c2, 0.f); c3 = fmaxf(c3, 0.f);
            }
            if (OUTBF) {
                uint16_t* Cb = (uint16_t*)Cout + (long long)z * sC;
                *(uint32_t*)(Cb + (long long)row * Nc + col)       = packbf2(c0, c1);
                *(uint32_t*)(Cb + (long long)(row + 8) * Nc + col) = packbf2(c2, c3);
            } else {
                float* Cf = (float*)Cout + (long long)z * sC;
                *(float2*)(Cf + (long long)row * Nc + col)       = make_float2(c0, c1);
                *(float2*)(Cf + (long long)(row + 8) * Nc + col) = make_float2(c2, c3);
            }
        }
    }
}

// ---------------- routing scan + l_aux (fused, single block) ----------------
__global__ void __launch_bounds__(256) scan_laux_kernel(
    const int* __restrict__ eidx, const float* __restrict__ gp,
    const float* __restrict__ gates,
    int* __restrict__ slot, float* __restrict__ gv, int* __restrict__ cnt,
    float* __restrict__ out_laux)
{
    __shared__ int scnt[256][E];
    __shared__ int scnt_tot[E];
    int t = threadIdx.x;
    int c[E];
#pragma unroll
    for (int e = 0; e < E; e++) c[e] = 0;
    int n0 = t * (N / 256);
    for (int i = 0; i < N / 256; i++) c[eidx[n0 + i]]++;
#pragma unroll
    for (int e = 0; e < E; e++) scnt[t][e] = c[e];
    __syncthreads();
    if (t < E) {
        int run = 0;
        for (int j = 0; j < 256; j++) { int tmp = scnt[j][t]; scnt[j][t] = run; run += tmp; }
        cnt[t] = run;
        scnt_tot[t] = run;
    }
    __syncthreads();
    int off[E];
#pragma unroll
    for (int e = 0; e < E; e++) off[e] = scnt[t][e];
    for (int i = 0; i < N / 256; i++) {
        int n = n0 + i;
        int e = eidx[n];
        int l = off[e]++;
        bool keep = (l < CAP);
        slot[n] = keep ? e * CAP + l : -1;
        gv[n]   = keep ? gp[n] : 0.f;
    }
    // ---- l_aux (same order as the old laux_kernel) ----
    __shared__ float red[256];
    float loc[E];
#pragma unroll
    for (int e = 0; e < E; e++) loc[e] = 0.f;
    for (int n = t; n < N; n += 256)
#pragma unroll
        for (int e = 0; e < E; e++) loc[e] += gates[(long)n * E + e];
    float total[E];
    for (int e = 0; e < E; e++) {
        __syncthreads();
        red[t] = loc[e]; __syncthreads();
        for (int st = 128; st > 0; st >>= 1) {
            if (t < st) red[t] += red[t + st];
            __syncthreads();
        }
        if (t == 0) total[e] = red[0];
    }
    if (t == 0) {
        float la = 0.f;
        for (int e = 0; e < E; e++)
            la += (total[e] / N) * ((float)scnt_tot[e] / N);
        *out_laux = (float)E * la;
    }
}

// ---------------- dispatch / combine ----------------
__global__ void __launch_bounds__(256) dispatch_kernel(
    const float* __restrict__ tok, const int* __restrict__ slot,
    uint16_t* __restrict__ dispb)
{
    int n = blockIdx.x;
    int s = slot[n];
    if (s < 0) return;
    int t = threadIdx.x;
    float4 v = ((const float4*)(tok + (long)n * D))[t];
    uint2 o;
    o.x = packbf2(v.x, v.y);
    o.y = packbf2(v.z, v.w);
    *(uint2*)(dispb + (long)s * D + t * 4) = o;
}

__global__ void __launch_bounds__(256) combine_kernel(
    const float* __restrict__ x1, const float* __restrict__ eo,
    const int* __restrict__ slot, const float* __restrict__ gv,
    float* __restrict__ out)
{
    int n = blockIdx.x, t = threadIdx.x;
    int s = slot[n];
    float g = gv[n];
    float4 r = ((const float4*)(x1 + (long)n * D))[t];
    if (s >= 0) {
        float4 v = ((const float4*)(eo + (long)s * D))[t];
        r.x += v.x * g; r.y += v.y * g; r.z += v.z * g; r.w += v.w * g;
    }
    ((float4*)(out + (long)n * D))[t] = r;
}

// ---------------- launch ----------------
extern "C" void kernel_launch(void* const* d_in, const int* in_sizes, int n_in,
                              void* d_out, int out_size) {
    const float* x    = (const float*)d_in[0];
    const float* wq   = (const float*)d_in[2];
    const float* bq   = (const float*)d_in[3];
    const float* wk   = (const float*)d_in[4];
    const float* bk   = (const float*)d_in[5];
    const float* wv   = (const float*)d_in[6];
    const float* bv   = (const float*)d_in[7];
    const float* wo   = (const float*)d_in[8];
    const float* bo   = (const float*)d_in[9];
    const float* ln1g = (const float*)d_in[10];
    const float* ln1b = (const float*)d_in[11];
    const float* ln2g = (const float*)d_in[12];
    const float* ln2b = (const float*)d_in[13];
    const float* gw   = (const float*)d_in[14];
    const float* w1   = (const float*)d_in[15];
    const float* b1   = (const float*)d_in[16];
    const float* w2   = (const float*)d_in[17];
    const float* b2   = (const float*)d_in[18];
    float* out = (float*)d_out;

    float *qkv, *x1, *tok, *eo, *gates, *gp, *gv, *b3;
    uint32_t *xnh, *xnl, *aoh, *aol, *wqkvh, *wqkvl, *woh, *wol, *w1p, *w2p;
    uint32_t *kh2, *kl2, *vh2, *vl2;
    uint16_t *dispb, *hb;
    int *eidx, *slot, *cnt;
    cudaGetSymbolAddress((void**)&xnh,   g_xnh);
    cudaGetSymbolAddress((void**)&xnl,   g_xnl);
    cudaGetSymbolAddress((void**)&qkv,   g_qkv);
    cudaGetSymbolAddress((void**)&aoh,   g_aoh);
    cudaGetSymbolAddress((void**)&aol,   g_aol);
    cudaGetSymbolAddress((void**)&x1,    g_x1);
    cudaGetSymbolAddress((void**)&tok,   g_tok);
    cudaGetSymbolAddress((void**)&wqkvh, g_wqkvh);
    cudaGetSymbolAddress((void**)&wqkvl, g_wqkvl);
    cudaGetSymbolAddress((void**)&b3,    g_b3);
    cudaGetSymbolAddress((void**)&woh,   g_woh);
    cudaGetSymbolAddress((void**)&wol,   g_wol);
    cudaGetSymbolAddress((void**)&kh2,   g_kh2);
    cudaGetSymbolAddress((void**)&kl2,   g_kl2);
    cudaGetSymbolAddress((void**)&vh2,   g_vh2);
    cudaGetSymbolAddress((void**)&vl2,   g_vl2);
    cudaGetSymbolAddress((void**)&dispb, g_dispb);
    cudaGetSymbolAddress((void**)&hb,    g_hb);
    cudaGetSymbolAddress((void**)&eo,    g_eo);
    cudaGetSymbolAddress((void**)&w1p,   g_w1p);
    cudaGetSymbolAddress((void**)&w2p,   g_w2p);
    cudaGetSymbolAddress((void**)&gates, g_gates);
    cudaGetSymbolAddress((void**)&gp,    g_gp);
    cudaGetSymbolAddress((void**)&gv,    g_gv);
    cudaGetSymbolAddress((void**)&eidx,  g_eidx);
    cudaGetSymbolAddress((void**)&slot,  g_slot);
    cudaGetSymbolAddress((void**)&cnt,   g_cnt);

    cudaFuncSetAttribute(gemm_bf16w_kernel<1, 1>,
                         cudaFuncAttributeMaxDynamicSharedMemorySize, EXP_SMEM);
    cudaFuncSetAttribute(gemm_bf16w_kernel<0, 0>,
                         cudaFuncAttributeMaxDynamicSharedMemorySize, EXP_SMEM);

    // one-time prep (merged launches)
    splitwp3_kernel<<<dim3(D / 256, Dp, 3), 256>>>(wq, wk, wv, wqkvh, wqkvl);
    biascat3_kernel<<<D / 256, 256>>>(bq, bk, bv, b3);
    splitwp_kernel<<<dim3(D / 256, Dp), 256>>>(wo, woh, wol);
    packw_kernel<<<dim3(F / 256, D / 2, E), 256>>>(w1, w1p, F,
        (long long)D * F, (long long)(D / 2) * F);
    packw_kernel<<<dim3(D / 256, F / 2, E), 256>>>(w2, w2p, D,
        (long long)F * D, (long long)(F / 2) * D);

    // 1) LN1 -> bf16-pair hi/lo
    ln_splitp_kernel<<<N, 256>>>(x, ln1g, ln1b, xnh, xnl);
    // 2) merged QKV projection (bf16x3, Nc=3072)
    gemm_b3_kernel<0><<<dim3(D3 / 128, N / 128), 256>>>(
        xnh, xnl, wqkvh, wqkvl, b3, nullptr, qkv, N, D3, D);
    // 3a) K/V -> packed bf16-pair hi/lo planes
    convk_kernel<<<dim3(S / 32, B * H), 256>>>(qkv, kh2, kl2);
    convv_kernel<<<dim3(S / 8,  B * H), 256>>>(qkv, vh2, vl2);
    // 3b) tensor-core flash attention
    attn_tc_kernel<<<dim3(S / 128, B * H), 256>>>(
        qkv, kh2, kl2, vh2, vl2, aoh, aol);
    // 4) output projection + residual (bf16x3)
    gemm_b3_kernel<1><<<dim3(D / 128, N / 128), 256>>>(
        aoh, aol, woh, wol, bo, x, x1, N, D, D);
    // 5+6) LN2 + gate (fused, bitwise-identical order)
    ln_gate_kernel<<<N, 256>>>(x1, ln2g, ln2b, gw, tok, gates, eidx, gp);
    // 7+8) routing scan + l_aux (fused) -> last output element
    scan_laux_kernel<<<1, 256>>>(eidx, gp, gates, slot, gv, cnt,
                                 out + (out_size - 1));
    // 9) dispatch (writes bf16)
    dispatch_kernel<<<N, 256>>>(tok, slot, dispb);
    // 10) expert GEMM1 (relu, bf16 -> bf16) — only live tiles compute
    gemm_bf16w_kernel<1, 1><<<dim3(F / 256, CAP / 128, E), 256, EXP_SMEM>>>(
        dispb, w1p, b1, hb, cnt, CAP, F, D,
        (long long)CAP * D, (long long)(D / 2) * F, (long long)F, (long long)CAP * F);
    // 11) expert GEMM2 (bf16 -> fp32) — only live tiles compute
    gemm_bf16w_kernel<0, 0><<<dim3(D / 256, CAP / 128, E), 256, EXP_SMEM>>>(
        hb, w2p, b2, eo, cnt, CAP, D, F,
        (long long)CAP * F, (long long)(F / 2) * D, (long long)D, (long long)CAP * D);
    // 12) combine + residual -> output
    combine_kernel<<<N, 256>>>(x1, eo, slot, gv, out);
}